// round 2
// baseline (speedup 1.0000x reference)
#include <cuda_runtime.h>
#include <math.h>

// Problem constants
#define Bb   2
#define Ss   2048
#define Dd   4096
#define Hh   32
#define HDd  128
#define ALa  10
#define MROWS (Bb*Ss)          // 4096

// ---------------------------------------------------------------------------
// Scratch (device globals; no cudaMalloc allowed)
// ---------------------------------------------------------------------------
__device__ float g_xq[MROWS*Dd];
__device__ float g_xk[MROWS*Dd];
__device__ float g_xv[MROWS*Dd];
__device__ float g_att[MROWS*Dd];
__device__ float g_T [MROWS*48];   // [x@lq1^T | x@lk1^T | x@lv1^T]
__device__ float g_To[MROWS*16];   // att@lo1^T
__device__ float g_ak[Bb*ALa*Dd];
__device__ float g_av[Bb*ALa*Dd];

// ---------------------------------------------------------------------------
// GEMM: C[M,N] = A(MxK,rm) * W(NxK,rm)^T + T(Mx16 @ ldt,toff) * L2(Nx16,rm)^T
// 128x128 tile, BK=16, 256 threads, 8x8 microtile, double-buffered smem.
// ---------------------------------------------------------------------------
__global__ __launch_bounds__(256) void gemm_nt_lora(
    const float* __restrict__ A, const float* __restrict__ W,
    const float* __restrict__ T, int ldt, int toff,
    const float* __restrict__ L2,
    float* __restrict__ C, int Ntot, int Ktot)
{
    __shared__ float As[2][16][132];
    __shared__ float Bs[2][16][132];
    const int tid = threadIdx.x;
    const int tx = tid & 15, ty = tid >> 4;
    const int m0 = blockIdx.y << 7;
    const int n0 = blockIdx.x << 7;
    const float* Ag = A + (size_t)m0 * Ktot;
    const float* Wg = W + (size_t)n0 * Ktot;
    const int lr = tid >> 2;          // 0..63 (row within half-tile)
    const int lc = (tid & 3) << 2;    // 0,4,8,12

    float acc[8][8];
    #pragma unroll
    for (int i = 0; i < 8; ++i)
        #pragma unroll
        for (int j = 0; j < 8; ++j) acc[i][j] = 0.f;

    // prologue: tile 0 -> buffer 0
    #pragma unroll
    for (int i = 0; i < 2; ++i) {
        int r = lr + i*64;
        float4 a4 = *(const float4*)(Ag + (size_t)r*Ktot + lc);
        As[0][lc+0][r]=a4.x; As[0][lc+1][r]=a4.y; As[0][lc+2][r]=a4.z; As[0][lc+3][r]=a4.w;
        float4 b4 = *(const float4*)(Wg + (size_t)r*Ktot + lc);
        Bs[0][lc+0][r]=b4.x; Bs[0][lc+1][r]=b4.y; Bs[0][lc+2][r]=b4.z; Bs[0][lc+3][r]=b4.w;
    }
    __syncthreads();

    const int NK = Ktot >> 4;
    for (int kt = 0; kt < NK; ++kt) {
        const int cur = kt & 1;
        float4 pa[2], pb[2];
        const bool nxt = (kt + 1 < NK);
        if (nxt) {
            int k0 = (kt + 1) << 4;
            #pragma unroll
            for (int i = 0; i < 2; ++i) {
                int r = lr + i*64;
                pa[i] = *(const float4*)(Ag + (size_t)r*Ktot + k0 + lc);
                pb[i] = *(const float4*)(Wg + (size_t)r*Ktot + k0 + lc);
            }
        }
        #pragma unroll
        for (int kk = 0; kk < 16; ++kk) {
            float a[8], b[8];
            *(float4*)(a)   = *(const float4*)&As[cur][kk][8*ty];
            *(float4*)(a+4) = *(const float4*)&As[cur][kk][8*ty+4];
            *(float4*)(b)   = *(const float4*)&Bs[cur][kk][8*tx];
            *(float4*)(b+4) = *(const float4*)&Bs[cur][kk][8*tx+4];
            #pragma unroll
            for (int i = 0; i < 8; ++i)
                #pragma unroll
                for (int j = 0; j < 8; ++j)
                    acc[i][j] = fmaf(a[i], b[j], acc[i][j]);
        }
        if (nxt) {
            const int nb = cur ^ 1;
            #pragma unroll
            for (int i = 0; i < 2; ++i) {
                int r = lr + i*64;
                As[nb][lc+0][r]=pa[i].x; As[nb][lc+1][r]=pa[i].y; As[nb][lc+2][r]=pa[i].z; As[nb][lc+3][r]=pa[i].w;
                Bs[nb][lc+0][r]=pb[i].x; Bs[nb][lc+1][r]=pb[i].y; Bs[nb][lc+2][r]=pb[i].z; Bs[nb][lc+3][r]=pb[i].w;
            }
        }
        __syncthreads();
    }

    // LoRA epilogue: acc += T[m, toff:toff+16] * L2[n, 0:16]^T
    #pragma unroll
    for (int i = 0; i < 2; ++i) {
        int r = lr + i*64;
        float4 t4 = *(const float4*)(T + (size_t)(m0 + r)*ldt + toff + lc);
        As[0][lc+0][r]=t4.x; As[0][lc+1][r]=t4.y; As[0][lc+2][r]=t4.z; As[0][lc+3][r]=t4.w;
        float4 l4 = *(const float4*)(L2 + (size_t)(n0 + r)*16 + lc);
        Bs[0][lc+0][r]=l4.x; Bs[0][lc+1][r]=l4.y; Bs[0][lc+2][r]=l4.z; Bs[0][lc+3][r]=l4.w;
    }
    __syncthreads();
    #pragma unroll
    for (int kk = 0; kk < 16; ++kk) {
        float a[8], b[8];
        *(float4*)(a)   = *(const float4*)&As[0][kk][8*ty];
        *(float4*)(a+4) = *(const float4*)&As[0][kk][8*ty+4];
        *(float4*)(b)   = *(const float4*)&Bs[0][kk][8*tx];
        *(float4*)(b+4) = *(const float4*)&Bs[0][kk][8*tx+4];
        #pragma unroll
        for (int i = 0; i < 8; ++i)
            #pragma unroll
            for (int j = 0; j < 8; ++j)
                acc[i][j] = fmaf(a[i], b[j], acc[i][j]);
    }

    #pragma unroll
    for (int i = 0; i < 8; ++i) {
        float* cp = C + (size_t)(m0 + 8*ty + i)*Ntot + n0 + 8*tx;
        *(float4*)cp     = make_float4(acc[i][0], acc[i][1], acc[i][2], acc[i][3]);
        *(float4*)(cp+4) = make_float4(acc[i][4], acc[i][5], acc[i][6], acc[i][7]);
    }
}

// ---------------------------------------------------------------------------
// T = X @ [L1a;L1b;L1c]^T   (rank-16 LoRA intermediates).  64-row tiles.
// ---------------------------------------------------------------------------
__global__ __launch_bounds__(256) void lora_t_kernel(
    const float* __restrict__ X,
    const float* __restrict__ L1a, const float* __restrict__ L1b, const float* __restrict__ L1c,
    float* __restrict__ T, int nmat, int ldt, int Ktot)
{
    __shared__ float Xs[32][68];   // [k][m]
    __shared__ float Ls[32][52];   // [k][r]
    const int tid = threadIdx.x;
    const int tx = tid & 15, ty = tid >> 4;
    const int m0 = blockIdx.x << 6;
    const int Rtot = nmat << 4;
    float acc[4][3];
    #pragma unroll
    for (int i = 0; i < 4; ++i)
        #pragma unroll
        for (int j = 0; j < 3; ++j) acc[i][j] = 0.f;

    for (int k0 = 0; k0 < Ktot; k0 += 32) {
        __syncthreads();
        #pragma unroll
        for (int i = 0; i < 2; ++i) {
            int v = tid + i*256;
            int r = v >> 3, c = (v & 7) << 2;
            float4 x4 = *(const float4*)(X + (size_t)(m0 + r)*Ktot + k0 + c);
            Xs[c+0][r]=x4.x; Xs[c+1][r]=x4.y; Xs[c+2][r]=x4.z; Xs[c+3][r]=x4.w;
        }
        for (int v = tid; v < Rtot*8; v += 256) {
            int r = v >> 3, c = (v & 7) << 2;
            const float* src = (r < 16) ? (L1a + (size_t)r*Ktot)
                             : (r < 32) ? (L1b + (size_t)(r-16)*Ktot)
                                        : (L1c + (size_t)(r-32)*Ktot);
            float4 l4 = *(const float4*)(src + k0 + c);
            Ls[c+0][r]=l4.x; Ls[c+1][r]=l4.y; Ls[c+2][r]=l4.z; Ls[c+3][r]=l4.w;
        }
        __syncthreads();
        #pragma unroll
        for (int k = 0; k < 32; ++k) {
            float xv[4];
            #pragma unroll
            for (int i = 0; i < 4; ++i) xv[i] = Xs[k][4*ty + i];
            for (int j = 0; j < nmat; ++j) {
                float lv = Ls[k][tx + 16*j];
                #pragma unroll
                for (int i = 0; i < 4; ++i) acc[i][j] = fmaf(xv[i], lv, acc[i][j]);
            }
        }
    }
    for (int j = 0; j < nmat; ++j)
        #pragma unroll
        for (int i = 0; i < 4; ++i)
            T[(size_t)(m0 + 4*ty + i)*ldt + tx + 16*j] = acc[i][j];
}

// ---------------------------------------------------------------------------
// Adapter K/V projection: AK = Ad(20xK) @ Wk^T, AV = Ad @ Wv^T (no LoRA).
// One block per 64 output columns.
// ---------------------------------------------------------------------------
__global__ __launch_bounds__(256) void adapter_proj_kernel(
    const float* __restrict__ Ad, const float* __restrict__ Wk, const float* __restrict__ Wv,
    float* __restrict__ AK, float* __restrict__ AV, int Ktot, int Ntot)
{
    __shared__ float Ads[20][68];   // [m][k]
    __shared__ float Wks[64][65];   // [k][n]
    __shared__ float Wvs[64][65];
    const int tid = threadIdx.x;
    const int nl = tid & 63, mg = tid >> 6;
    const int n0 = blockIdx.x << 6;
    float ak[5] = {0,0,0,0,0}, av[5] = {0,0,0,0,0};

    for (int k0 = 0; k0 < Ktot; k0 += 64) {
        __syncthreads();
        // FIXED: 320 float4 loads needed with 256 threads -> strided loop
        // (previously `if (tid < 320)` left Ads rows 16..19 uninitialized,
        //  corrupting the adapter branch for batch 1 -> rel_err 0.62)
        for (int v = tid; v < 320; v += 256) {
            int r = v >> 4, c = (v & 15) << 2;
            float4 a4 = *(const float4*)(Ad + (size_t)r*Ktot + k0 + c);
            Ads[r][c+0]=a4.x; Ads[r][c+1]=a4.y; Ads[r][c+2]=a4.z; Ads[r][c+3]=a4.w;
        }
        #pragma unroll
        for (int i = 0; i < 4; ++i) {
            int v = tid + i*256;
            int r = v >> 4, c = (v & 15) << 2;
            float4 w4 = *(const float4*)(Wk + (size_t)(n0 + r)*Ktot + k0 + c);
            Wks[c+0][r]=w4.x; Wks[c+1][r]=w4.y; Wks[c+2][r]=w4.z; Wks[c+3][r]=w4.w;
            float4 w5 = *(const float4*)(Wv + (size_t)(n0 + r)*Ktot + k0 + c);
            Wvs[c+0][r]=w5.x; Wvs[c+1][r]=w5.y; Wvs[c+2][r]=w5.z; Wvs[c+3][r]=w5.w;
        }
        __syncthreads();
        #pragma unroll
        for (int k = 0; k < 64; ++k) {
            float wkv = Wks[k][nl];
            float wvv = Wvs[k][nl];
            #pragma unroll
            for (int i = 0; i < 5; ++i) {
                float a = Ads[5*mg + i][k];
                ak[i] = fmaf(a, wkv, ak[i]);
                av[i] = fmaf(a, wvv, av[i]);
            }
        }
    }
    #pragma unroll
    for (int i = 0; i < 5; ++i) {
        AK[(size_t)(5*mg + i)*Ntot + n0 + nl] = ak[i];
        AV[(size_t)(5*mg + i)*Ntot + n0 + nl] = av[i];
    }
}

// ---------------------------------------------------------------------------
// Flash attention, fp32, causal. 64 q-rows x 64 k-cols tiles, HD=128.
// Layout of XQ/XK/XV/O: (B,S,D) with head h at columns h*128..h*128+127.
// ---------------------------------------------------------------------------
#define FLASH_SMEM_FLOATS (64*132 + 128*68 + 64*132 + 64*68)
#define FLASH_SMEM_BYTES  (FLASH_SMEM_FLOATS*4)

__global__ __launch_bounds__(256) void flash_kernel(
    const float* __restrict__ XQ, const float* __restrict__ XK,
    const float* __restrict__ XV, float* __restrict__ O)
{
    extern __shared__ float sm[];
    float* Qs  = sm;                      // [64][132]
    float* Kts = sm + 64*132;             // [128][68]  (K transposed: [hd][key])
    float* Vs  = Kts + 128*68;            // [64][132]
    float* Ps  = Vs + 64*132;             // [64][68]

    const int tid = threadIdx.x;
    const int tx = tid & 15, ty = tid >> 4;
    const int q0 = blockIdx.x << 6;
    const int h = blockIdx.y, b = blockIdx.z;
    const size_t hoff = (size_t)h * HDd;
    const float scale = 0.08838834764831845f;   // 1/sqrt(128)

    // load Q tile
    #pragma unroll
    for (int t = 0; t < 8; ++t) {
        int v = tid + t*256;
        int r = v >> 5, c = (v & 31) << 2;
        float4 q4 = *(const float4*)(XQ + ((size_t)(b*Ss + q0 + r))*Dd + hoff + c);
        *(float4*)&Qs[r*132 + c] = q4;
    }

    float o[4][8];
    #pragma unroll
    for (int i = 0; i < 4; ++i)
        #pragma unroll
        for (int j = 0; j < 8; ++j) o[i][j] = 0.f;
    float m[4] = {-1e30f,-1e30f,-1e30f,-1e30f};
    float l[4] = {0.f,0.f,0.f,0.f};

    const int ktEnd = blockIdx.x;   // causal: only tiles up to diagonal
    for (int kt = 0; kt <= ktEnd; ++kt) {
        const int k0 = kt << 6;
        __syncthreads();   // previous Vs/Ps fully consumed; Qs visible on iter 0
        #pragma unroll
        for (int t = 0; t < 8; ++t) {
            int v = tid + t*256;
            int r = v >> 5, c = (v & 31) << 2;
            float4 k4 = *(const float4*)(XK + ((size_t)(b*Ss + k0 + r))*Dd + hoff + c);
            Kts[(c+0)*68 + r]=k4.x; Kts[(c+1)*68 + r]=k4.y; Kts[(c+2)*68 + r]=k4.z; Kts[(c+3)*68 + r]=k4.w;
            float4 v4 = *(const float4*)(XV + ((size_t)(b*Ss + k0 + r))*Dd + hoff + c);
            *(float4*)&Vs[r*132 + c] = v4;
        }
        __syncthreads();

        // S = Q * K^T  (4x4 per thread; rows 4*ty+i, cols 4*tx+j)
        float s[4][4];
        #pragma unroll
        for (int i = 0; i < 4; ++i)
            #pragma unroll
            for (int j = 0; j < 4; ++j) s[i][j] = 0.f;
        #pragma unroll
        for (int k4i = 0; k4i < 32; ++k4i) {
            float4 qf[4];
            #pragma unroll
            for (int i = 0; i < 4; ++i) qf[i] = *(const float4*)&Qs[(4*ty+i)*132 + 4*k4i];
            #pragma unroll
            for (int e = 0; e < 4; ++e) {
                float4 kf = *(const float4*)&Kts[(4*k4i + e)*68 + 4*tx];
                #pragma unroll
                for (int i = 0; i < 4; ++i) {
                    float qv = ((const float*)&qf[i])[e];
                    s[i][0] = fmaf(qv, kf.x, s[i][0]);
                    s[i][1] = fmaf(qv, kf.y, s[i][1]);
                    s[i][2] = fmaf(qv, kf.z, s[i][2]);
                    s[i][3] = fmaf(qv, kf.w, s[i][3]);
                }
            }
        }

        const bool diag = (kt == ktEnd);
        #pragma unroll
        for (int i = 0; i < 4; ++i) {
            const int qr = q0 + 4*ty + i;
            #pragma unroll
            for (int j = 0; j < 4; ++j) {
                float sv = s[i][j] * scale;
                if (diag && (k0 + 4*tx + j > qr)) sv = -1e30f;
                s[i][j] = sv;
            }
            float rm = fmaxf(fmaxf(s[i][0], s[i][1]), fmaxf(s[i][2], s[i][3]));
            #pragma unroll
            for (int off = 8; off > 0; off >>= 1)
                rm = fmaxf(rm, __shfl_xor_sync(0xffffffffu, rm, off, 16));
            float mn = fmaxf(m[i], rm);
            float corr = __expf(m[i] - mn);
            float rs = 0.f;
            #pragma unroll
            for (int j = 0; j < 4; ++j) { s[i][j] = __expf(s[i][j] - mn); rs += s[i][j]; }
            #pragma unroll
            for (int off = 8; off > 0; off >>= 1)
                rs += __shfl_xor_sync(0xffffffffu, rs, off, 16);
            l[i] = l[i]*corr + rs;
            m[i] = mn;
            #pragma unroll
            for (int j = 0; j < 8; ++j) o[i][j] *= corr;
            #pragma unroll
            for (int j = 0; j < 4; ++j) Ps[(4*ty+i)*68 + 4*tx + j] = s[i][j];
        }
        __syncthreads();

        // O += P * V   (cols 8*tx..8*tx+7)
        #pragma unroll
        for (int kb = 0; kb < 16; ++kb) {
            float4 p4[4];
            #pragma unroll
            for (int i = 0; i < 4; ++i) p4[i] = *(const float4*)&Ps[(4*ty+i)*68 + 4*kb];
            #pragma unroll
            for (int e = 0; e < 4; ++e) {
                const int k = 4*kb + e;
                float4 v0 = *(const float4*)&Vs[k*132 + 8*tx];
                float4 v1 = *(const float4*)&Vs[k*132 + 8*tx + 4];
                #pragma unroll
                for (int i = 0; i < 4; ++i) {
                    float pv = ((const float*)&p4[i])[e];
                    o[i][0] = fmaf(pv, v0.x, o[i][0]);
                    o[i][1] = fmaf(pv, v0.y, o[i][1]);
                    o[i][2] = fmaf(pv, v0.z, o[i][2]);
                    o[i][3] = fmaf(pv, v0.w, o[i][3]);
                    o[i][4] = fmaf(pv, v1.x, o[i][4]);
                    o[i][5] = fmaf(pv, v1.y, o[i][5]);
                    o[i][6] = fmaf(pv, v1.z, o[i][6]);
                    o[i][7] = fmaf(pv, v1.w, o[i][7]);
                }
            }
        }
    }

    #pragma unroll
    for (int i = 0; i < 4; ++i) {
        float inv = 1.f / l[i];
        float* op = O + ((size_t)(b*Ss + q0 + 4*ty + i))*Dd + hoff + 8*tx;
        *(float4*)op     = make_float4(o[i][0]*inv, o[i][1]*inv, o[i][2]*inv, o[i][3]*inv);
        *(float4*)(op+4) = make_float4(o[i][4]*inv, o[i][5]*inv, o[i][6]*inv, o[i][7]*inv);
    }
}

// ---------------------------------------------------------------------------
// Gated adapter cross-attention: att += tanh(gate[h])*new_gate * softmax(q·ak^T*scale) @ av
// One warp per query row; ak/av head slices cached in smem.
// ---------------------------------------------------------------------------
__global__ __launch_bounds__(256) void adapter_attn_kernel(
    const float* __restrict__ XQ, const float* __restrict__ AK, const float* __restrict__ AV,
    const float* __restrict__ gate, const float* __restrict__ ngate, float* __restrict__ O)
{
    __shared__ float aks[ALa][HDd];
    __shared__ float avs[ALa][HDd];
    const int tid = threadIdx.x;
    const int q0 = blockIdx.x << 6;
    const int h = blockIdx.y, b = blockIdx.z;
    const size_t hoff = (size_t)h * HDd;
    const float scale = 0.08838834764831845f;

    for (int v = tid; v < ALa*32; v += 256) {
        int r = v >> 5, c = (v & 31) << 2;
        *(float4*)&aks[r][c] = *(const float4*)(AK + ((size_t)(b*ALa + r))*Dd + hoff + c);
        *(float4*)&avs[r][c] = *(const float4*)(AV + ((size_t)(b*ALa + r))*Dd + hoff + c);
    }
    __syncthreads();

    const int lane = tid & 31, wid = tid >> 5;
    const float g = tanhf(gate[h]) * ngate[0];

    for (int it = 0; it < 8; ++it) {
        const int q = q0 + it*8 + wid;
        const float* qp = XQ + ((size_t)(b*Ss + q))*Dd + hoff;
        float qv[4];
        #pragma unroll
        for (int e = 0; e < 4; ++e) qv[e] = qp[lane + 32*e];

        float p[ALa];
        float mx = -1e30f;
        #pragma unroll
        for (int j = 0; j < ALa; ++j) {
            float sc = 0.f;
            #pragma unroll
            for (int e = 0; e < 4; ++e) sc = fmaf(qv[e], aks[j][lane + 32*e], sc);
            #pragma unroll
            for (int off = 16; off > 0; off >>= 1) sc += __shfl_xor_sync(0xffffffffu, sc, off);
            sc *= scale;
            p[j] = sc;
            mx = fmaxf(mx, sc);
        }
        float sum = 0.f;
        #pragma unroll
        for (int j = 0; j < ALa; ++j) { p[j] = __expf(p[j] - mx); sum += p[j]; }
        const float w = g / sum;

        float* op = O + ((size_t)(b*Ss + q))*Dd + hoff;
        #pragma unroll
        for (int e = 0; e < 4; ++e) {
            float acc = 0.f;
            #pragma unroll
            for (int j = 0; j < ALa; ++j) acc = fmaf(p[j], avs[j][lane + 32*e], acc);
            op[lane + 32*e] += acc * w;
        }
    }
}

// ---------------------------------------------------------------------------
// Launch
// ---------------------------------------------------------------------------
extern "C" void kernel_launch(void* const* d_in, const int* in_sizes, int n_in,
                              void* d_out, int out_size)
{
    (void)in_sizes; (void)n_in; (void)out_size;
    const float* x       = (const float*)d_in[0];
    // d_in[1] start_pos (0), d_in[2] freqs_cis (unused), d_in[3] mask (causal, reimplemented exactly)
    const float* adapter = (const float*)d_in[4];
    const float* wq  = (const float*)d_in[5];
    const float* wk  = (const float*)d_in[6];
    const float* wv  = (const float*)d_in[7];
    const float* wo  = (const float*)d_in[8];
    const float* lq1 = (const float*)d_in[9];
    const float* lq2 = (const float*)d_in[10];
    const float* lk1 = (const float*)d_in[11];
    const float* lk2 = (const float*)d_in[12];
    const float* lv1 = (const float*)d_in[13];
    const float* lv2 = (const float*)d_in[14];
    const float* lo1 = (const float*)d_in[15];
    const float* lo2 = (const float*)d_in[16];
    const float* gate  = (const float*)d_in[17];
    const float* ngate = (const float*)d_in[18];
    float* out = (float*)d_out;

    float *xq, *xk, *xv, *att, *T, *To, *ak, *av;
    cudaGetSymbolAddress((void**)&xq,  g_xq);
    cudaGetSymbolAddress((void**)&xk,  g_xk);
    cudaGetSymbolAddress((void**)&xv,  g_xv);
    cudaGetSymbolAddress((void**)&att, g_att);
    cudaGetSymbolAddress((void**)&T,   g_T);
    cudaGetSymbolAddress((void**)&To,  g_To);
    cudaGetSymbolAddress((void**)&ak,  g_ak);
    cudaGetSymbolAddress((void**)&av,  g_av);

    // Opt-in to >48KB dynamic smem for flash (sticky; harmless to repeat)
    cudaFuncSetAttribute(flash_kernel, cudaFuncAttributeMaxDynamicSharedMemorySize, FLASH_SMEM_BYTES);

    const dim3 gGrid(Dd/128, MROWS/128);   // (32, 32)

    // 1) LoRA intermediates for q/k/v
    lora_t_kernel<<<MROWS/64, 256>>>(x, lq1, lk1, lv1, T, 3, 48, Dd);
    // 2) QKV projections with fused LoRA epilogue
    gemm_nt_lora<<<gGrid, 256>>>(x, wq, T, 48, 0,  lq2, xq, Dd, Dd);
    gemm_nt_lora<<<gGrid, 256>>>(x, wk, T, 48, 16, lk2, xk, Dd, Dd);
    gemm_nt_lora<<<gGrid, 256>>>(x, wv, T, 48, 32, lv2, xv, Dd, Dd);
    // 3) adapter K/V projection (plain weights, no LoRA)
    adapter_proj_kernel<<<Dd/64, 256>>>(adapter, wk, wv, ak, av, Dd, Dd);
    // 4) causal flash attention
    flash_kernel<<<dim3(Ss/64, Hh, Bb), 256, FLASH_SMEM_BYTES>>>(xq, xk, xv, att);
    // 5) gated adapter cross-attention, added in place
    adapter_attn_kernel<<<dim3(Ss/64, Hh, Bb), 256>>>(xq, ak, av, gate, ngate, att);
    // 6) output LoRA intermediate + output projection
    lora_t_kernel<<<MROWS/64, 256>>>(att, lo1, lo1, lo1, To, 1, 16, Dd);
    gemm_nt_lora<<<gGrid, 256>>>(att, wo, To, 16, 0, lo2, out, Dd, Dd);
}

// round 4
// speedup vs baseline: 1.4905x; 1.4905x over previous
#include <cuda_runtime.h>
#include <cuda_bf16.h>
#include <math.h>
#include <stdint.h>

// Problem constants
#define Bb   2
#define Ss   2048
#define Dd   4096
#define Hh   32
#define HDd  128
#define ALa  10
#define MROWS (Bb*Ss)          // 4096

// ---------------------------------------------------------------------------
// Scratch (device globals; no cudaMalloc allowed)
// ---------------------------------------------------------------------------
__device__ float g_xq[MROWS*Dd];
__device__ float g_xk[MROWS*Dd];
__device__ float g_xv[MROWS*Dd];
__device__ float g_att[MROWS*Dd];
__device__ float g_T [MROWS*48];   // [x@lq1^T | x@lk1^T | x@lv1^T]
__device__ float g_To[MROWS*16];   // att@lo1^T
__device__ float g_ak[Bb*ALa*Dd];
__device__ float g_av[Bb*ALa*Dd];

// ---------------------------------------------------------------------------
// helpers
// ---------------------------------------------------------------------------
__device__ __forceinline__ uint32_t smem_u32(const void* p) {
    uint32_t a;
    asm("{ .reg .u64 t; cvta.to.shared.u64 t, %1; cvt.u32.u64 %0, t; }" : "=r"(a) : "l"(p));
    return a;
}
__device__ __forceinline__ void ldmx4(uint32_t* r, uint32_t addr) {
    asm volatile("ldmatrix.sync.aligned.m8n8.x4.shared.b16 {%0,%1,%2,%3}, [%4];"
                 : "=r"(r[0]), "=r"(r[1]), "=r"(r[2]), "=r"(r[3]) : "r"(addr));
}
__device__ __forceinline__ void mma16816(float* c, const uint32_t* a, const uint32_t* b) {
    asm volatile(
        "mma.sync.aligned.m16n8k16.row.col.f32.bf16.bf16.f32 "
        "{%0,%1,%2,%3}, {%4,%5,%6,%7}, {%8,%9}, {%0,%1,%2,%3};"
        : "+f"(c[0]), "+f"(c[1]), "+f"(c[2]), "+f"(c[3])
        : "r"(a[0]), "r"(a[1]), "r"(a[2]), "r"(a[3]), "r"(b[0]), "r"(b[1]));
}
// pack 2 fp32 -> bf16x2 (hi) and residual bf16x2 (lo)
__device__ __forceinline__ void split2(float f0, float f1, uint32_t& hi, uint32_t& lo) {
    __nv_bfloat16 h0 = __float2bfloat16_rn(f0);
    __nv_bfloat16 h1 = __float2bfloat16_rn(f1);
    __nv_bfloat16 l0 = __float2bfloat16_rn(f0 - __bfloat162float(h0));
    __nv_bfloat16 l1 = __float2bfloat16_rn(f1 - __bfloat162float(h1));
    __nv_bfloat162 ph; ph.x = h0; ph.y = h1;
    __nv_bfloat162 pl; pl.x = l0; pl.y = l1;
    hi = *(uint32_t*)&ph;
    lo = *(uint32_t*)&pl;
}

// ---------------------------------------------------------------------------
// mma.sync split-bf16 GEMM:
//   C[M,N] = A(MxK,rm) * W(NxK,rm)^T + T(Mx16) * L2(Nx16)^T
// 128x128 CTA tile, BK=64, 8 warps (4m x 2n), warp tile 32x64.
// fp32 -> hi/lo bf16 smem planes, double buffered; 3 mma passes (hh, hl, lh).
// LoRA folded in as a 65th zero-padded K-chunk.
// ---------------------------------------------------------------------------
#define BK      64
#define LDSROW  72                       // bf16 per row (pad 8 -> 144B stride)
#define PLANE_B (128*LDSROW*2)           // bytes per plane = 18432
#define BUF_B   (4*PLANE_B)              // Ahi,Alo,Bhi,Blo = 73728
#define GEMM_SMEM_BYTES (2*BUF_B)        // 147456
#define NIT 65                           // 64 main + 1 lora

__global__ __launch_bounds__(256, 1) void gemm_mma(
    const float* __restrict__ A, const float* __restrict__ W,
    const float* __restrict__ T, int ldt, int toff,
    const float* __restrict__ L2,
    float* __restrict__ C)
{
    extern __shared__ char sm[];
    const int tid  = threadIdx.x;
    const int lane = tid & 31, wid = tid >> 5;
    const int wm = wid & 3, wn = wid >> 2;       // 4 x 2 warp grid
    const int m0 = blockIdx.y << 7;
    const int n0 = blockIdx.x << 7;
    const uint32_t sbase = smem_u32(sm);

    float acc[2][8][4];
    #pragma unroll
    for (int mt = 0; mt < 2; ++mt)
        #pragma unroll
        for (int nt = 0; nt < 8; ++nt)
            #pragma unroll
            for (int e = 0; e < 4; ++e) acc[mt][nt][e] = 0.f;

    // per-thread staging: 8 float4 of A, 8 float4 of B (row r=u>>4, col4 = u&15)
    float4 rga[8], rgb[8];

    // ---- global load for chunk kt into registers ----
    auto g_load = [&](int kt) {
        if (kt < 64) {
            const float* Ap = A + (size_t)m0*Dd + kt*BK;
            const float* Bp = W + (size_t)n0*Dd + kt*BK;
            #pragma unroll
            for (int it = 0; it < 8; ++it) {
                int u = tid + it*256;
                int r = u >> 4, c4 = u & 15;
                rga[it] = *(const float4*)(Ap + (size_t)r*Dd + c4*4);
                rgb[it] = *(const float4*)(Bp + (size_t)r*Dd + c4*4);
            }
        } else {
            const float4 z = make_float4(0.f, 0.f, 0.f, 0.f);
            #pragma unroll
            for (int it = 0; it < 8; ++it) {
                int u = tid + it*256;
                int r = u >> 4, c4 = u & 15;
                rga[it] = (c4 < 4) ? *(const float4*)(T + (size_t)(m0 + r)*ldt + toff + c4*4) : z;
                rgb[it] = (c4 < 4) ? *(const float4*)(L2 + (size_t)(n0 + r)*16 + c4*4) : z;
            }
        }
    };
    // ---- convert + store staging into smem buffer ----
    auto s_store = [&](int buf) {
        const uint32_t base = sbase + buf*BUF_B;
        #pragma unroll
        for (int it = 0; it < 8; ++it) {
            int u = tid + it*256;
            int r = u >> 4, c4 = u & 15;
            uint32_t off = (uint32_t)r*144 + c4*8;   // bytes
            uint32_t h0, h1, l0, l1;
            split2(rga[it].x, rga[it].y, h0, l0);
            split2(rga[it].z, rga[it].w, h1, l1);
            uint2 vh = make_uint2(h0, h1), vl = make_uint2(l0, l1);
            *(uint2*)(sm + (base - sbase) + off)            = vh;    // Ahi
            *(uint2*)(sm + (base - sbase) + PLANE_B + off)  = vl;    // Alo
            split2(rgb[it].x, rgb[it].y, h0, l0);
            split2(rgb[it].z, rgb[it].w, h1, l1);
            vh = make_uint2(h0, h1); vl = make_uint2(l0, l1);
            *(uint2*)(sm + (base - sbase) + 2*PLANE_B + off) = vh;   // Bhi
            *(uint2*)(sm + (base - sbase) + 3*PLANE_B + off) = vl;   // Blo
        }
    };

    g_load(0);
    s_store(0);
    __syncthreads();

    for (int kt = 0; kt < NIT; ++kt) {
        const int cur = kt & 1;
        const bool nxt = (kt + 1 < NIT);
        if (nxt) g_load(kt + 1);

        const uint32_t aAhi = sbase + cur*BUF_B;
        const uint32_t aBhi = aAhi + 2*PLANE_B;
        #pragma unroll
        for (int kk = 0; kk < 4; ++kk) {
            uint32_t ah[2][4], al[2][4];
            #pragma unroll
            for (int mt = 0; mt < 2; ++mt) {
                int row = wm*32 + mt*16 + (lane & 15);
                uint32_t addr = aAhi + (uint32_t)row*144 + (kk*16 + (lane >> 4)*8)*2;
                ldmx4(ah[mt], addr);
                ldmx4(al[mt], addr + PLANE_B);
            }
            uint32_t bh[8][2], bl[8][2];
            #pragma unroll
            for (int np = 0; np < 4; ++np) {
                int nrow = wn*64 + np*16 + (lane >> 4)*8 + (lane & 7);
                uint32_t addr = aBhi + (uint32_t)nrow*144 + (kk*16 + ((lane >> 3) & 1)*8)*2;
                uint32_t t[4];
                ldmx4(t, addr);
                bh[2*np][0] = t[0]; bh[2*np][1] = t[1];
                bh[2*np+1][0] = t[2]; bh[2*np+1][1] = t[3];
                ldmx4(t, addr + PLANE_B);
                bl[2*np][0] = t[0]; bl[2*np][1] = t[1];
                bl[2*np+1][0] = t[2]; bl[2*np+1][1] = t[3];
            }
            #pragma unroll
            for (int mt = 0; mt < 2; ++mt)
                #pragma unroll
                for (int nt = 0; nt < 8; ++nt) {
                    mma16816(acc[mt][nt], ah[mt], bh[nt]);
                    mma16816(acc[mt][nt], ah[mt], bl[nt]);
                    mma16816(acc[mt][nt], al[mt], bh[nt]);
                }
        }
        if (nxt) s_store(cur ^ 1);
        __syncthreads();
    }

    // epilogue: c-frag -> C.  c0,c1: row lane/4, cols 2*(lane%4)+{0,1}; c2,c3: row+8
    #pragma unroll
    for (int mt = 0; mt < 2; ++mt) {
        const int row = m0 + wm*32 + mt*16 + (lane >> 2);
        #pragma unroll
        for (int nt = 0; nt < 8; ++nt) {
            const int col = n0 + wn*64 + nt*8 + (lane & 3)*2;
            *(float2*)(C + (size_t)row*Dd + col)       = make_float2(acc[mt][nt][0], acc[mt][nt][1]);
            *(float2*)(C + (size_t)(row + 8)*Dd + col) = make_float2(acc[mt][nt][2], acc[mt][nt][3]);
        }
    }
}

// ---------------------------------------------------------------------------
// T = X @ [L1a;L1b;L1c]^T   (rank-16 LoRA intermediates).  64-row tiles.
// ---------------------------------------------------------------------------
__global__ __launch_bounds__(256) void lora_t_kernel(
    const float* __restrict__ X,
    const float* __restrict__ L1a, const float* __restrict__ L1b, const float* __restrict__ L1c,
    float* __restrict__ T, int nmat, int ldt, int Ktot)
{
    __shared__ float Xs[32][68];   // [k][m]
    __shared__ float Ls[32][52];   // [k][r]
    const int tid = threadIdx.x;
    const int tx = tid & 15, ty = tid >> 4;
    const int m0 = blockIdx.x << 6;
    const int Rtot = nmat << 4;
    float acc[4][3];
    #pragma unroll
    for (int i = 0; i < 4; ++i)
        #pragma unroll
        for (int j = 0; j < 3; ++j) acc[i][j] = 0.f;

    for (int k0 = 0; k0 < Ktot; k0 += 32) {
        __syncthreads();
        #pragma unroll
        for (int i = 0; i < 2; ++i) {
            int v = tid + i*256;
            int r = v >> 3, c = (v & 7) << 2;
            float4 x4 = *(const float4*)(X + (size_t)(m0 + r)*Ktot + k0 + c);
            Xs[c+0][r]=x4.x; Xs[c+1][r]=x4.y; Xs[c+2][r]=x4.z; Xs[c+3][r]=x4.w;
        }
        for (int v = tid; v < Rtot*8; v += 256) {
            int r = v >> 3, c = (v & 7) << 2;
            const float* src = (r < 16) ? (L1a + (size_t)r*Ktot)
                             : (r < 32) ? (L1b + (size_t)(r-16)*Ktot)
                                        : (L1c + (size_t)(r-32)*Ktot);
            float4 l4 = *(const float4*)(src + k0 + c);
            Ls[c+0][r]=l4.x; Ls[c+1][r]=l4.y; Ls[c+2][r]=l4.z; Ls[c+3][r]=l4.w;
        }
        __syncthreads();
        #pragma unroll
        for (int k = 0; k < 32; ++k) {
            float xv[4];
            #pragma unroll
            for (int i = 0; i < 4; ++i) xv[i] = Xs[k][4*ty + i];
            for (int j = 0; j < nmat; ++j) {
                float lv = Ls[k][tx + 16*j];
                #pragma unroll
                for (int i = 0; i < 4; ++i) acc[i][j] = fmaf(xv[i], lv, acc[i][j]);
            }
        }
    }
    for (int j = 0; j < nmat; ++j)
        #pragma unroll
        for (int i = 0; i < 4; ++i)
            T[(size_t)(m0 + 4*ty + i)*ldt + tx + 16*j] = acc[i][j];
}

// ---------------------------------------------------------------------------
// Adapter K/V projection: AK = Ad(20xK) @ Wk^T, AV = Ad @ Wv^T (no LoRA).
// ---------------------------------------------------------------------------
__global__ __launch_bounds__(256) void adapter_proj_kernel(
    const float* __restrict__ Ad, const float* __restrict__ Wk, const float* __restrict__ Wv,
    float* __restrict__ AK, float* __restrict__ AV, int Ktot, int Ntot)
{
    __shared__ float Ads[20][68];   // [m][k]
    __shared__ float Wks[64][65];   // [k][n]
    __shared__ float Wvs[64][65];
    const int tid = threadIdx.x;
    const int nl = tid & 63, mg = tid >> 6;
    const int n0 = blockIdx.x << 6;
    float ak[5] = {0,0,0,0,0}, av[5] = {0,0,0,0,0};

    for (int k0 = 0; k0 < Ktot; k0 += 64) {
        __syncthreads();
        for (int v = tid; v < 320; v += 256) {
            int r = v >> 4, c = (v & 15) << 2;
            float4 a4 = *(const float4*)(Ad + (size_t)r*Ktot + k0 + c);
            Ads[r][c+0]=a4.x; Ads[r][c+1]=a4.y; Ads[r][c+2]=a4.z; Ads[r][c+3]=a4.w;
        }
        #pragma unroll
        for (int i = 0; i < 4; ++i) {
            int v = tid + i*256;
            int r = v >> 4, c = (v & 15) << 2;
            float4 w4 = *(const float4*)(Wk + (size_t)(n0 + r)*Ktot + k0 + c);
            Wks[c+0][r]=w4.x; Wks[c+1][r]=w4.y; Wks[c+2][r]=w4.z; Wks[c+3][r]=w4.w;
            float4 w5 = *(const float4*)(Wv + (size_t)(n0 + r)*Ktot + k0 + c);
            Wvs[c+0][r]=w5.x; Wvs[c+1][r]=w5.y; Wvs[c+2][r]=w5.z; Wvs[c+3][r]=w5.w;
        }
        __syncthreads();
        #pragma unroll
        for (int k = 0; k < 64; ++k) {
            float wkv = Wks[k][nl];
            float wvv = Wvs[k][nl];
            #pragma unroll
            for (int i = 0; i < 5; ++i) {
                float a = Ads[5*mg + i][k];
                ak[i] = fmaf(a, wkv, ak[i]);
                av[i] = fmaf(a, wvv, av[i]);
            }
        }
    }
    #pragma unroll
    for (int i = 0; i < 5; ++i) {
        AK[(size_t)(5*mg + i)*Ntot + n0 + nl] = ak[i];
        AV[(size_t)(5*mg + i)*Ntot + n0 + nl] = av[i];
    }
}

// ---------------------------------------------------------------------------
// Flash attention, fp32, causal. 64 q-rows x 64 k-cols tiles, HD=128.
// ---------------------------------------------------------------------------
#define FLASH_SMEM_FLOATS (64*132 + 128*68 + 64*132 + 64*68)
#define FLASH_SMEM_BYTES  (FLASH_SMEM_FLOATS*4)

__global__ __launch_bounds__(256) void flash_kernel(
    const float* __restrict__ XQ, const float* __restrict__ XK,
    const float* __restrict__ XV, float* __restrict__ O)
{
    extern __shared__ float smf[];
    float* Qs  = smf;                     // [64][132]
    float* Kts = smf + 64*132;            // [128][68]
    float* Vs  = Kts + 128*68;            // [64][132]
    float* Ps  = Vs + 64*132;             // [64][68]

    const int tid = threadIdx.x;
    const int tx = tid & 15, ty = tid >> 4;
    const int q0 = blockIdx.x << 6;
    const int h = blockIdx.y, b = blockIdx.z;
    const size_t hoff = (size_t)h * HDd;
    const float scale = 0.08838834764831845f;

    #pragma unroll
    for (int t = 0; t < 8; ++t) {
        int v = tid + t*256;
        int r = v >> 5, c = (v & 31) << 2;
        float4 q4 = *(const float4*)(XQ + ((size_t)(b*Ss + q0 + r))*Dd + hoff + c);
        *(float4*)&Qs[r*132 + c] = q4;
    }

    float o[4][8];
    #pragma unroll
    for (int i = 0; i < 4; ++i)
        #pragma unroll
        for (int j = 0; j < 8; ++j) o[i][j] = 0.f;
    float m[4] = {-1e30f,-1e30f,-1e30f,-1e30f};
    float l[4] = {0.f,0.f,0.f,0.f};

    const int ktEnd = blockIdx.x;
    for (int kt = 0; kt <= ktEnd; ++kt) {
        const int k0 = kt << 6;
        __syncthreads();
        #pragma unroll
        for (int t = 0; t < 8; ++t) {
            int v = tid + t*256;
            int r = v >> 5, c = (v & 31) << 2;
            float4 k4 = *(const float4*)(XK + ((size_t)(b*Ss + k0 + r))*Dd + hoff + c);
            Kts[(c+0)*68 + r]=k4.x; Kts[(c+1)*68 + r]=k4.y; Kts[(c+2)*68 + r]=k4.z; Kts[(c+3)*68 + r]=k4.w;
            float4 v4 = *(const float4*)(XV + ((size_t)(b*Ss + k0 + r))*Dd + hoff + c);
            *(float4*)&Vs[r*132 + c] = v4;
        }
        __syncthreads();

        float s[4][4];
        #pragma unroll
        for (int i = 0; i < 4; ++i)
            #pragma unroll
            for (int j = 0; j < 4; ++j) s[i][j] = 0.f;
        #pragma unroll
        for (int k4i = 0; k4i < 32; ++k4i) {
            float4 qf[4];
            #pragma unroll
            for (int i = 0; i < 4; ++i) qf[i] = *(const float4*)&Qs[(4*ty+i)*132 + 4*k4i];
            #pragma unroll
            for (int e = 0; e < 4; ++e) {
                float4 kf = *(const float4*)&Kts[(4*k4i + e)*68 + 4*tx];
                #pragma unroll
                for (int i = 0; i < 4; ++i) {
                    float qv = ((const float*)&qf[i])[e];
                    s[i][0] = fmaf(qv, kf.x, s[i][0]);
                    s[i][1] = fmaf(qv, kf.y, s[i][1]);
                    s[i][2] = fmaf(qv, kf.z, s[i][2]);
                    s[i][3] = fmaf(qv, kf.w, s[i][3]);
                }
            }
        }

        const bool diag = (kt == ktEnd);
        #pragma unroll
        for (int i = 0; i < 4; ++i) {
            const int qr = q0 + 4*ty + i;
            #pragma unroll
            for (int j = 0; j < 4; ++j) {
                float sv = s[i][j] * scale;
                if (diag && (k0 + 4*tx + j > qr)) sv = -1e30f;
                s[i][j] = sv;
            }
            float rm = fmaxf(fmaxf(s[i][0], s[i][1]), fmaxf(s[i][2], s[i][3]));
            #pragma unroll
            for (int off = 8; off > 0; off >>= 1)
                rm = fmaxf(rm, __shfl_xor_sync(0xffffffffu, rm, off, 16));
            float mn = fmaxf(m[i], rm);
            float corr = __expf(m[i] - mn);
            float rs = 0.f;
            #pragma unroll
            for (int j = 0; j < 4; ++j) { s[i][j] = __expf(s[i][j] - mn); rs += s[i][j]; }
            #pragma unroll
            for (int off = 8; off > 0; off >>= 1)
                rs += __shfl_xor_sync(0xffffffffu, rs, off, 16);
            l[i] = l[i]*corr + rs;
            m[i] = mn;
            #pragma unroll
            for (int j = 0; j < 8; ++j) o[i][j] *= corr;
            #pragma unroll
            for (int j = 0; j < 4; ++j) Ps[(4*ty+i)*68 + 4*tx + j] = s[i][j];
        }
        __syncthreads();

        #pragma unroll
        for (int kb = 0; kb < 16; ++kb) {
            float4 p4[4];
            #pragma unroll
            for (int i = 0; i < 4; ++i) p4[i] = *(const float4*)&Ps[(4*ty+i)*68 + 4*kb];
            #pragma unroll
            for (int e = 0; e < 4; ++e) {
                const int k = 4*kb + e;
                float4 v0 = *(const float4*)&Vs[k*132 + 8*tx];
                float4 v1 = *(const float4*)&Vs[k*132 + 8*tx + 4];
                #pragma unroll
                for (int i = 0; i < 4; ++i) {
                    float pv = ((const float*)&p4[i])[e];
                    o[i][0] = fmaf(pv, v0.x, o[i][0]);
                    o[i][1] = fmaf(pv, v0.y, o[i][1]);
                    o[i][2] = fmaf(pv, v0.z, o[i][2]);
                    o[i][3] = fmaf(pv, v0.w, o[i][3]);
                    o[i][4] = fmaf(pv, v1.x, o[i][4]);
                    o[i][5] = fmaf(pv, v1.y, o[i][5]);
                    o[i][6] = fmaf(pv, v1.z, o[i][6]);
                    o[i][7] = fmaf(pv, v1.w, o[i][7]);
                }
            }
        }
    }

    #pragma unroll
    for (int i = 0; i < 4; ++i) {
        float inv = 1.f / l[i];
        float* op = O + ((size_t)(b*Ss + q0 + 4*ty + i))*Dd + hoff + 8*tx;
        *(float4*)op     = make_float4(o[i][0]*inv, o[i][1]*inv, o[i][2]*inv, o[i][3]*inv);
        *(float4*)(op+4) = make_float4(o[i][4]*inv, o[i][5]*inv, o[i][6]*inv, o[i][7]*inv);
    }
}

// ---------------------------------------------------------------------------
// Gated adapter cross-attention (adds in place)
// ---------------------------------------------------------------------------
__global__ __launch_bounds__(256) void adapter_attn_kernel(
    const float* __restrict__ XQ, const float* __restrict__ AK, const float* __restrict__ AV,
    const float* __restrict__ gate, const float* __restrict__ ngate, float* __restrict__ O)
{
    __shared__ float aks[ALa][HDd];
    __shared__ float avs[ALa][HDd];
    const int tid = threadIdx.x;
    const int q0 = blockIdx.x << 6;
    const int h = blockIdx.y, b = blockIdx.z;
    const size_t hoff = (size_t)h * HDd;
    const float scale = 0.08838834764831845f;

    for (int v = tid; v < ALa*32; v += 256) {
        int r = v >> 5, c = (v & 31) << 2;
        *(float4*)&aks[r][c] = *(const float4*)(AK + ((size_t)(b*ALa + r))*Dd + hoff + c);
        *(float4*)&avs[r][c] = *(const float4*)(AV + ((size_t)(b*ALa + r))*Dd + hoff + c);
    }
    __syncthreads();

    const int lane = tid & 31, wid = tid >> 5;
    const float g = tanhf(gate[h]) * ngate[0];

    for (int it = 0; it < 8; ++it) {
        const int q = q0 + it*8 + wid;
        const float* qp = XQ + ((size_t)(b*Ss + q))*Dd + hoff;
        float qv[4];
        #pragma unroll
        for (int e = 0; e < 4; ++e) qv[e] = qp[lane + 32*e];

        float p[ALa];
        float mx = -1e30f;
        #pragma unroll
        for (int j = 0; j < ALa; ++j) {
            float sc = 0.f;
            #pragma unroll
            for (int e = 0; e < 4; ++e) sc = fmaf(qv[e], aks[j][lane + 32*e], sc);
            #pragma unroll
            for (int off = 16; off > 0; off >>= 1) sc += __shfl_xor_sync(0xffffffffu, sc, off);
            sc *= scale;
            p[j] = sc;
            mx = fmaxf(mx, sc);
        }
        float sum = 0.f;
        #pragma unroll
        for (int j = 0; j < ALa; ++j) { p[j] = __expf(p[j] - mx); sum += p[j]; }
        const float w = g / sum;

        float* op = O + ((size_t)(b*Ss + q))*Dd + hoff;
        #pragma unroll
        for (int e = 0; e < 4; ++e) {
            float acc = 0.f;
            #pragma unroll
            for (int j = 0; j < ALa; ++j) acc = fmaf(p[j], avs[j][lane + 32*e], acc);
            op[lane + 32*e] += acc * w;
        }
    }
}

// ---------------------------------------------------------------------------
// Launch
// ---------------------------------------------------------------------------
extern "C" void kernel_launch(void* const* d_in, const int* in_sizes, int n_in,
                              void* d_out, int out_size)
{
    (void)in_sizes; (void)n_in; (void)out_size;
    const float* x       = (const float*)d_in[0];
    const float* adapter = (const float*)d_in[4];
    const float* wq  = (const float*)d_in[5];
    const float* wk  = (const float*)d_in[6];
    const float* wv  = (const float*)d_in[7];
    const float* wo  = (const float*)d_in[8];
    const float* lq1 = (const float*)d_in[9];
    const float* lq2 = (const float*)d_in[10];
    const float* lk1 = (const float*)d_in[11];
    const float* lk2 = (const float*)d_in[12];
    const float* lv1 = (const float*)d_in[13];
    const float* lv2 = (const float*)d_in[14];
    const float* lo1 = (const float*)d_in[15];
    const float* lo2 = (const float*)d_in[16];
    const float* gate  = (const float*)d_in[17];
    const float* ngate = (const float*)d_in[18];
    float* out = (float*)d_out;

    float *xq, *xk, *xv, *att, *T, *To, *ak, *av;
    cudaGetSymbolAddress((void**)&xq,  g_xq);
    cudaGetSymbolAddress((void**)&xk,  g_xk);
    cudaGetSymbolAddress((void**)&xv,  g_xv);
    cudaGetSymbolAddress((void**)&att, g_att);
    cudaGetSymbolAddress((void**)&T,   g_T);
    cudaGetSymbolAddress((void**)&To,  g_To);
    cudaGetSymbolAddress((void**)&ak,  g_ak);
    cudaGetSymbolAddress((void**)&av,  g_av);

    cudaFuncSetAttribute(flash_kernel, cudaFuncAttributeMaxDynamicSharedMemorySize, FLASH_SMEM_BYTES);
    cudaFuncSetAttribute(gemm_mma, cudaFuncAttributeMaxDynamicSharedMemorySize, GEMM_SMEM_BYTES);

    const dim3 gGrid(Dd/128, MROWS/128);   // (32, 32)

    // 1) LoRA intermediates for q/k/v
    lora_t_kernel<<<MROWS/64, 256>>>(x, lq1, lk1, lv1, T, 3, 48, Dd);
    // 2) QKV projections, split-bf16 mma.sync, LoRA folded in
    gemm_mma<<<gGrid, 256, GEMM_SMEM_BYTES>>>(x, wq, T, 48, 0,  lq2, xq);
    gemm_mma<<<gGrid, 256, GEMM_SMEM_BYTES>>>(x, wk, T, 48, 16, lk2, xk);
    gemm_mma<<<gGrid, 256, GEMM_SMEM_BYTES>>>(x, wv, T, 48, 32, lv2, xv);
    // 3) adapter K/V projection
    adapter_proj_kernel<<<Dd/64, 256>>>(adapter, wk, wv, ak, av, Dd, Dd);
    // 4) causal flash attention
    flash_kernel<<<dim3(Ss/64, Hh, Bb), 256, FLASH_SMEM_BYTES>>>(xq, xk, xv, att);
    // 5) gated adapter cross-attention, added in place
    adapter_attn_kernel<<<dim3(Ss/64, Hh, Bb), 256>>>(xq, ak, av, gate, ngate, att);
    // 6) output LoRA intermediate + output projection
    lora_t_kernel<<<MROWS/64, 256>>>(att, lo1, lo1, lo1, To, 1, 16, Dd);
    gemm_mma<<<gGrid, 256, GEMM_SMEM_BYTES>>>(att, wo, To, 16, 0, lo2, out);
}

// round 5
// speedup vs baseline: 1.9335x; 1.2972x over previous
#include <cuda_runtime.h>
#include <cuda_bf16.h>
#include <math.h>
#include <stdint.h>

// Problem constants
#define Bb   2
#define Ss   2048
#define Dd   4096
#define Hh   32
#define HDd  128
#define ALa  10
#define MROWS (Bb*Ss)          // 4096
#define KP   4160              // 4096 + 64 (LoRA chunk)
#define NCH  65                // K'/64

// ---------------------------------------------------------------------------
// Scratch (device globals; no cudaMalloc allowed)
// ---------------------------------------------------------------------------
__device__ float g_xq [MROWS*Dd];
__device__ float g_att[MROWS*Dd];
__device__ float g_dmp[MROWS*Dd];         // dump target for xk/xv fp32 (unused)
__device__ float g_T  [MROWS*48];
__device__ float g_To [MROWS*16];
__device__ float g_ak [Bb*ALa*Dd];
__device__ float g_av [Bb*ALa*Dd];
__device__ __nv_bfloat16 g_cvAhi[MROWS*KP];
__device__ __nv_bfloat16 g_cvAlo[MROWS*KP];
__device__ __nv_bfloat16 g_cvBhi[Dd*KP];
__device__ __nv_bfloat16 g_cvBlo[Dd*KP];
__device__ __nv_bfloat16 g_qhi[MROWS*Dd];
__device__ __nv_bfloat16 g_qlo[MROWS*Dd];
__device__ __nv_bfloat16 g_khi[MROWS*Dd];
__device__ __nv_bfloat16 g_klo[MROWS*Dd];
__device__ __nv_bfloat16 g_vhi[MROWS*Dd];
__device__ __nv_bfloat16 g_vlo[MROWS*Dd];

// ---------------------------------------------------------------------------
// helpers
// ---------------------------------------------------------------------------
__device__ __forceinline__ uint32_t smem_u32(const void* p) {
    uint32_t a;
    asm("{ .reg .u64 t; cvta.to.shared.u64 t, %1; cvt.u32.u64 %0, t; }" : "=r"(a) : "l"(p));
    return a;
}
__device__ __forceinline__ void cpa16(uint32_t dst, const void* src) {
    asm volatile("cp.async.cg.shared.global [%0], [%1], 16;" :: "r"(dst), "l"(src));
}
__device__ __forceinline__ void cpa_commit() { asm volatile("cp.async.commit_group;"); }
#define CPA_WAIT(N) asm volatile("cp.async.wait_group %0;" :: "n"(N))
__device__ __forceinline__ void ldmx4(uint32_t* r, uint32_t addr) {
    asm volatile("ldmatrix.sync.aligned.m8n8.x4.shared.b16 {%0,%1,%2,%3}, [%4];"
                 : "=r"(r[0]), "=r"(r[1]), "=r"(r[2]), "=r"(r[3]) : "r"(addr));
}
__device__ __forceinline__ void ldmx4t(uint32_t* r, uint32_t addr) {
    asm volatile("ldmatrix.sync.aligned.m8n8.x4.trans.shared.b16 {%0,%1,%2,%3}, [%4];"
                 : "=r"(r[0]), "=r"(r[1]), "=r"(r[2]), "=r"(r[3]) : "r"(addr));
}
__device__ __forceinline__ void mma16816(float* c, const uint32_t* a, const uint32_t* b) {
    asm volatile(
        "mma.sync.aligned.m16n8k16.row.col.f32.bf16.bf16.f32 "
        "{%0,%1,%2,%3}, {%4,%5,%6,%7}, {%8,%9}, {%0,%1,%2,%3};"
        : "+f"(c[0]), "+f"(c[1]), "+f"(c[2]), "+f"(c[3])
        : "r"(a[0]), "r"(a[1]), "r"(a[2]), "r"(a[3]), "r"(b[0]), "r"(b[1]));
}
__device__ __forceinline__ void split2(float f0, float f1, uint32_t& hi, uint32_t& lo) {
    __nv_bfloat16 h0 = __float2bfloat16_rn(f0);
    __nv_bfloat16 h1 = __float2bfloat16_rn(f1);
    __nv_bfloat16 l0 = __float2bfloat16_rn(f0 - __bfloat162float(h0));
    __nv_bfloat16 l1 = __float2bfloat16_rn(f1 - __bfloat162float(h1));
    __nv_bfloat162 ph; ph.x = h0; ph.y = h1;
    __nv_bfloat162 pl; pl.x = l0; pl.y = l1;
    hi = *(uint32_t*)&ph;
    lo = *(uint32_t*)&pl;
}

// ---------------------------------------------------------------------------
// conv_split: dst[M x KP] (hi/lo bf16) = [src(Mx4096) | lora block | zeros]
// extra col e = c-4096: value = (e in [lshift, lshift+lcols)) ? lsrc[r*ldl+e-lshift] : 0
// ---------------------------------------------------------------------------
__global__ __launch_bounds__(256) void conv_split(
    const float* __restrict__ src,
    const float* __restrict__ lsrc, int ldl, int lcols, int lshift,
    __nv_bfloat16* __restrict__ dhi, __nv_bfloat16* __restrict__ dlo)
{
    const int u = blockIdx.x * 256 + threadIdx.x;       // grid covers M*520 exactly
    const int r = u / 520, g = u % 520;
    float f[8];
    if (g < 512) {
        float4 a = *(const float4*)(src + (size_t)r*4096 + g*8);
        float4 b = *(const float4*)(src + (size_t)r*4096 + g*8 + 4);
        f[0]=a.x; f[1]=a.y; f[2]=a.z; f[3]=a.w; f[4]=b.x; f[5]=b.y; f[6]=b.z; f[7]=b.w;
    } else {
        #pragma unroll
        for (int i = 0; i < 8; ++i) {
            int e = g*8 - 4096 + i;
            int lc = e - lshift;
            f[i] = (lc >= 0 && lc < lcols) ? lsrc[(size_t)r*ldl + lc] : 0.f;
        }
    }
    uint32_t h[4], l[4];
    #pragma unroll
    for (int e = 0; e < 4; ++e) split2(f[2*e], f[2*e+1], h[e], l[e]);
    *(uint4*)(dhi + (size_t)r*KP + g*8) = make_uint4(h[0], h[1], h[2], h[3]);
    *(uint4*)(dlo + (size_t)r*KP + g*8) = make_uint4(l[0], l[1], l[2], l[3]);
}

// ---------------------------------------------------------------------------
// Pure-bf16 mma GEMM with cp.async 3-stage pipeline.
//   C[M,N] = (Ahi+Alo)(M x KP) * (Bhi+Blo)(N x KP)^T   (3 passes: hh, hl, lh)
// 128x128 CTA tile, chunk=64 k. smem rows: 64 bf16 = 128B, chunk-XOR swizzle.
// Optionally also writes bf16 hi/lo planes of C (for flash operands).
// ---------------------------------------------------------------------------
#define GPLANE 16384
#define GSTGB  (4*GPLANE)
#define GEMM_SMEM (3*GSTGB)   // 196608

__global__ __launch_bounds__(256, 1) void gemm_bf(
    const __nv_bfloat16* __restrict__ Ahi, const __nv_bfloat16* __restrict__ Alo,
    const __nv_bfloat16* __restrict__ Bhi, const __nv_bfloat16* __restrict__ Blo,
    float* __restrict__ C, __nv_bfloat16* __restrict__ Chi, __nv_bfloat16* __restrict__ Clo)
{
    extern __shared__ char smg[];
    const int tid = threadIdx.x;
    const int lane = tid & 31, wid = tid >> 5;
    const int wm = wid & 3, wn = wid >> 2;
    const int m0 = blockIdx.y << 7;
    const int n0 = blockIdx.x << 7;
    const uint32_t sbase = smem_u32(smg);

    float acc[2][8][4];
    #pragma unroll
    for (int mt = 0; mt < 2; ++mt)
        #pragma unroll
        for (int nt = 0; nt < 8; ++nt)
            #pragma unroll
            for (int e = 0; e < 4; ++e) acc[mt][nt][e] = 0.f;

    auto load_st = [&](int kt, int s) {
        const __nv_bfloat16* srcs[4] = {
            Ahi + (size_t)m0*KP + kt*64, Alo + (size_t)m0*KP + kt*64,
            Bhi + (size_t)n0*KP + kt*64, Blo + (size_t)n0*KP + kt*64 };
        const uint32_t base = sbase + s*GSTGB;
        #pragma unroll
        for (int p = 0; p < 4; ++p) {
            #pragma unroll
            for (int i = 0; i < 4; ++i) {
                int u = tid + i*256;
                int r = u >> 3, c = u & 7;
                cpa16(base + p*GPLANE + r*128 + (((uint32_t)c ^ (r & 7)) << 4),
                      srcs[p] + (size_t)r*KP + c*8);
            }
        }
        cpa_commit();
    };

    load_st(0, 0);
    load_st(1, 1);

    for (int kt = 0; kt < NCH; ++kt) {
        const int s = kt % 3;
        CPA_WAIT(1);
        __syncthreads();

        const uint32_t aAhi = sbase + s*GSTGB;
        const uint32_t aAlo = aAhi + GPLANE;
        const uint32_t aBhi = aAhi + 2*GPLANE;
        const uint32_t aBlo = aAhi + 3*GPLANE;
        #pragma unroll
        for (int kk = 0; kk < 4; ++kk) {
            uint32_t ah[2][4], al[2][4];
            #pragma unroll
            for (int mt = 0; mt < 2; ++mt) {
                int row = wm*32 + mt*16 + (lane & 15);
                uint32_t c = kk*2 + (lane >> 4);
                uint32_t off = (uint32_t)row*128 + ((c ^ (row & 7)) << 4);
                ldmx4(ah[mt], aAhi + off);
                ldmx4(al[mt], aAlo + off);
            }
            uint32_t bh[8][2], bl[8][2];
            #pragma unroll
            for (int np = 0; np < 4; ++np) {
                int nrow = wn*64 + np*16 + (lane >> 4)*8 + (lane & 7);
                uint32_t c = kk*2 + ((lane >> 3) & 1);
                uint32_t off = (uint32_t)nrow*128 + ((c ^ (nrow & 7)) << 4);
                uint32_t t[4];
                ldmx4(t, aBhi + off);
                bh[2*np][0]=t[0]; bh[2*np][1]=t[1]; bh[2*np+1][0]=t[2]; bh[2*np+1][1]=t[3];
                ldmx4(t, aBlo + off);
                bl[2*np][0]=t[0]; bl[2*np][1]=t[1]; bl[2*np+1][0]=t[2]; bl[2*np+1][1]=t[3];
            }
            #pragma unroll
            for (int mt = 0; mt < 2; ++mt)
                #pragma unroll
                for (int nt = 0; nt < 8; ++nt) {
                    mma16816(acc[mt][nt], ah[mt], bh[nt]);
                    mma16816(acc[mt][nt], ah[mt], bl[nt]);
                    mma16816(acc[mt][nt], al[mt], bh[nt]);
                }
        }
        if (kt + 2 < NCH) load_st(kt + 2, (kt + 2) % 3);
    }

    // epilogue
    #pragma unroll
    for (int mt = 0; mt < 2; ++mt) {
        const int row = m0 + wm*32 + mt*16 + (lane >> 2);
        #pragma unroll
        for (int nt = 0; nt < 8; ++nt) {
            const int col = n0 + wn*64 + nt*8 + (lane & 3)*2;
            *(float2*)(C + (size_t)row*Dd + col)       = make_float2(acc[mt][nt][0], acc[mt][nt][1]);
            *(float2*)(C + (size_t)(row + 8)*Dd + col) = make_float2(acc[mt][nt][2], acc[mt][nt][3]);
            if (Chi) {
                uint32_t h, l;
                split2(acc[mt][nt][0], acc[mt][nt][1], h, l);
                *(uint32_t*)(Chi + (size_t)row*Dd + col) = h;
                *(uint32_t*)(Clo + (size_t)row*Dd + col) = l;
                split2(acc[mt][nt][2], acc[mt][nt][3], h, l);
                *(uint32_t*)(Chi + (size_t)(row + 8)*Dd + col) = h;
                *(uint32_t*)(Clo + (size_t)(row + 8)*Dd + col) = l;
            }
        }
    }
}

// ---------------------------------------------------------------------------
// Flash attention on mma.sync, split-bf16, causal.
// CTA: 128 q rows x 64 kv per iter. 8 warps, warp = 16 q rows.
// Q/K/V read as precomputed hi/lo bf16 planes. O (fp32) = g_att.
// smem: Q hi/lo (2x32KB) + 2 stages x (K hi/lo + V hi/lo = 64KB) = 192KB.
// ---------------------------------------------------------------------------
#define FQPL 32768
#define FKPL 16384
#define FKVSTG (4*FKPL)
#define FLASH_SMEM (2*FQPL + 2*FKVSTG)   // 196608

__global__ __launch_bounds__(256, 1) void flash_mma(
    const __nv_bfloat16* __restrict__ Qhi, const __nv_bfloat16* __restrict__ Qlo,
    const __nv_bfloat16* __restrict__ Khi, const __nv_bfloat16* __restrict__ Klo,
    const __nv_bfloat16* __restrict__ Vhi, const __nv_bfloat16* __restrict__ Vlo,
    float* __restrict__ O)
{
    extern __shared__ char smf[];
    const int tid = threadIdx.x;
    const int lane = tid & 31, w = tid >> 5;
    const int qt = blockIdx.x, h = blockIdx.y, b = blockIdx.z;
    const int q0 = qt << 7;
    const uint32_t sbase = smem_u32(smf);
    const float scale = 0.08838834764831845f;

    // load Q planes (swizzled 256B rows)
    {
        const __nv_bfloat16* srcs[2] = {
            Qhi + (size_t)(b*Ss + q0)*Dd + h*HDd,
            Qlo + (size_t)(b*Ss + q0)*Dd + h*HDd };
        #pragma unroll
        for (int p = 0; p < 2; ++p)
            #pragma unroll
            for (int i = 0; i < 8; ++i) {
                int u = tid + i*256;
                int r = u >> 4, c = u & 15;
                uint32_t dst = sbase + p*FQPL + (uint32_t)r*256 + (c >> 3)*128
                             + ((((uint32_t)c & 7) ^ (r & 7)) << 4);
                cpa16(dst, srcs[p] + (size_t)r*Dd + c*8);
            }
    }
    auto loadKV = [&](int kt, int s) {
        const int k0 = kt << 6;
        const __nv_bfloat16* srcs[4] = {
            Khi + (size_t)(b*Ss + k0)*Dd + h*HDd, Klo + (size_t)(b*Ss + k0)*Dd + h*HDd,
            Vhi + (size_t)(b*Ss + k0)*Dd + h*HDd, Vlo + (size_t)(b*Ss + k0)*Dd + h*HDd };
        const uint32_t base = sbase + 2*FQPL + s*FKVSTG;
        #pragma unroll
        for (int p = 0; p < 4; ++p)
            #pragma unroll
            for (int i = 0; i < 4; ++i) {
                int u = tid + i*256;
                int r = u >> 4, c = u & 15;
                uint32_t dst = base + p*FKPL + (uint32_t)r*256 + (c >> 3)*128
                             + ((((uint32_t)c & 7) ^ (r & 7)) << 4);
                cpa16(dst, srcs[p] + (size_t)r*Dd + c*8);
            }
        cpa_commit();
    };
    loadKV(0, 0);   // Q cp.asyncs join this group

    float oacc[16][4];
    #pragma unroll
    for (int nt = 0; nt < 16; ++nt)
        #pragma unroll
        for (int e = 0; e < 4; ++e) oacc[nt][e] = 0.f;
    float mrow[2] = {-1e30f, -1e30f};
    float lrow[2] = {0.f, 0.f};

    const int nkt = 2*(qt + 1);
    for (int kt = 0; kt < nkt; ++kt) {
        const int s = kt & 1;
        CPA_WAIT(0);
        __syncthreads();
        if (kt + 1 < nkt) loadKV(kt + 1, s ^ 1);

        const uint32_t kb = sbase + 2*FQPL + s*FKVSTG;       // Khi; +FKPL = Klo
        const uint32_t vb = kb + 2*FKPL;                     // Vhi; +FKPL = Vlo

        // ---- S = Q K^T (3 passes over HD=128 in 8 k16 steps)
        float sacc[8][4];
        #pragma unroll
        for (int nt = 0; nt < 8; ++nt)
            #pragma unroll
            for (int e = 0; e < 4; ++e) sacc[nt][e] = 0.f;
        #pragma unroll
        for (int kk = 0; kk < 8; ++kk) {
            uint32_t ah[4], al[4];
            {
                int row = w*16 + (lane & 15);
                uint32_t c = kk*2 + (lane >> 4);
                uint32_t off = (uint32_t)row*256 + (c >> 3)*128 + (((c & 7) ^ (row & 7)) << 4);
                ldmx4(ah, sbase + off);
                ldmx4(al, sbase + FQPL + off);
            }
            uint32_t bh[8][2], bl[8][2];
            #pragma unroll
            for (int np = 0; np < 4; ++np) {
                int nrow = np*16 + (lane >> 4)*8 + (lane & 7);
                uint32_t c = kk*2 + ((lane >> 3) & 1);
                uint32_t off = (uint32_t)nrow*256 + (c >> 3)*128 + (((c & 7) ^ (nrow & 7)) << 4);
                uint32_t t[4];
                ldmx4(t, kb + off);
                bh[2*np][0]=t[0]; bh[2*np][1]=t[1]; bh[2*np+1][0]=t[2]; bh[2*np+1][1]=t[3];
                ldmx4(t, kb + FKPL + off);
                bl[2*np][0]=t[0]; bl[2*np][1]=t[1]; bl[2*np+1][0]=t[2]; bl[2*np+1][1]=t[3];
            }
            #pragma unroll
            for (int nt = 0; nt < 8; ++nt) {
                mma16816(sacc[nt], ah, bh[nt]);
                mma16816(sacc[nt], ah, bl[nt]);
                mma16816(sacc[nt], al, bh[nt]);
            }
        }

        // ---- mask + online softmax (rows: lane>>2 and +8)
        const int k0 = kt << 6;
        float corr[2];
        #pragma unroll
        for (int hh = 0; hh < 2; ++hh) {
            const int rowg = q0 + w*16 + (lane >> 2) + hh*8;
            float rmax = -1e30f;
            #pragma unroll
            for (int nt = 0; nt < 8; ++nt)
                #pragma unroll
                for (int e2 = 0; e2 < 2; ++e2) {
                    int colg = k0 + nt*8 + (lane & 3)*2 + e2;
                    float v = sacc[nt][hh*2 + e2] * scale;
                    if (colg > rowg) v = -1e30f;
                    sacc[nt][hh*2 + e2] = v;
                    rmax = fmaxf(rmax, v);
                }
            rmax = fmaxf(rmax, __shfl_xor_sync(0xffffffffu, rmax, 1));
            rmax = fmaxf(rmax, __shfl_xor_sync(0xffffffffu, rmax, 2));
            float mn = fmaxf(mrow[hh], rmax);
            corr[hh] = __expf(mrow[hh] - mn);
            float rs = 0.f;
            #pragma unroll
            for (int nt = 0; nt < 8; ++nt)
                #pragma unroll
                for (int e2 = 0; e2 < 2; ++e2) {
                    float p = __expf(sacc[nt][hh*2 + e2] - mn);
                    sacc[nt][hh*2 + e2] = p;
                    rs += p;
                }
            rs += __shfl_xor_sync(0xffffffffu, rs, 1);
            rs += __shfl_xor_sync(0xffffffffu, rs, 2);
            lrow[hh] = lrow[hh]*corr[hh] + rs;
            mrow[hh] = mn;
        }
        #pragma unroll
        for (int nt = 0; nt < 16; ++nt) {
            oacc[nt][0] *= corr[0]; oacc[nt][1] *= corr[0];
            oacc[nt][2] *= corr[1]; oacc[nt][3] *= corr[1];
        }

        // ---- O += P V  (3 passes; P packed from sacc, V via ldmatrix.trans)
        #pragma unroll
        for (int kk4 = 0; kk4 < 4; ++kk4) {
            uint32_t ph[4], pl[4];
            #pragma unroll
            for (int part = 0; part < 4; ++part) {
                int tl = 2*kk4 + (part >> 1);
                int eh = part & 1;
                split2(sacc[tl][eh*2], sacc[tl][eh*2 + 1], ph[part], pl[part]);
            }
            const int mi = lane >> 3;
            const int krow = kk4*16 + (lane & 7) + (mi & 1)*8;
            #pragma unroll
            for (int np = 0; np < 8; ++np) {
                uint32_t c = np*2 + (mi >> 1);
                uint32_t off = (uint32_t)krow*256 + (c >> 3)*128 + (((c & 7) ^ (krow & 7)) << 4);
                uint32_t t[4], t2[4];
                ldmx4t(t,  vb + off);
                ldmx4t(t2, vb + FKPL + off);
                uint32_t bvh0[2] = {t[0],  t[1]},  bvh1[2] = {t[2],  t[3]};
                uint32_t bvl0[2] = {t2[0], t2[1]}, bvl1[2] = {t2[2], t2[3]};
                mma16816(oacc[2*np],     ph, bvh0);
                mma16816(oacc[2*np],     ph, bvl0);
                mma16816(oacc[2*np],     pl, bvh0);
                mma16816(oacc[2*np + 1], ph, bvh1);
                mma16816(oacc[2*np + 1], ph, bvl1);
                mma16816(oacc[2*np + 1], pl, bvh1);
            }
        }
    }

    // ---- normalize + store fp32
    const float inv0 = 1.f / lrow[0];
    const float inv1 = 1.f / lrow[1];
    const size_t r0 = (size_t)(b*Ss + q0 + w*16 + (lane >> 2));
    #pragma unroll
    for (int nt = 0; nt < 16; ++nt) {
        const int col = h*HDd + nt*8 + (lane & 3)*2;
        *(float2*)(O + r0*Dd + col)       = make_float2(oacc[nt][0]*inv0, oacc[nt][1]*inv0);
        *(float2*)(O + (r0 + 8)*Dd + col) = make_float2(oacc[nt][2]*inv1, oacc[nt][3]*inv1);
    }
}

// ---------------------------------------------------------------------------
// T = X @ [L1a;L1b;L1c]^T   (rank-16 LoRA intermediates).  64-row tiles.
// ---------------------------------------------------------------------------
__global__ __launch_bounds__(256) void lora_t_kernel(
    const float* __restrict__ X,
    const float* __restrict__ L1a, const float* __restrict__ L1b, const float* __restrict__ L1c,
    float* __restrict__ T, int nmat, int ldt, int Ktot)
{
    __shared__ float Xs[32][68];
    __shared__ float Ls[32][52];
    const int tid = threadIdx.x;
    const int tx = tid & 15, ty = tid >> 4;
    const int m0 = blockIdx.x << 6;
    const int Rtot = nmat << 4;
    float acc[4][3];
    #pragma unroll
    for (int i = 0; i < 4; ++i)
        #pragma unroll
        for (int j = 0; j < 3; ++j) acc[i][j] = 0.f;

    for (int k0 = 0; k0 < Ktot; k0 += 32) {
        __syncthreads();
        #pragma unroll
        for (int i = 0; i < 2; ++i) {
            int v = tid + i*256;
            int r = v >> 3, c = (v & 7) << 2;
            float4 x4 = *(const float4*)(X + (size_t)(m0 + r)*Ktot + k0 + c);
            Xs[c+0][r]=x4.x; Xs[c+1][r]=x4.y; Xs[c+2][r]=x4.z; Xs[c+3][r]=x4.w;
        }
        for (int v = tid; v < Rtot*8; v += 256) {
            int r = v >> 3, c = (v & 7) << 2;
            const float* src = (r < 16) ? (L1a + (size_t)r*Ktot)
                             : (r < 32) ? (L1b + (size_t)(r-16)*Ktot)
                                        : (L1c + (size_t)(r-32)*Ktot);
            float4 l4 = *(const float4*)(src + k0 + c);
            Ls[c+0][r]=l4.x; Ls[c+1][r]=l4.y; Ls[c+2][r]=l4.z; Ls[c+3][r]=l4.w;
        }
        __syncthreads();
        #pragma unroll
        for (int k = 0; k < 32; ++k) {
            float xv[4];
            #pragma unroll
            for (int i = 0; i < 4; ++i) xv[i] = Xs[k][4*ty + i];
            for (int j = 0; j < nmat; ++j) {
                float lv = Ls[k][tx + 16*j];
                #pragma unroll
                for (int i = 0; i < 4; ++i) acc[i][j] = fmaf(xv[i], lv, acc[i][j]);
            }
        }
    }
    for (int j = 0; j < nmat; ++j)
        #pragma unroll
        for (int i = 0; i < 4; ++i)
            T[(size_t)(m0 + 4*ty + i)*ldt + tx + 16*j] = acc[i][j];
}

// ---------------------------------------------------------------------------
// Adapter K/V projection: AK = Ad(20xK) @ Wk^T, AV = Ad @ Wv^T (no LoRA).
// ---------------------------------------------------------------------------
__global__ __launch_bounds__(256) void adapter_proj_kernel(
    const float* __restrict__ Ad, const float* __restrict__ Wk, const float* __restrict__ Wv,
    float* __restrict__ AK, float* __restrict__ AV, int Ktot, int Ntot)
{
    __shared__ float Ads[20][68];
    __shared__ float Wks[64][65];
    __shared__ float Wvs[64][65];
    const int tid = threadIdx.x;
    const int nl = tid & 63, mg = tid >> 6;
    const int n0 = blockIdx.x << 6;
    float ak[5] = {0,0,0,0,0}, av[5] = {0,0,0,0,0};

    for (int k0 = 0; k0 < Ktot; k0 += 64) {
        __syncthreads();
        for (int v = tid; v < 320; v += 256) {
            int r = v >> 4, c = (v & 15) << 2;
            float4 a4 = *(const float4*)(Ad + (size_t)r*Ktot + k0 + c);
            Ads[r][c+0]=a4.x; Ads[r][c+1]=a4.y; Ads[r][c+2]=a4.z; Ads[r][c+3]=a4.w;
        }
        #pragma unroll
        for (int i = 0; i < 4; ++i) {
            int v = tid + i*256;
            int r = v >> 4, c = (v & 15) << 2;
            float4 w4 = *(const float4*)(Wk + (size_t)(n0 + r)*Ktot + k0 + c);
            Wks[c+0][r]=w4.x; Wks[c+1][r]=w4.y; Wks[c+2][r]=w4.z; Wks[c+3][r]=w4.w;
            float4 w5 = *(const float4*)(Wv + (size_t)(n0 + r)*Ktot + k0 + c);
            Wvs[c+0][r]=w5.x; Wvs[c+1][r]=w5.y; Wvs[c+2][r]=w5.z; Wvs[c+3][r]=w5.w;
        }
        __syncthreads();
        #pragma unroll
        for (int k = 0; k < 64; ++k) {
            float wkv = Wks[k][nl];
            float wvv = Wvs[k][nl];
            #pragma unroll
            for (int i = 0; i < 5; ++i) {
                float a = Ads[5*mg + i][k];
                ak[i] = fmaf(a, wkv, ak[i]);
                av[i] = fmaf(a, wvv, av[i]);
            }
        }
    }
    #pragma unroll
    for (int i = 0; i < 5; ++i) {
        AK[(size_t)(5*mg + i)*Ntot + n0 + nl] = ak[i];
        AV[(size_t)(5*mg + i)*Ntot + n0 + nl] = av[i];
    }
}

// ---------------------------------------------------------------------------
// Gated adapter cross-attention (adds in place)
// ---------------------------------------------------------------------------
__global__ __launch_bounds__(256) void adapter_attn_kernel(
    const float* __restrict__ XQ, const float* __restrict__ AK, const float* __restrict__ AV,
    const float* __restrict__ gate, const float* __restrict__ ngate, float* __restrict__ O)
{
    __shared__ float aks[ALa][HDd];
    __shared__ float avs[ALa][HDd];
    const int tid = threadIdx.x;
    const int q0 = blockIdx.x << 6;
    const int h = blockIdx.y, b = blockIdx.z;
    const size_t hoff = (size_t)h * HDd;
    const float scale = 0.08838834764831845f;

    for (int v = tid; v < ALa*32; v += 256) {
        int r = v >> 5, c = (v & 31) << 2;
        *(float4*)&aks[r][c] = *(const float4*)(AK + ((size_t)(b*ALa + r))*Dd + hoff + c);
        *(float4*)&avs[r][c] = *(const float4*)(AV + ((size_t)(b*ALa + r))*Dd + hoff + c);
    }
    __syncthreads();

    const int lane = tid & 31, wid = tid >> 5;
    const float g = tanhf(gate[h]) * ngate[0];

    for (int it = 0; it < 8; ++it) {
        const int q = q0 + it*8 + wid;
        const float* qp = XQ + ((size_t)(b*Ss + q))*Dd + hoff;
        float qv[4];
        #pragma unroll
        for (int e = 0; e < 4; ++e) qv[e] = qp[lane + 32*e];

        float p[ALa];
        float mx = -1e30f;
        #pragma unroll
        for (int j = 0; j < ALa; ++j) {
            float sc = 0.f;
            #pragma unroll
            for (int e = 0; e < 4; ++e) sc = fmaf(qv[e], aks[j][lane + 32*e], sc);
            #pragma unroll
            for (int off = 16; off > 0; off >>= 1) sc += __shfl_xor_sync(0xffffffffu, sc, off);
            sc *= scale;
            p[j] = sc;
            mx = fmaxf(mx, sc);
        }
        float sum = 0.f;
        #pragma unroll
        for (int j = 0; j < ALa; ++j) { p[j] = __expf(p[j] - mx); sum += p[j]; }
        const float wgt = g / sum;

        float* op = O + ((size_t)(b*Ss + q))*Dd + hoff;
        #pragma unroll
        for (int e = 0; e < 4; ++e) {
            float acc = 0.f;
            #pragma unroll
            for (int j = 0; j < ALa; ++j) acc = fmaf(p[j], avs[j][lane + 32*e], acc);
            op[lane + 32*e] += acc * wgt;
        }
    }
}

// ---------------------------------------------------------------------------
// Launch
// ---------------------------------------------------------------------------
extern "C" void kernel_launch(void* const* d_in, const int* in_sizes, int n_in,
                              void* d_out, int out_size)
{
    (void)in_sizes; (void)n_in; (void)out_size;
    const float* x       = (const float*)d_in[0];
    const float* adapter = (const float*)d_in[4];
    const float* wq  = (const float*)d_in[5];
    const float* wk  = (const float*)d_in[6];
    const float* wv  = (const float*)d_in[7];
    const float* wo  = (const float*)d_in[8];
    const float* lq1 = (const float*)d_in[9];
    const float* lq2 = (const float*)d_in[10];
    const float* lk1 = (const float*)d_in[11];
    const float* lk2 = (const float*)d_in[12];
    const float* lv1 = (const float*)d_in[13];
    const float* lv2 = (const float*)d_in[14];
    const float* lo1 = (const float*)d_in[15];
    const float* lo2 = (const float*)d_in[16];
    const float* gate  = (const float*)d_in[17];
    const float* ngate = (const float*)d_in[18];
    float* out = (float*)d_out;

    float *xq, *att, *dmp, *T, *To, *ak, *av;
    __nv_bfloat16 *cvAhi, *cvAlo, *cvBhi, *cvBlo, *qhi, *qlo, *khi, *klo, *vhi, *vlo;
    cudaGetSymbolAddress((void**)&xq,   g_xq);
    cudaGetSymbolAddress((void**)&att,  g_att);
    cudaGetSymbolAddress((void**)&dmp,  g_dmp);
    cudaGetSymbolAddress((void**)&T,    g_T);
    cudaGetSymbolAddress((void**)&To,   g_To);
    cudaGetSymbolAddress((void**)&ak,   g_ak);
    cudaGetSymbolAddress((void**)&av,   g_av);
    cudaGetSymbolAddress((void**)&cvAhi, g_cvAhi);
    cudaGetSymbolAddress((void**)&cvAlo, g_cvAlo);
    cudaGetSymbolAddress((void**)&cvBhi, g_cvBhi);
    cudaGetSymbolAddress((void**)&cvBlo, g_cvBlo);
    cudaGetSymbolAddress((void**)&qhi,  g_qhi);
    cudaGetSymbolAddress((void**)&qlo,  g_qlo);
    cudaGetSymbolAddress((void**)&khi,  g_khi);
    cudaGetSymbolAddress((void**)&klo,  g_klo);
    cudaGetSymbolAddress((void**)&vhi,  g_vhi);
    cudaGetSymbolAddress((void**)&vlo,  g_vlo);

    cudaFuncSetAttribute(gemm_bf,   cudaFuncAttributeMaxDynamicSharedMemorySize, GEMM_SMEM);
    cudaFuncSetAttribute(flash_mma, cudaFuncAttributeMaxDynamicSharedMemorySize, FLASH_SMEM);

    const dim3 gGrid(Dd/128, MROWS/128);          // (32, 32)
    const int convBlocks = MROWS*520/256;         // 8320 (M = N = 4096)

    // 1) LoRA intermediates (q/k/v)
    lora_t_kernel<<<MROWS/64, 256>>>(x, lq1, lk1, lv1, T, 3, 48, Dd);
    // 2) convert A = [x | T(48) | 0]
    conv_split<<<convBlocks, 256>>>(x, T, 48, 48, 0, cvAhi, cvAlo);
    // 3) QKV projections (convert W per GEMM, stream-ordered buffer reuse)
    conv_split<<<convBlocks, 256>>>(wq, lq2, 16, 16, 0, cvBhi, cvBlo);
    gemm_bf<<<gGrid, 256, GEMM_SMEM>>>(cvAhi, cvAlo, cvBhi, cvBlo, xq,  qhi, qlo);
    conv_split<<<convBlocks, 256>>>(wk, lk2, 16, 16, 16, cvBhi, cvBlo);
    gemm_bf<<<gGrid, 256, GEMM_SMEM>>>(cvAhi, cvAlo, cvBhi, cvBlo, dmp, khi, klo);
    conv_split<<<convBlocks, 256>>>(wv, lv2, 16, 16, 32, cvBhi, cvBlo);
    gemm_bf<<<gGrid, 256, GEMM_SMEM>>>(cvAhi, cvAlo, cvBhi, cvBlo, dmp, vhi, vlo);
    // 4) adapter K/V projection
    adapter_proj_kernel<<<Dd/64, 256>>>(adapter, wk, wv, ak, av, Dd, Dd);
    // 5) causal flash attention (tensor-core) -> att
    flash_mma<<<dim3(Ss/128, Hh, Bb), 256, FLASH_SMEM>>>(qhi, qlo, khi, klo, vhi, vlo, att);
    // 6) gated adapter cross-attention, added in place
    adapter_attn_kernel<<<dim3(Ss/64, Hh, Bb), 256>>>(xq, ak, av, gate, ngate, att);
    // 7) output projection
    lora_t_kernel<<<MROWS/64, 256>>>(att, lo1, lo1, lo1, To, 1, 16, Dd);
    conv_split<<<convBlocks, 256>>>(att, To, 16, 16, 0, cvAhi, cvAlo);
    conv_split<<<convBlocks, 256>>>(wo, lo2, 16, 16, 0, cvBhi, cvBlo);
    gemm_bf<<<gGrid, 256, GEMM_SMEM>>>(cvAhi, cvAlo, cvBhi, cvBlo, out, nullptr, nullptr);
}

// round 6
// speedup vs baseline: 3.9540x; 2.0450x over previous
#include <cuda_runtime.h>
#include <cuda_bf16.h>
#include <math.h>
#include <stdint.h>

// Problem constants
#define Bb   2
#define Ss   2048
#define Dd   4096
#define Hh   32
#define HDd  128
#define ALa  10
#define MROWS (Bb*Ss)          // 4096
#define KP   4160              // 4096 + 64 (LoRA chunk)
#define NCH  65                // K'/64
#define KSPL 8                 // k-split for small gemms

// ---------------------------------------------------------------------------
// Scratch (device globals; no cudaMalloc allowed)
// ---------------------------------------------------------------------------
__device__ float g_att[MROWS*Dd];
__device__ float g_T  [MROWS*48];
__device__ float g_To [MROWS*16];
__device__ float g_Tp [KSPL*MROWS*48];
__device__ float g_ak [Bb*ALa*Dd];
__device__ float g_av [Bb*ALa*Dd];
__device__ float g_akp[KSPL*Bb*ALa*Dd];
__device__ float g_avp[KSPL*Bb*ALa*Dd];
__device__ __nv_bfloat16 g_cvAhi[MROWS*KP];
__device__ __nv_bfloat16 g_cvAlo[MROWS*KP];
__device__ __nv_bfloat16 g_cvBhi[Dd*KP];
__device__ __nv_bfloat16 g_cvBlo[Dd*KP];
__device__ __nv_bfloat16 g_qhi[MROWS*Dd];
__device__ __nv_bfloat16 g_qlo[MROWS*Dd];
__device__ __nv_bfloat16 g_khi[MROWS*Dd];
__device__ __nv_bfloat16 g_klo[MROWS*Dd];
__device__ __nv_bfloat16 g_vhi[MROWS*Dd];
__device__ __nv_bfloat16 g_vlo[MROWS*Dd];

// ---------------------------------------------------------------------------
// helpers
// ---------------------------------------------------------------------------
__device__ __forceinline__ uint32_t smem_u32(const void* p) {
    uint32_t a;
    asm("{ .reg .u64 t; cvta.to.shared.u64 t, %1; cvt.u32.u64 %0, t; }" : "=r"(a) : "l"(p));
    return a;
}
__device__ __forceinline__ void cpa16(uint32_t dst, const void* src) {
    asm volatile("cp.async.cg.shared.global [%0], [%1], 16;" :: "r"(dst), "l"(src));
}
__device__ __forceinline__ void cpa_commit() { asm volatile("cp.async.commit_group;"); }
#define CPA_WAIT(N) asm volatile("cp.async.wait_group %0;" :: "n"(N))
__device__ __forceinline__ void ldmx4(uint32_t* r, uint32_t addr) {
    asm volatile("ldmatrix.sync.aligned.m8n8.x4.shared.b16 {%0,%1,%2,%3}, [%4];"
                 : "=r"(r[0]), "=r"(r[1]), "=r"(r[2]), "=r"(r[3]) : "r"(addr));
}
__device__ __forceinline__ void ldmx4t(uint32_t* r, uint32_t addr) {
    asm volatile("ldmatrix.sync.aligned.m8n8.x4.trans.shared.b16 {%0,%1,%2,%3}, [%4];"
                 : "=r"(r[0]), "=r"(r[1]), "=r"(r[2]), "=r"(r[3]) : "r"(addr));
}
__device__ __forceinline__ void mma16816(float* c, const uint32_t* a, const uint32_t* b) {
    asm volatile(
        "mma.sync.aligned.m16n8k16.row.col.f32.bf16.bf16.f32 "
        "{%0,%1,%2,%3}, {%4,%5,%6,%7}, {%8,%9}, {%0,%1,%2,%3};"
        : "+f"(c[0]), "+f"(c[1]), "+f"(c[2]), "+f"(c[3])
        : "r"(a[0]), "r"(a[1]), "r"(a[2]), "r"(a[3]), "r"(b[0]), "r"(b[1]));
}
__device__ __forceinline__ void split2(float f0, float f1, uint32_t& hi, uint32_t& lo) {
    __nv_bfloat16 h0 = __float2bfloat16_rn(f0);
    __nv_bfloat16 h1 = __float2bfloat16_rn(f1);
    __nv_bfloat16 l0 = __float2bfloat16_rn(f0 - __bfloat162float(h0));
    __nv_bfloat16 l1 = __float2bfloat16_rn(f1 - __bfloat162float(h1));
    __nv_bfloat162 ph; ph.x = h0; ph.y = h1;
    __nv_bfloat162 pl; pl.x = l0; pl.y = l1;
    hi = *(uint32_t*)&ph;
    lo = *(uint32_t*)&pl;
}

// ---------------------------------------------------------------------------
// conv_split: dst[M x KP] (hi/lo bf16) = [src(Mx4096) | lora block | zeros]
// ---------------------------------------------------------------------------
__global__ __launch_bounds__(256) void conv_split(
    const float* __restrict__ src,
    const float* __restrict__ lsrc, int ldl, int lcols, int lshift,
    __nv_bfloat16* __restrict__ dhi, __nv_bfloat16* __restrict__ dlo)
{
    const int u = blockIdx.x * 256 + threadIdx.x;
    const int r = u / 520, g = u % 520;
    float f[8];
    if (g < 512) {
        float4 a = *(const float4*)(src + (size_t)r*4096 + g*8);
        float4 b = *(const float4*)(src + (size_t)r*4096 + g*8 + 4);
        f[0]=a.x; f[1]=a.y; f[2]=a.z; f[3]=a.w; f[4]=b.x; f[5]=b.y; f[6]=b.z; f[7]=b.w;
    } else {
        #pragma unroll
        for (int i = 0; i < 8; ++i) {
            int e = g*8 - 4096 + i;
            int lc = e - lshift;
            f[i] = (lc >= 0 && lc < lcols) ? lsrc[(size_t)r*ldl + lc] : 0.f;
        }
    }
    uint32_t h[4], l[4];
    #pragma unroll
    for (int e = 0; e < 4; ++e) split2(f[2*e], f[2*e+1], h[e], l[e]);
    *(uint4*)(dhi + (size_t)r*KP + g*8) = make_uint4(h[0], h[1], h[2], h[3]);
    *(uint4*)(dlo + (size_t)r*KP + g*8) = make_uint4(l[0], l[1], l[2], l[3]);
}

// ---------------------------------------------------------------------------
// reduce8: dst[i] = sum_{s<8} src[s*len + i]
// ---------------------------------------------------------------------------
__global__ __launch_bounds__(256) void reduce8(
    float* __restrict__ dst, const float* __restrict__ src, int len)
{
    const int i = blockIdx.x*256 + threadIdx.x;
    float s = 0.f;
    #pragma unroll
    for (int k = 0; k < KSPL; ++k) s += src[(size_t)k*len + i];
    dst[i] = s;
}

// ---------------------------------------------------------------------------
// Pure-bf16 mma GEMM with cp.async 3-stage pipeline (C optional).
// ---------------------------------------------------------------------------
#define GPLANE 16384
#define GSTGB  (4*GPLANE)
#define GEMM_SMEM (3*GSTGB)   // 196608

__global__ __launch_bounds__(256, 1) void gemm_bf(
    const __nv_bfloat16* __restrict__ Ahi, const __nv_bfloat16* __restrict__ Alo,
    const __nv_bfloat16* __restrict__ Bhi, const __nv_bfloat16* __restrict__ Blo,
    float* __restrict__ C, __nv_bfloat16* __restrict__ Chi, __nv_bfloat16* __restrict__ Clo)
{
    extern __shared__ char smg[];
    const int tid = threadIdx.x;
    const int lane = tid & 31, wid = tid >> 5;
    const int wm = wid & 3, wn = wid >> 2;
    const int m0 = blockIdx.y << 7;
    const int n0 = blockIdx.x << 7;
    const uint32_t sbase = smem_u32(smg);

    float acc[2][8][4];
    #pragma unroll
    for (int mt = 0; mt < 2; ++mt)
        #pragma unroll
        for (int nt = 0; nt < 8; ++nt)
            #pragma unroll
            for (int e = 0; e < 4; ++e) acc[mt][nt][e] = 0.f;

    auto load_st = [&](int kt, int s) {
        const __nv_bfloat16* srcs[4] = {
            Ahi + (size_t)m0*KP + kt*64, Alo + (size_t)m0*KP + kt*64,
            Bhi + (size_t)n0*KP + kt*64, Blo + (size_t)n0*KP + kt*64 };
        const uint32_t base = sbase + s*GSTGB;
        #pragma unroll
        for (int p = 0; p < 4; ++p) {
            #pragma unroll
            for (int i = 0; i < 4; ++i) {
                int u = tid + i*256;
                int r = u >> 3, c = u & 7;
                cpa16(base + p*GPLANE + r*128 + (((uint32_t)c ^ (r & 7)) << 4),
                      srcs[p] + (size_t)r*KP + c*8);
            }
        }
        cpa_commit();
    };

    load_st(0, 0);
    load_st(1, 1);

    for (int kt = 0; kt < NCH; ++kt) {
        const int s = kt % 3;
        CPA_WAIT(1);
        __syncthreads();

        const uint32_t aAhi = sbase + s*GSTGB;
        const uint32_t aAlo = aAhi + GPLANE;
        const uint32_t aBhi = aAhi + 2*GPLANE;
        const uint32_t aBlo = aAhi + 3*GPLANE;
        #pragma unroll
        for (int kk = 0; kk < 4; ++kk) {
            uint32_t ah[2][4], al[2][4];
            #pragma unroll
            for (int mt = 0; mt < 2; ++mt) {
                int row = wm*32 + mt*16 + (lane & 15);
                uint32_t c = kk*2 + (lane >> 4);
                uint32_t off = (uint32_t)row*128 + ((c ^ (row & 7)) << 4);
                ldmx4(ah[mt], aAhi + off);
                ldmx4(al[mt], aAlo + off);
            }
            uint32_t bh[8][2], bl[8][2];
            #pragma unroll
            for (int np = 0; np < 4; ++np) {
                int nrow = wn*64 + np*16 + (lane >> 4)*8 + (lane & 7);
                uint32_t c = kk*2 + ((lane >> 3) & 1);
                uint32_t off = (uint32_t)nrow*128 + ((c ^ (nrow & 7)) << 4);
                uint32_t t[4];
                ldmx4(t, aBhi + off);
                bh[2*np][0]=t[0]; bh[2*np][1]=t[1]; bh[2*np+1][0]=t[2]; bh[2*np+1][1]=t[3];
                ldmx4(t, aBlo + off);
                bl[2*np][0]=t[0]; bl[2*np][1]=t[1]; bl[2*np+1][0]=t[2]; bl[2*np+1][1]=t[3];
            }
            #pragma unroll
            for (int mt = 0; mt < 2; ++mt)
                #pragma unroll
                for (int nt = 0; nt < 8; ++nt) {
                    mma16816(acc[mt][nt], ah[mt], bh[nt]);
                    mma16816(acc[mt][nt], ah[mt], bl[nt]);
                    mma16816(acc[mt][nt], al[mt], bh[nt]);
                }
        }
        if (kt + 2 < NCH) load_st(kt + 2, (kt + 2) % 3);
    }

    #pragma unroll
    for (int mt = 0; mt < 2; ++mt) {
        const int row = m0 + wm*32 + mt*16 + (lane >> 2);
        #pragma unroll
        for (int nt = 0; nt < 8; ++nt) {
            const int col = n0 + wn*64 + nt*8 + (lane & 3)*2;
            if (C) {
                *(float2*)(C + (size_t)row*Dd + col)       = make_float2(acc[mt][nt][0], acc[mt][nt][1]);
                *(float2*)(C + (size_t)(row + 8)*Dd + col) = make_float2(acc[mt][nt][2], acc[mt][nt][3]);
            }
            if (Chi) {
                uint32_t h, l;
                split2(acc[mt][nt][0], acc[mt][nt][1], h, l);
                *(uint32_t*)(Chi + (size_t)row*Dd + col) = h;
                *(uint32_t*)(Clo + (size_t)row*Dd + col) = l;
                split2(acc[mt][nt][2], acc[mt][nt][3], h, l);
                *(uint32_t*)(Chi + (size_t)(row + 8)*Dd + col) = h;
                *(uint32_t*)(Clo + (size_t)(row + 8)*Dd + col) = l;
            }
        }
    }
}

// ---------------------------------------------------------------------------
// Flash attention v2: Q frags hoisted, 3-stage KV ring, warp-level tile skip.
// CTA: 128 q x 64 kv. 8 warps, warp = 16 q rows x 128 hd.
// smem: Q hi/lo (64KB, becomes stage 2 after hoist) + 2 KV stages (128KB).
// ---------------------------------------------------------------------------
#define FQPL 32768
#define FKPL 16384
#define FKVSTG (4*FKPL)
#define FLASH_SMEM (2*FQPL + 2*FKVSTG)   // 196608

__global__ __launch_bounds__(256, 1) void flash_mma(
    const __nv_bfloat16* __restrict__ Qhi, const __nv_bfloat16* __restrict__ Qlo,
    const __nv_bfloat16* __restrict__ Khi, const __nv_bfloat16* __restrict__ Klo,
    const __nv_bfloat16* __restrict__ Vhi, const __nv_bfloat16* __restrict__ Vlo,
    float* __restrict__ O)
{
    extern __shared__ char smf[];
    const int tid = threadIdx.x;
    const int lane = tid & 31, w = tid >> 5;
    const int qt = blockIdx.x, h = blockIdx.y, b = blockIdx.z;
    const int q0 = qt << 7;
    const uint32_t sbase = smem_u32(smf);
    const float scale = 0.08838834764831845f;

    // Q load (group 0)
    {
        const __nv_bfloat16* srcs[2] = {
            Qhi + (size_t)(b*Ss + q0)*Dd + h*HDd,
            Qlo + (size_t)(b*Ss + q0)*Dd + h*HDd };
        #pragma unroll
        for (int p = 0; p < 2; ++p)
            #pragma unroll
            for (int i = 0; i < 8; ++i) {
                int u = tid + i*256;
                int r = u >> 4, c = u & 15;
                uint32_t dst = sbase + p*FQPL + (uint32_t)r*256 + (c >> 3)*128
                             + ((((uint32_t)c & 7) ^ (r & 7)) << 4);
                cpa16(dst, srcs[p] + (size_t)r*Dd + c*8);
            }
        cpa_commit();
    }
    // KV stage base: stages 0,1 in dedicated region, stage 2 reuses Q region
    auto stg = [&](int s) -> uint32_t {
        return (s == 2) ? sbase : (sbase + 2*FQPL + s*FKVSTG);
    };
    auto loadKV = [&](int kt, int s) {
        const int k0 = kt << 6;
        const __nv_bfloat16* srcs[4] = {
            Khi + (size_t)(b*Ss + k0)*Dd + h*HDd, Klo + (size_t)(b*Ss + k0)*Dd + h*HDd,
            Vhi + (size_t)(b*Ss + k0)*Dd + h*HDd, Vlo + (size_t)(b*Ss + k0)*Dd + h*HDd };
        const uint32_t base = stg(s);
        #pragma unroll
        for (int p = 0; p < 4; ++p)
            #pragma unroll
            for (int i = 0; i < 4; ++i) {
                int u = tid + i*256;
                int r = u >> 4, c = u & 15;
                uint32_t dst = base + p*FKPL + (uint32_t)r*256 + (c >> 3)*128
                             + ((((uint32_t)c & 7) ^ (r & 7)) << 4);
                cpa16(dst, srcs[p] + (size_t)r*Dd + c*8);
            }
        cpa_commit();
    };
    loadKV(0, 0);
    CPA_WAIT(1);        // Q group done (KV0 may fly)
    __syncthreads();

    // hoist Q fragments (then Q smem becomes KV stage 2)
    uint32_t qh[8][4], ql[8][4];
    #pragma unroll
    for (int kk = 0; kk < 8; ++kk) {
        int row = w*16 + (lane & 15);
        uint32_t c = kk*2 + (lane >> 4);
        uint32_t off = (uint32_t)row*256 + (c >> 3)*128 + (((c & 7) ^ (row & 7)) << 4);
        ldmx4(qh[kk], sbase + off);
        ldmx4(ql[kk], sbase + FQPL + off);
    }
    loadKV(1, 1);

    float oacc[16][4];
    #pragma unroll
    for (int nt = 0; nt < 16; ++nt)
        #pragma unroll
        for (int e = 0; e < 4; ++e) oacc[nt][e] = 0.f;
    float mrow[2] = {-1e30f, -1e30f};
    float lrow[2] = {0.f, 0.f};

    const int nkt = 2*(qt + 1);
    for (int kt = 0; kt < nkt; ++kt) {
        if (kt + 1 < nkt) { CPA_WAIT(1); } else { CPA_WAIT(0); }
        __syncthreads();
        if (kt + 2 < nkt) loadKV(kt + 2, (kt + 2) % 3);

        const int k0 = kt << 6;
        const bool active = (k0 <= q0 + w*16 + 15);  // warp has >=1 unmasked row
        if (active) {
        const uint32_t kb = stg(kt % 3);
        const uint32_t vb = kb + 2*FKPL;

        // ---- S = Q K^T
        float sacc[8][4];
        #pragma unroll
        for (int nt = 0; nt < 8; ++nt)
            #pragma unroll
            for (int e = 0; e < 4; ++e) sacc[nt][e] = 0.f;
        #pragma unroll
        for (int kk = 0; kk < 8; ++kk) {
            #pragma unroll
            for (int np = 0; np < 4; ++np) {
                int nrow = np*16 + (lane >> 4)*8 + (lane & 7);
                uint32_t c = kk*2 + ((lane >> 3) & 1);
                uint32_t off = (uint32_t)nrow*256 + (c >> 3)*128 + (((c & 7) ^ (nrow & 7)) << 4);
                uint32_t tb[4], tl[4];
                ldmx4(tb, kb + off);
                ldmx4(tl, kb + FKPL + off);
                uint32_t b0[2] = {tb[0], tb[1]}, b1[2] = {tb[2], tb[3]};
                uint32_t l0[2] = {tl[0], tl[1]}, l1[2] = {tl[2], tl[3]};
                mma16816(sacc[2*np],     qh[kk], b0);
                mma16816(sacc[2*np],     qh[kk], l0);
                mma16816(sacc[2*np],     ql[kk], b0);
                mma16816(sacc[2*np + 1], qh[kk], b1);
                mma16816(sacc[2*np + 1], qh[kk], l1);
                mma16816(sacc[2*np + 1], ql[kk], b1);
            }
        }

        // ---- mask + online softmax
        const bool needmask = (k0 + 63 > q0 + w*16);
        float corr[2];
        #pragma unroll
        for (int hh = 0; hh < 2; ++hh) {
            const int rowg = q0 + w*16 + (lane >> 2) + hh*8;
            float rmax = -1e30f;
            #pragma unroll
            for (int nt = 0; nt < 8; ++nt)
                #pragma unroll
                for (int e2 = 0; e2 < 2; ++e2) {
                    float v = sacc[nt][hh*2 + e2] * scale;
                    if (needmask) {
                        int colg = k0 + nt*8 + (lane & 3)*2 + e2;
                        if (colg > rowg) v = -1e30f;
                    }
                    sacc[nt][hh*2 + e2] = v;
                    rmax = fmaxf(rmax, v);
                }
            rmax = fmaxf(rmax, __shfl_xor_sync(0xffffffffu, rmax, 1));
            rmax = fmaxf(rmax, __shfl_xor_sync(0xffffffffu, rmax, 2));
            float mn = fmaxf(mrow[hh], rmax);
            corr[hh] = __expf(mrow[hh] - mn);
            float rs = 0.f;
            #pragma unroll
            for (int nt = 0; nt < 8; ++nt)
                #pragma unroll
                for (int e2 = 0; e2 < 2; ++e2) {
                    float p = __expf(sacc[nt][hh*2 + e2] - mn);
                    sacc[nt][hh*2 + e2] = p;
                    rs += p;
                }
            rs += __shfl_xor_sync(0xffffffffu, rs, 1);
            rs += __shfl_xor_sync(0xffffffffu, rs, 2);
            lrow[hh] = lrow[hh]*corr[hh] + rs;
            mrow[hh] = mn;
        }
        #pragma unroll
        for (int nt = 0; nt < 16; ++nt) {
            oacc[nt][0] *= corr[0]; oacc[nt][1] *= corr[0];
            oacc[nt][2] *= corr[1]; oacc[nt][3] *= corr[1];
        }

        // ---- O += P V
        #pragma unroll
        for (int kk4 = 0; kk4 < 4; ++kk4) {
            uint32_t ph[4], pl[4];
            #pragma unroll
            for (int part = 0; part < 4; ++part) {
                int tl2 = 2*kk4 + (part >> 1);
                int eh = part & 1;
                split2(sacc[tl2][eh*2], sacc[tl2][eh*2 + 1], ph[part], pl[part]);
            }
            const int mi = lane >> 3;
            const int krow = kk4*16 + (lane & 7) + (mi & 1)*8;
            #pragma unroll
            for (int np = 0; np < 8; ++np) {
                uint32_t c = np*2 + (mi >> 1);
                uint32_t off = (uint32_t)krow*256 + (c >> 3)*128 + (((c & 7) ^ (krow & 7)) << 4);
                uint32_t t[4], t2[4];
                ldmx4t(t,  vb + off);
                ldmx4t(t2, vb + FKPL + off);
                uint32_t bvh0[2] = {t[0],  t[1]},  bvh1[2] = {t[2],  t[3]};
                uint32_t bvl0[2] = {t2[0], t2[1]}, bvl1[2] = {t2[2], t2[3]};
                mma16816(oacc[2*np],     ph, bvh0);
                mma16816(oacc[2*np],     ph, bvl0);
                mma16816(oacc[2*np],     pl, bvh0);
                mma16816(oacc[2*np + 1], ph, bvh1);
                mma16816(oacc[2*np + 1], ph, bvl1);
                mma16816(oacc[2*np + 1], pl, bvh1);
            }
        }
        } // active
    }

    const float inv0 = 1.f / lrow[0];
    const float inv1 = 1.f / lrow[1];
    const size_t r0 = (size_t)(b*Ss + q0 + w*16 + (lane >> 2));
    #pragma unroll
    for (int nt = 0; nt < 16; ++nt) {
        const int col = h*HDd + nt*8 + (lane & 3)*2;
        *(float2*)(O + r0*Dd + col)       = make_float2(oacc[nt][0]*inv0, oacc[nt][1]*inv0);
        *(float2*)(O + (r0 + 8)*Dd + col) = make_float2(oacc[nt][2]*inv1, oacc[nt][3]*inv1);
    }
}

// ---------------------------------------------------------------------------
// lora_part: partial T over k-range [ks*512, +512).  grid (M/64, KSPL)
// ---------------------------------------------------------------------------
__global__ __launch_bounds__(256) void lora_part(
    const float* __restrict__ X,
    const float* __restrict__ L1a, const float* __restrict__ L1b, const float* __restrict__ L1c,
    float* __restrict__ Tp, int nmat, int ldt)
{
    __shared__ float Xs[32][68];
    __shared__ float Ls[32][52];
    const int tid = threadIdx.x;
    const int tx = tid & 15, ty = tid >> 4;
    const int m0 = blockIdx.x << 6;
    const int ks = blockIdx.y;
    const int kbeg = ks*512, kend = kbeg + 512;
    const int Rtot = nmat << 4;
    float acc[4][3];
    #pragma unroll
    for (int i = 0; i < 4; ++i)
        #pragma unroll
        for (int j = 0; j < 3; ++j) acc[i][j] = 0.f;

    for (int k0 = kbeg; k0 < kend; k0 += 32) {
        __syncthreads();
        #pragma unroll
        for (int i = 0; i < 2; ++i) {
            int v = tid + i*256;
            int r = v >> 3, c = (v & 7) << 2;
            float4 x4 = *(const float4*)(X + (size_t)(m0 + r)*Dd + k0 + c);
            Xs[c+0][r]=x4.x; Xs[c+1][r]=x4.y; Xs[c+2][r]=x4.z; Xs[c+3][r]=x4.w;
        }
        for (int v = tid; v < Rtot*8; v += 256) {
            int r = v >> 3, c = (v & 7) << 2;
            const float* src = (r < 16) ? (L1a + (size_t)r*Dd)
                             : (r < 32) ? (L1b + (size_t)(r-16)*Dd)
                                        : (L1c + (size_t)(r-32)*Dd);
            float4 l4 = *(const float4*)(src + k0 + c);
            Ls[c+0][r]=l4.x; Ls[c+1][r]=l4.y; Ls[c+2][r]=l4.z; Ls[c+3][r]=l4.w;
        }
        __syncthreads();
        #pragma unroll
        for (int k = 0; k < 32; ++k) {
            float xv[4];
            #pragma unroll
            for (int i = 0; i < 4; ++i) xv[i] = Xs[k][4*ty + i];
            for (int j = 0; j < nmat; ++j) {
                float lv = Ls[k][tx + 16*j];
                #pragma unroll
                for (int i = 0; i < 4; ++i) acc[i][j] = fmaf(xv[i], lv, acc[i][j]);
            }
        }
    }
    float* out = Tp + (size_t)ks*MROWS*ldt;
    for (int j = 0; j < nmat; ++j)
        #pragma unroll
        for (int i = 0; i < 4; ++i)
            out[(size_t)(m0 + 4*ty + i)*ldt + tx + 16*j] = acc[i][j];
}

// ---------------------------------------------------------------------------
// adapter_part: partial AK/AV over k-range. grid (Dd/64, KSPL)
// ---------------------------------------------------------------------------
__global__ __launch_bounds__(256) void adapter_part(
    const float* __restrict__ Ad, const float* __restrict__ Wk, const float* __restrict__ Wv,
    float* __restrict__ AKp, float* __restrict__ AVp)
{
    __shared__ float Ads[20][68];
    __shared__ float Wks[64][65];
    __shared__ float Wvs[64][65];
    const int tid = threadIdx.x;
    const int nl = tid & 63, mg = tid >> 6;
    const int n0 = blockIdx.x << 6;
    const int ks = blockIdx.y;
    float ak[5] = {0,0,0,0,0}, av[5] = {0,0,0,0,0};

    for (int k0 = ks*512; k0 < ks*512 + 512; k0 += 64) {
        __syncthreads();
        for (int v = tid; v < 320; v += 256) {
            int r = v >> 4, c = (v & 15) << 2;
            float4 a4 = *(const float4*)(Ad + (size_t)r*Dd + k0 + c);
            Ads[r][c+0]=a4.x; Ads[r][c+1]=a4.y; Ads[r][c+2]=a4.z; Ads[r][c+3]=a4.w;
        }
        #pragma unroll
        for (int i = 0; i < 4; ++i) {
            int v = tid + i*256;
            int r = v >> 4, c = (v & 15) << 2;
            float4 w4 = *(const float4*)(Wk + (size_t)(n0 + r)*Dd + k0 + c);
            Wks[c+0][r]=w4.x; Wks[c+1][r]=w4.y; Wks[c+2][r]=w4.z; Wks[c+3][r]=w4.w;
            float4 w5 = *(const float4*)(Wv + (size_t)(n0 + r)*Dd + k0 + c);
            Wvs[c+0][r]=w5.x; Wvs[c+1][r]=w5.y; Wvs[c+2][r]=w5.z; Wvs[c+3][r]=w5.w;
        }
        __syncthreads();
        #pragma unroll
        for (int k = 0; k < 64; ++k) {
            float wkv = Wks[k][nl];
            float wvv = Wvs[k][nl];
            #pragma unroll
            for (int i = 0; i < 5; ++i) {
                float a = Ads[5*mg + i][k];
                ak[i] = fmaf(a, wkv, ak[i]);
                av[i] = fmaf(a, wvv, av[i]);
            }
        }
    }
    float* akp = AKp + (size_t)ks*20*Dd;
    float* avp = AVp + (size_t)ks*20*Dd;
    #pragma unroll
    for (int i = 0; i < 5; ++i) {
        akp[(size_t)(5*mg + i)*Dd + n0 + nl] = ak[i];
        avp[(size_t)(5*mg + i)*Dd + n0 + nl] = av[i];
    }
}

// ---------------------------------------------------------------------------
// Gated adapter cross-attention (adds in place); q from bf16 hi/lo planes.
// ---------------------------------------------------------------------------
__global__ __launch_bounds__(256) void adapter_attn_kernel(
    const __nv_bfloat16* __restrict__ Qhi, const __nv_bfloat16* __restrict__ Qlo,
    const float* __restrict__ AK, const float* __restrict__ AV,
    const float* __restrict__ gate, const float* __restrict__ ngate, float* __restrict__ O)
{
    __shared__ float aks[ALa][HDd];
    __shared__ float avs[ALa][HDd];
    const int tid = threadIdx.x;
    const int q0 = blockIdx.x << 6;
    const int h = blockIdx.y, b = blockIdx.z;
    const size_t hoff = (size_t)h * HDd;
    const float scale = 0.08838834764831845f;

    for (int v = tid; v < ALa*32; v += 256) {
        int r = v >> 5, c = (v & 31) << 2;
        *(float4*)&aks[r][c] = *(const float4*)(AK + ((size_t)(b*ALa + r))*Dd + hoff + c);
        *(float4*)&avs[r][c] = *(const float4*)(AV + ((size_t)(b*ALa + r))*Dd + hoff + c);
    }
    __syncthreads();

    const int lane = tid & 31, wid = tid >> 5;
    const float g = tanhf(gate[h]) * ngate[0];

    for (int it = 0; it < 8; ++it) {
        const int q = q0 + it*8 + wid;
        const __nv_bfloat16* qph = Qhi + ((size_t)(b*Ss + q))*Dd + hoff;
        const __nv_bfloat16* qpl = Qlo + ((size_t)(b*Ss + q))*Dd + hoff;
        float qv[4];
        #pragma unroll
        for (int e = 0; e < 4; ++e)
            qv[e] = __bfloat162float(qph[lane + 32*e]) + __bfloat162float(qpl[lane + 32*e]);

        float p[ALa];
        float mx = -1e30f;
        #pragma unroll
        for (int j = 0; j < ALa; ++j) {
            float sc = 0.f;
            #pragma unroll
            for (int e = 0; e < 4; ++e) sc = fmaf(qv[e], aks[j][lane + 32*e], sc);
            #pragma unroll
            for (int off = 16; off > 0; off >>= 1) sc += __shfl_xor_sync(0xffffffffu, sc, off);
            sc *= scale;
            p[j] = sc;
            mx = fmaxf(mx, sc);
        }
        float sum = 0.f;
        #pragma unroll
        for (int j = 0; j < ALa; ++j) { p[j] = __expf(p[j] - mx); sum += p[j]; }
        const float wgt = g / sum;

        float* op = O + ((size_t)(b*Ss + q))*Dd + hoff;
        #pragma unroll
        for (int e = 0; e < 4; ++e) {
            float acc = 0.f;
            #pragma unroll
            for (int j = 0; j < ALa; ++j) acc = fmaf(p[j], avs[j][lane + 32*e], acc);
            op[lane + 32*e] += acc * wgt;
        }
    }
}

// ---------------------------------------------------------------------------
// Launch
// ---------------------------------------------------------------------------
extern "C" void kernel_launch(void* const* d_in, const int* in_sizes, int n_in,
                              void* d_out, int out_size)
{
    (void)in_sizes; (void)n_in; (void)out_size;
    const float* x       = (const float*)d_in[0];
    const float* adapter = (const float*)d_in[4];
    const float* wq  = (const float*)d_in[5];
    const float* wk  = (const float*)d_in[6];
    const float* wv  = (const float*)d_in[7];
    const float* wo  = (const float*)d_in[8];
    const float* lq1 = (const float*)d_in[9];
    const float* lq2 = (const float*)d_in[10];
    const float* lk1 = (const float*)d_in[11];
    const float* lk2 = (const float*)d_in[12];
    const float* lv1 = (const float*)d_in[13];
    const float* lv2 = (const float*)d_in[14];
    const float* lo1 = (const float*)d_in[15];
    const float* lo2 = (const float*)d_in[16];
    const float* gate  = (const float*)d_in[17];
    const float* ngate = (const float*)d_in[18];
    float* out = (float*)d_out;

    float *att, *T, *To, *Tp, *ak, *av, *akp, *avp;
    __nv_bfloat16 *cvAhi, *cvAlo, *cvBhi, *cvBlo, *qhi, *qlo, *khi, *klo, *vhi, *vlo;
    cudaGetSymbolAddress((void**)&att,  g_att);
    cudaGetSymbolAddress((void**)&T,    g_T);
    cudaGetSymbolAddress((void**)&To,   g_To);
    cudaGetSymbolAddress((void**)&Tp,   g_Tp);
    cudaGetSymbolAddress((void**)&ak,   g_ak);
    cudaGetSymbolAddress((void**)&av,   g_av);
    cudaGetSymbolAddress((void**)&akp,  g_akp);
    cudaGetSymbolAddress((void**)&avp,  g_avp);
    cudaGetSymbolAddress((void**)&cvAhi, g_cvAhi);
    cudaGetSymbolAddress((void**)&cvAlo, g_cvAlo);
    cudaGetSymbolAddress((void**)&cvBhi, g_cvBhi);
    cudaGetSymbolAddress((void**)&cvBlo, g_cvBlo);
    cudaGetSymbolAddress((void**)&qhi,  g_qhi);
    cudaGetSymbolAddress((void**)&qlo,  g_qlo);
    cudaGetSymbolAddress((void**)&khi,  g_khi);
    cudaGetSymbolAddress((void**)&klo,  g_klo);
    cudaGetSymbolAddress((void**)&vhi,  g_vhi);
    cudaGetSymbolAddress((void**)&vlo,  g_vlo);

    cudaFuncSetAttribute(gemm_bf,   cudaFuncAttributeMaxDynamicSharedMemorySize, GEMM_SMEM);
    cudaFuncSetAttribute(flash_mma, cudaFuncAttributeMaxDynamicSharedMemorySize, FLASH_SMEM);

    const dim3 gGrid(Dd/128, MROWS/128);
    const int convBlocks = MROWS*520/256;

    // 1) LoRA intermediates (q/k/v), k-split
    lora_part<<<dim3(MROWS/64, KSPL), 256>>>(x, lq1, lk1, lv1, Tp, 3, 48);
    reduce8<<<MROWS*48/256, 256>>>(T, Tp, MROWS*48);
    // 2) convert A = [x | T(48) | 0]
    conv_split<<<convBlocks, 256>>>(x, T, 48, 48, 0, cvAhi, cvAlo);
    // 3) QKV projections -> bf16 hi/lo planes only
    conv_split<<<convBlocks, 256>>>(wq, lq2, 16, 16, 0, cvBhi, cvBlo);
    gemm_bf<<<gGrid, 256, GEMM_SMEM>>>(cvAhi, cvAlo, cvBhi, cvBlo, nullptr, qhi, qlo);
    conv_split<<<convBlocks, 256>>>(wk, lk2, 16, 16, 16, cvBhi, cvBlo);
    gemm_bf<<<gGrid, 256, GEMM_SMEM>>>(cvAhi, cvAlo, cvBhi, cvBlo, nullptr, khi, klo);
    conv_split<<<convBlocks, 256>>>(wv, lv2, 16, 16, 32, cvBhi, cvBlo);
    gemm_bf<<<gGrid, 256, GEMM_SMEM>>>(cvAhi, cvAlo, cvBhi, cvBlo, nullptr, vhi, vlo);
    // 4) adapter K/V projection, k-split
    adapter_part<<<dim3(Dd/64, KSPL), 256>>>(adapter, wk, wv, akp, avp);
    reduce8<<<20*Dd/256, 256>>>(ak, akp, 20*Dd);
    reduce8<<<20*Dd/256, 256>>>(av, avp, 20*Dd);
    // 5) flash attention -> att
    flash_mma<<<dim3(Ss/128, Hh, Bb), 256, FLASH_SMEM>>>(qhi, qlo, khi, klo, vhi, vlo, att);
    // 6) adapter cross-attention (in place)
    adapter_attn_kernel<<<dim3(Ss/64, Hh, Bb), 256>>>(qhi, qlo, ak, av, gate, ngate, att);
    // 7) output projection
    lora_part<<<dim3(MROWS/64, KSPL), 256>>>(att, lo1, lo1, lo1, Tp, 1, 16);
    reduce8<<<MROWS*16/256, 256>>>(To, Tp, MROWS*16);
    conv_split<<<convBlocks, 256>>>(att, To, 16, 16, 0, cvAhi, cvAlo);
    conv_split<<<convBlocks, 256>>>(wo, lo2, 16, 16, 0, cvBhi, cvBlo);
    gemm_bf<<<gGrid, 256, GEMM_SMEM>>>(cvAhi, cvAlo, cvBhi, cvBlo, out, nullptr, nullptr);
}

// round 8
// speedup vs baseline: 4.0492x; 1.0241x over previous
#include <cuda_runtime.h>
#include <cuda_bf16.h>
#include <math.h>
#include <stdint.h>

// Problem constants
#define Bb   2
#define Ss   2048
#define Dd   4096
#define Hh   32
#define HDd  128
#define ALa  10
#define MROWS (Bb*Ss)          // 4096
#define KP   4160              // 4096 + 64 (LoRA chunk)
#define NCH  65                // K'/64
#define KSPL 8                 // k-split for small gemms

// ---------------------------------------------------------------------------
// Scratch (device globals; no cudaMalloc allowed)
// ---------------------------------------------------------------------------
__device__ float g_T  [MROWS*48];
__device__ float g_Tp [KSPL*MROWS*48];
__device__ float g_ak [Bb*ALa*Dd];
__device__ float g_av [Bb*ALa*Dd];
__device__ float g_akp[KSPL*Bb*ALa*Dd];
__device__ float g_avp[KSPL*Bb*ALa*Dd];
__device__ __nv_bfloat16 g_cvAhi[MROWS*KP];
__device__ __nv_bfloat16 g_cvAlo[MROWS*KP];
__device__ __nv_bfloat16 g_cvBhi[Dd*KP];
__device__ __nv_bfloat16 g_cvBlo[Dd*KP];
__device__ __nv_bfloat16 g_qhi[MROWS*Dd];
__device__ __nv_bfloat16 g_qlo[MROWS*Dd];
__device__ __nv_bfloat16 g_khi[MROWS*Dd];
__device__ __nv_bfloat16 g_klo[MROWS*Dd];
__device__ __nv_bfloat16 g_vhi[MROWS*Dd];
__device__ __nv_bfloat16 g_vlo[MROWS*Dd];

// ---------------------------------------------------------------------------
// helpers
// ---------------------------------------------------------------------------
__device__ __forceinline__ uint32_t smem_u32(const void* p) {
    uint32_t a;
    asm("{ .reg .u64 t; cvta.to.shared.u64 t, %1; cvt.u32.u64 %0, t; }" : "=r"(a) : "l"(p));
    return a;
}
__device__ __forceinline__ void cpa16(uint32_t dst, const void* src) {
    asm volatile("cp.async.cg.shared.global [%0], [%1], 16;" :: "r"(dst), "l"(src));
}
__device__ __forceinline__ void cpa_commit() { asm volatile("cp.async.commit_group;"); }
#define CPA_WAIT(N) asm volatile("cp.async.wait_group %0;" :: "n"(N))
__device__ __forceinline__ void ldmx4(uint32_t* r, uint32_t addr) {
    asm volatile("ldmatrix.sync.aligned.m8n8.x4.shared.b16 {%0,%1,%2,%3}, [%4];"
                 : "=r"(r[0]), "=r"(r[1]), "=r"(r[2]), "=r"(r[3]) : "r"(addr));
}
__device__ __forceinline__ void ldmx4t(uint32_t* r, uint32_t addr) {
    asm volatile("ldmatrix.sync.aligned.m8n8.x4.trans.shared.b16 {%0,%1,%2,%3}, [%4];"
                 : "=r"(r[0]), "=r"(r[1]), "=r"(r[2]), "=r"(r[3]) : "r"(addr));
}
__device__ __forceinline__ void mma16816(float* c, const uint32_t* a, const uint32_t* b) {
    asm volatile(
        "mma.sync.aligned.m16n8k16.row.col.f32.bf16.bf16.f32 "
        "{%0,%1,%2,%3}, {%4,%5,%6,%7}, {%8,%9}, {%0,%1,%2,%3};"
        : "+f"(c[0]), "+f"(c[1]), "+f"(c[2]), "+f"(c[3])
        : "r"(a[0]), "r"(a[1]), "r"(a[2]), "r"(a[3]), "r"(b[0]), "r"(b[1]));
}
__device__ __forceinline__ void split2(float f0, float f1, uint32_t& hi, uint32_t& lo) {
    __nv_bfloat16 h0 = __float2bfloat16_rn(f0);
    __nv_bfloat16 h1 = __float2bfloat16_rn(f1);
    __nv_bfloat16 l0 = __float2bfloat16_rn(f0 - __bfloat162float(h0));
    __nv_bfloat16 l1 = __float2bfloat16_rn(f1 - __bfloat162float(h1));
    __nv_bfloat162 ph; ph.x = h0; ph.y = h1;
    __nv_bfloat162 pl; pl.x = l0; pl.y = l1;
    hi = *(uint32_t*)&ph;
    lo = *(uint32_t*)&pl;
}

// ---------------------------------------------------------------------------
// conv_split: dst[M x KP] (hi/lo bf16) = [src(Mx4096) | lora block | zeros]
// ---------------------------------------------------------------------------
__global__ __launch_bounds__(256) void conv_split(
    const float* __restrict__ src,
    const float* __restrict__ lsrc, int ldl, int lcols, int lshift,
    __nv_bfloat16* __restrict__ dhi, __nv_bfloat16* __restrict__ dlo)
{
    const int u = blockIdx.x * 256 + threadIdx.x;
    const int r = u / 520, g = u % 520;
    float f[8];
    if (g < 512) {
        float4 a = *(const float4*)(src + (size_t)r*4096 + g*8);
        float4 b = *(const float4*)(src + (size_t)r*4096 + g*8 + 4);
        f[0]=a.x; f[1]=a.y; f[2]=a.z; f[3]=a.w; f[4]=b.x; f[5]=b.y; f[6]=b.z; f[7]=b.w;
    } else {
        #pragma unroll
        for (int i = 0; i < 8; ++i) {
            int e = g*8 - 4096 + i;
            int lc = e - lshift;
            f[i] = (lc >= 0 && lc < lcols) ? lsrc[(size_t)r*ldl + lc] : 0.f;
        }
    }
    uint32_t h[4], l[4];
    #pragma unroll
    for (int e = 0; e < 4; ++e) split2(f[2*e], f[2*e+1], h[e], l[e]);
    *(uint4*)(dhi + (size_t)r*KP + g*8) = make_uint4(h[0], h[1], h[2], h[3]);
    *(uint4*)(dlo + (size_t)r*KP + g*8) = make_uint4(l[0], l[1], l[2], l[3]);
}

// ---------------------------------------------------------------------------
// reduce8: dst[i] = sum_{s<8} src[s*len + i]
// ---------------------------------------------------------------------------
__global__ __launch_bounds__(256) void reduce8(
    float* __restrict__ dst, const float* __restrict__ src, int len)
{
    const int i = blockIdx.x*256 + threadIdx.x;
    float s = 0.f;
    #pragma unroll
    for (int k = 0; k < KSPL; ++k) s += src[(size_t)k*len + i];
    dst[i] = s;
}

// ---------------------------------------------------------------------------
// reduce_fill: To = sum8 Tp; write split into cvA cols [4096, 4160)
// ---------------------------------------------------------------------------
__global__ __launch_bounds__(256) void reduce_fill(
    const float* __restrict__ Tp,
    __nv_bfloat16* __restrict__ dhi, __nv_bfloat16* __restrict__ dlo)
{
    const int u = blockIdx.x*256 + threadIdx.x;
    const int r = u >> 6, c = u & 63;
    float s = 0.f;
    if (c < 16) {
        #pragma unroll
        for (int k = 0; k < KSPL; ++k) s += Tp[(size_t)k*MROWS*16 + r*16 + c];
    }
    __nv_bfloat16 h = __float2bfloat16_rn(s);
    __nv_bfloat16 l = __float2bfloat16_rn(s - __bfloat162float(h));
    dhi[(size_t)r*KP + 4096 + c] = h;
    dlo[(size_t)r*KP + 4096 + c] = l;
}

// ---------------------------------------------------------------------------
// Pure-bf16 mma GEMM, 512 threads (16 warps, 32x32 warp tiles), cp.async
// 3-stage pipeline. C (fp32) optional; hi/lo output planes optional.
// ---------------------------------------------------------------------------
#define GPLANE 16384
#define GSTGB  (4*GPLANE)
#define GEMM_SMEM (3*GSTGB)   // 196608

__global__ __launch_bounds__(512, 1) void gemm_bf(
    const __nv_bfloat16* __restrict__ Ahi, const __nv_bfloat16* __restrict__ Alo,
    const __nv_bfloat16* __restrict__ Bhi, const __nv_bfloat16* __restrict__ Blo,
    float* __restrict__ C, __nv_bfloat16* __restrict__ Chi, __nv_bfloat16* __restrict__ Clo)
{
    extern __shared__ char smg[];
    const int tid = threadIdx.x;
    const int lane = tid & 31, wid = tid >> 5;
    const int wm = wid & 3, wn = wid >> 2;    // 4 x 4 warp grid, 32x32 tiles
    const int m0 = blockIdx.y << 7;
    const int n0 = blockIdx.x << 7;
    const uint32_t sbase = smem_u32(smg);

    float acc[2][4][4];
    #pragma unroll
    for (int mt = 0; mt < 2; ++mt)
        #pragma unroll
        for (int nt = 0; nt < 4; ++nt)
            #pragma unroll
            for (int e = 0; e < 4; ++e) acc[mt][nt][e] = 0.f;

    auto load_st = [&](int kt, int s) {
        const __nv_bfloat16* srcs[4] = {
            Ahi + (size_t)m0*KP + kt*64, Alo + (size_t)m0*KP + kt*64,
            Bhi + (size_t)n0*KP + kt*64, Blo + (size_t)n0*KP + kt*64 };
        const uint32_t base = sbase + s*GSTGB;
        #pragma unroll
        for (int p = 0; p < 4; ++p) {
            #pragma unroll
            for (int i = 0; i < 2; ++i) {
                int u = tid + i*512;
                int r = u >> 3, c = u & 7;
                cpa16(base + p*GPLANE + r*128 + (((uint32_t)c ^ (r & 7)) << 4),
                      srcs[p] + (size_t)r*KP + c*8);
            }
        }
        cpa_commit();
    };

    load_st(0, 0);
    load_st(1, 1);

    for (int kt = 0; kt < NCH; ++kt) {
        const int s = kt % 3;
        CPA_WAIT(1);
        __syncthreads();

        const uint32_t aAhi = sbase + s*GSTGB;
        const uint32_t aAlo = aAhi + GPLANE;
        const uint32_t aBhi = aAhi + 2*GPLANE;
        const uint32_t aBlo = aAhi + 3*GPLANE;
        #pragma unroll
        for (int kk = 0; kk < 4; ++kk) {
            uint32_t ah[2][4], al[2][4];
            #pragma unroll
            for (int mt = 0; mt < 2; ++mt) {
                int row = wm*32 + mt*16 + (lane & 15);
                uint32_t c = kk*2 + (lane >> 4);
                uint32_t off = (uint32_t)row*128 + ((c ^ (row & 7)) << 4);
                ldmx4(ah[mt], aAhi + off);
                ldmx4(al[mt], aAlo + off);
            }
            uint32_t bh[4][2], bl[4][2];
            #pragma unroll
            for (int np = 0; np < 2; ++np) {
                int nrow = wn*32 + np*16 + (lane >> 4)*8 + (lane & 7);
                uint32_t c = kk*2 + ((lane >> 3) & 1);
                uint32_t off = (uint32_t)nrow*128 + ((c ^ (nrow & 7)) << 4);
                uint32_t t[4];
                ldmx4(t, aBhi + off);
                bh[2*np][0]=t[0]; bh[2*np][1]=t[1]; bh[2*np+1][0]=t[2]; bh[2*np+1][1]=t[3];
                ldmx4(t, aBlo + off);
                bl[2*np][0]=t[0]; bl[2*np][1]=t[1]; bl[2*np+1][0]=t[2]; bl[2*np+1][1]=t[3];
            }
            #pragma unroll
            for (int mt = 0; mt < 2; ++mt)
                #pragma unroll
                for (int nt = 0; nt < 4; ++nt) {
                    mma16816(acc[mt][nt], ah[mt], bh[nt]);
                    mma16816(acc[mt][nt], ah[mt], bl[nt]);
                    mma16816(acc[mt][nt], al[mt], bh[nt]);
                }
        }
        if (kt + 2 < NCH) load_st(kt + 2, (kt + 2) % 3);
    }

    #pragma unroll
    for (int mt = 0; mt < 2; ++mt) {
        const int row = m0 + wm*32 + mt*16 + (lane >> 2);
        #pragma unroll
        for (int nt = 0; nt < 4; ++nt) {
            const int col = n0 + wn*32 + nt*8 + (lane & 3)*2;
            if (C) {
                *(float2*)(C + (size_t)row*Dd + col)       = make_float2(acc[mt][nt][0], acc[mt][nt][1]);
                *(float2*)(C + (size_t)(row + 8)*Dd + col) = make_float2(acc[mt][nt][2], acc[mt][nt][3]);
            }
            if (Chi) {
                uint32_t h, l;
                split2(acc[mt][nt][0], acc[mt][nt][1], h, l);
                *(uint32_t*)(Chi + (size_t)row*Dd + col) = h;
                *(uint32_t*)(Clo + (size_t)row*Dd + col) = l;
                split2(acc[mt][nt][2], acc[mt][nt][3], h, l);
                *(uint32_t*)(Chi + (size_t)(row + 8)*Dd + col) = h;
                *(uint32_t*)(Clo + (size_t)(row + 8)*Dd + col) = l;
            }
        }
    }
}

// ---------------------------------------------------------------------------
// Flash attention + fused gated adapter cross-attention.
// CTA: 128 q x 64 kv, 8 warps. Q frags hoisted; 3-stage KV ring (stage2 = Q smem).
// Output written as bf16 hi/lo planes at stride KP (Wo GEMM A-operand layout).
// LPT: qt reversed so heavy CTAs launch first.
// ---------------------------------------------------------------------------
#define FQPL 32768
#define FKPL 16384
#define FKVSTG (4*FKPL)
#define FLASH_SMEM (2*FQPL + 2*FKVSTG)   // 196608

__global__ __launch_bounds__(256, 1) void flash_fused(
    const __nv_bfloat16* __restrict__ Qhi, const __nv_bfloat16* __restrict__ Qlo,
    const __nv_bfloat16* __restrict__ Khi, const __nv_bfloat16* __restrict__ Klo,
    const __nv_bfloat16* __restrict__ Vhi, const __nv_bfloat16* __restrict__ Vlo,
    const float* __restrict__ AK, const float* __restrict__ AV,
    const float* __restrict__ gate, const float* __restrict__ ngate,
    __nv_bfloat16* __restrict__ Ohi, __nv_bfloat16* __restrict__ Olo)
{
    extern __shared__ char smf[];
    const int tid = threadIdx.x;
    const int lane = tid & 31, w = tid >> 5;
    const int qt = (int)gridDim.x - 1 - (int)blockIdx.x;    // LPT: heavy first
    const int h = blockIdx.y, b = blockIdx.z;
    const int q0 = qt << 7;
    const uint32_t sbase = smem_u32(smf);
    const float scale = 0.08838834764831845f;

    // Q load (group 0)
    {
        const __nv_bfloat16* srcs[2] = {
            Qhi + (size_t)(b*Ss + q0)*Dd + h*HDd,
            Qlo + (size_t)(b*Ss + q0)*Dd + h*HDd };
        #pragma unroll
        for (int p = 0; p < 2; ++p)
            #pragma unroll
            for (int i = 0; i < 8; ++i) {
                int u = tid + i*256;
                int r = u >> 4, c = u & 15;
                uint32_t dst = sbase + p*FQPL + (uint32_t)r*256 + (c >> 3)*128
                             + ((((uint32_t)c & 7) ^ (r & 7)) << 4);
                cpa16(dst, srcs[p] + (size_t)r*Dd + c*8);
            }
        cpa_commit();
    }
    auto stg = [&](int s) -> uint32_t {
        return (s == 2) ? sbase : (sbase + 2*FQPL + s*FKVSTG);
    };
    auto loadKV = [&](int kt, int s) {
        const int k0 = kt << 6;
        const __nv_bfloat16* srcs[4] = {
            Khi + (size_t)(b*Ss + k0)*Dd + h*HDd, Klo + (size_t)(b*Ss + k0)*Dd + h*HDd,
            Vhi + (size_t)(b*Ss + k0)*Dd + h*HDd, Vlo + (size_t)(b*Ss + k0)*Dd + h*HDd };
        const uint32_t base = stg(s);
        #pragma unroll
        for (int p = 0; p < 4; ++p)
            #pragma unroll
            for (int i = 0; i < 4; ++i) {
                int u = tid + i*256;
                int r = u >> 4, c = u & 15;
                uint32_t dst = base + p*FKPL + (uint32_t)r*256 + (c >> 3)*128
                             + ((((uint32_t)c & 7) ^ (r & 7)) << 4);
                cpa16(dst, srcs[p] + (size_t)r*Dd + c*8);
            }
        cpa_commit();
    };
    loadKV(0, 0);
    CPA_WAIT(1);
    __syncthreads();

    uint32_t qh[8][4], ql[8][4];
    #pragma unroll
    for (int kk = 0; kk < 8; ++kk) {
        int row = w*16 + (lane & 15);
        uint32_t c = kk*2 + (lane >> 4);
        uint32_t off = (uint32_t)row*256 + (c >> 3)*128 + (((c & 7) ^ (row & 7)) << 4);
        ldmx4(qh[kk], sbase + off);
        ldmx4(ql[kk], sbase + FQPL + off);
    }
    loadKV(1, 1);

    float oacc[16][4];
    #pragma unroll
    for (int nt = 0; nt < 16; ++nt)
        #pragma unroll
        for (int e = 0; e < 4; ++e) oacc[nt][e] = 0.f;
    float mrow[2] = {-1e30f, -1e30f};
    float lrow[2] = {0.f, 0.f};

    const int nkt = 2*(qt + 1);
    for (int kt = 0; kt < nkt; ++kt) {
        if (kt + 1 < nkt) { CPA_WAIT(1); } else { CPA_WAIT(0); }
        __syncthreads();
        if (kt + 2 < nkt) loadKV(kt + 2, (kt + 2) % 3);

        const int k0 = kt << 6;
        const bool active = (k0 <= q0 + w*16 + 15);
        if (active) {
        const uint32_t kb = stg(kt % 3);
        const uint32_t vb = kb + 2*FKPL;

        float sacc[8][4];
        #pragma unroll
        for (int nt = 0; nt < 8; ++nt)
            #pragma unroll
            for (int e = 0; e < 4; ++e) sacc[nt][e] = 0.f;
        #pragma unroll
        for (int kk = 0; kk < 8; ++kk) {
            #pragma unroll
            for (int np = 0; np < 4; ++np) {
                int nrow = np*16 + (lane >> 4)*8 + (lane & 7);
                uint32_t c = kk*2 + ((lane >> 3) & 1);
                uint32_t off = (uint32_t)nrow*256 + (c >> 3)*128 + (((c & 7) ^ (nrow & 7)) << 4);
                uint32_t tb[4], tl[4];
                ldmx4(tb, kb + off);
                ldmx4(tl, kb + FKPL + off);
                uint32_t b0[2] = {tb[0], tb[1]}, b1[2] = {tb[2], tb[3]};
                uint32_t l0[2] = {tl[0], tl[1]}, l1[2] = {tl[2], tl[3]};
                mma16816(sacc[2*np],     qh[kk], b0);
                mma16816(sacc[2*np],     qh[kk], l0);
                mma16816(sacc[2*np],     ql[kk], b0);
                mma16816(sacc[2*np + 1], qh[kk], b1);
                mma16816(sacc[2*np + 1], qh[kk], l1);
                mma16816(sacc[2*np + 1], ql[kk], b1);
            }
        }

        const bool needmask = (k0 + 63 > q0 + w*16);
        float corr[2];
        #pragma unroll
        for (int hh = 0; hh < 2; ++hh) {
            const int rowg = q0 + w*16 + (lane >> 2) + hh*8;
            float rmax = -1e30f;
            #pragma unroll
            for (int nt = 0; nt < 8; ++nt)
                #pragma unroll
                for (int e2 = 0; e2 < 2; ++e2) {
                    float v = sacc[nt][hh*2 + e2] * scale;
                    if (needmask) {
                        int colg = k0 + nt*8 + (lane & 3)*2 + e2;
                        if (colg > rowg) v = -1e30f;
                    }
                    sacc[nt][hh*2 + e2] = v;
                    rmax = fmaxf(rmax, v);
                }
            rmax = fmaxf(rmax, __shfl_xor_sync(0xffffffffu, rmax, 1));
            rmax = fmaxf(rmax, __shfl_xor_sync(0xffffffffu, rmax, 2));
            float mn = fmaxf(mrow[hh], rmax);
            corr[hh] = __expf(mrow[hh] - mn);
            float rs = 0.f;
            #pragma unroll
            for (int nt = 0; nt < 8; ++nt)
                #pragma unroll
                for (int e2 = 0; e2 < 2; ++e2) {
                    float p = __expf(sacc[nt][hh*2 + e2] - mn);
                    sacc[nt][hh*2 + e2] = p;
                    rs += p;
                }
            rs += __shfl_xor_sync(0xffffffffu, rs, 1);
            rs += __shfl_xor_sync(0xffffffffu, rs, 2);
            lrow[hh] = lrow[hh]*corr[hh] + rs;
            mrow[hh] = mn;
        }
        #pragma unroll
        for (int nt = 0; nt < 16; ++nt) {
            oacc[nt][0] *= corr[0]; oacc[nt][1] *= corr[0];
            oacc[nt][2] *= corr[1]; oacc[nt][3] *= corr[1];
        }

        #pragma unroll
        for (int kk4 = 0; kk4 < 4; ++kk4) {
            uint32_t ph[4], pl[4];
            #pragma unroll
            for (int part = 0; part < 4; ++part) {
                int tl2 = 2*kk4 + (part >> 1);
                int eh = part & 1;
                split2(sacc[tl2][eh*2], sacc[tl2][eh*2 + 1], ph[part], pl[part]);
            }
            const int mi = lane >> 3;
            const int krow = kk4*16 + (lane & 7) + (mi & 1)*8;
            #pragma unroll
            for (int np = 0; np < 8; ++np) {
                uint32_t c = np*2 + (mi >> 1);
                uint32_t off = (uint32_t)krow*256 + (c >> 3)*128 + (((c & 7) ^ (krow & 7)) << 4);
                uint32_t t[4], t2[4];
                ldmx4t(t,  vb + off);
                ldmx4t(t2, vb + FKPL + off);
                uint32_t bvh0[2] = {t[0],  t[1]},  bvh1[2] = {t[2],  t[3]};
                uint32_t bvl0[2] = {t2[0], t2[1]}, bvl1[2] = {t2[2], t2[3]};
                mma16816(oacc[2*np],     ph, bvh0);
                mma16816(oacc[2*np],     ph, bvl0);
                mma16816(oacc[2*np],     pl, bvh0);
                mma16816(oacc[2*np + 1], ph, bvh1);
                mma16816(oacc[2*np + 1], ph, bvl1);
                mma16816(oacc[2*np + 1], pl, bvh1);
            }
        }
        } // active
    }

    // normalize main attention
    {
        const float inv0 = 1.f / lrow[0];
        const float inv1 = 1.f / lrow[1];
        #pragma unroll
        for (int nt = 0; nt < 16; ++nt) {
            oacc[nt][0] *= inv0; oacc[nt][1] *= inv0;
            oacc[nt][2] *= inv1; oacc[nt][3] *= inv1;
        }
    }

    // ---- fused adapter cross-attention ----
    __syncthreads();   // all warps done reading KV stages
    // ak/av hi/lo planes at sbase: akhi 0, aklo 4K, avhi 8K, avlo 12K (16 rows x 128 cols)
    for (int u = tid; u < 16*64; u += 256) {
        int r = u >> 6, cp = u & 63;          // cols 2cp, 2cp+1
        float f0=0.f, f1=0.f, g0=0.f, g1=0.f;
        if (r < ALa) {
            const float* akp_ = AK + ((size_t)(b*ALa + r))*Dd + h*HDd + 2*cp;
            const float* avp_ = AV + ((size_t)(b*ALa + r))*Dd + h*HDd + 2*cp;
            f0 = akp_[0]; f1 = akp_[1];
            g0 = avp_[0]; g1 = avp_[1];
        }
        uint32_t cu = (uint32_t)(cp >> 2);            // 16B unit index (0..15)
        uint32_t intra = ((uint32_t)cp*4) & 15;
        uint32_t off = (uint32_t)r*256 + ((cu >> 3) << 7) + (((cu & 7) ^ (r & 7)) << 4) + intra;
        uint32_t hv, lv;
        split2(f0, f1, hv, lv);
        *(uint32_t*)(smf + off)         = hv;
        *(uint32_t*)(smf + 4096 + off)  = lv;
        split2(g0, g1, hv, lv);
        *(uint32_t*)(smf + 8192 + off)  = hv;
        *(uint32_t*)(smf + 12288 + off) = lv;
    }
    __syncthreads();

    // adapter scores: S_a (16q x 16k), K = HD = 128
    float sa[2][4];
    #pragma unroll
    for (int nt = 0; nt < 2; ++nt)
        #pragma unroll
        for (int e = 0; e < 4; ++e) sa[nt][e] = 0.f;
    #pragma unroll
    for (int kk = 0; kk < 8; ++kk) {
        int nrow = (lane >> 4)*8 + (lane & 7);
        uint32_t c = kk*2 + ((lane >> 3) & 1);
        uint32_t off = (uint32_t)nrow*256 + ((c >> 3) << 7) + (((c & 7) ^ (nrow & 7)) << 4);
        uint32_t tb[4], tl[4];
        ldmx4(tb, sbase + off);           // akhi
        ldmx4(tl, sbase + 4096 + off);    // aklo
        uint32_t b0[2] = {tb[0], tb[1]}, b1[2] = {tb[2], tb[3]};
        uint32_t l0[2] = {tl[0], tl[1]}, l1[2] = {tl[2], tl[3]};
        mma16816(sa[0], qh[kk], b0);
        mma16816(sa[0], qh[kk], l0);
        mma16816(sa[0], ql[kk], b0);
        mma16816(sa[1], qh[kk], b1);
        mma16816(sa[1], qh[kk], l1);
        mma16816(sa[1], ql[kk], b1);
    }
    // softmax over 10 valid cols, scale by tanh(gate)*ngate/sum
    {
        const float g = tanhf(gate[h]) * ngate[0];
        #pragma unroll
        for (int hh = 0; hh < 2; ++hh) {
            float rmax = -1e30f;
            #pragma unroll
            for (int nt = 0; nt < 2; ++nt)
                #pragma unroll
                for (int e2 = 0; e2 < 2; ++e2) {
                    int colg = nt*8 + (lane & 3)*2 + e2;
                    float v = sa[nt][hh*2 + e2] * scale;
                    if (colg >= ALa) v = -1e30f;
                    sa[nt][hh*2 + e2] = v;
                    rmax = fmaxf(rmax, v);
                }
            rmax = fmaxf(rmax, __shfl_xor_sync(0xffffffffu, rmax, 1));
            rmax = fmaxf(rmax, __shfl_xor_sync(0xffffffffu, rmax, 2));
            float rs = 0.f;
            #pragma unroll
            for (int nt = 0; nt < 2; ++nt)
                #pragma unroll
                for (int e2 = 0; e2 < 2; ++e2) {
                    float p = __expf(sa[nt][hh*2 + e2] - rmax);
                    sa[nt][hh*2 + e2] = p;
                    rs += p;
                }
            rs += __shfl_xor_sync(0xffffffffu, rs, 1);
            rs += __shfl_xor_sync(0xffffffffu, rs, 2);
            const float wgt = g / rs;
            #pragma unroll
            for (int nt = 0; nt < 2; ++nt)
                #pragma unroll
                for (int e2 = 0; e2 < 2; ++e2)
                    sa[nt][hh*2 + e2] *= wgt;
        }
    }
    // adapter PV into oacc (already normalized): O += P_a * AV
    {
        uint32_t ph[4], pl[4];
        #pragma unroll
        for (int part = 0; part < 4; ++part) {
            int tl2 = part >> 1;
            int eh = part & 1;
            split2(sa[tl2][eh*2], sa[tl2][eh*2 + 1], ph[part], pl[part]);
        }
        const int mi = lane >> 3;
        const int krow = (lane & 7) + (mi & 1)*8;
        #pragma unroll
        for (int np = 0; np < 8; ++np) {
            uint32_t c = np*2 + (mi >> 1);
            uint32_t off = (uint32_t)krow*256 + ((c >> 3) << 7) + (((c & 7) ^ (krow & 7)) << 4);
            uint32_t t[4], t2[4];
            ldmx4t(t,  sbase + 8192 + off);    // avhi
            ldmx4t(t2, sbase + 12288 + off);   // avlo
            uint32_t bvh0[2] = {t[0],  t[1]},  bvh1[2] = {t[2],  t[3]};
            uint32_t bvl0[2] = {t2[0], t2[1]}, bvl1[2] = {t2[2], t2[3]};
            mma16816(oacc[2*np],     ph, bvh0);
            mma16816(oacc[2*np],     ph, bvl0);
            mma16816(oacc[2*np],     pl, bvh0);
            mma16816(oacc[2*np + 1], ph, bvh1);
            mma16816(oacc[2*np + 1], ph, bvl1);
            mma16816(oacc[2*np + 1], pl, bvh1);
        }
    }

    // ---- store hi/lo planes (Wo GEMM A-operand layout, stride KP)
    const size_t r0 = (size_t)(b*Ss + q0 + w*16 + (lane >> 2));
    #pragma unroll
    for (int nt = 0; nt < 16; ++nt) {
        const int col = h*HDd + nt*8 + (lane & 3)*2;
        uint32_t hv, lv;
        split2(oacc[nt][0], oacc[nt][1], hv, lv);
        *(uint32_t*)(Ohi + r0*KP + col) = hv;
        *(uint32_t*)(Olo + r0*KP + col) = lv;
        split2(oacc[nt][2], oacc[nt][3], hv, lv);
        *(uint32_t*)(Ohi + (r0 + 8)*KP + col) = hv;
        *(uint32_t*)(Olo + (r0 + 8)*KP + col) = lv;
    }
}

// ---------------------------------------------------------------------------
// lora_part: partial T over k-range, X = fp32. grid (M/64, KSPL)
// ---------------------------------------------------------------------------
__global__ __launch_bounds__(256) void lora_part(
    const float* __restrict__ X,
    const float* __restrict__ L1a, const float* __restrict__ L1b, const float* __restrict__ L1c,
    float* __restrict__ Tp, int nmat, int ldt)
{
    __shared__ float Xs[32][68];
    __shared__ float Ls[32][52];
    const int tid = threadIdx.x;
    const int tx = tid & 15, ty = tid >> 4;
    const int m0 = blockIdx.x << 6;
    const int ks = blockIdx.y;
    const int Rtot = nmat << 4;
    float acc[4][3];
    #pragma unroll
    for (int i = 0; i < 4; ++i)
        #pragma unroll
        for (int j = 0; j < 3; ++j) acc[i][j] = 0.f;

    for (int k0 = ks*512; k0 < ks*512 + 512; k0 += 32) {
        __syncthreads();
        #pragma unroll
        for (int i = 0; i < 2; ++i) {
            int v = tid + i*256;
            int r = v >> 3, c = (v & 7) << 2;
            float4 x4 = *(const float4*)(X + (size_t)(m0 + r)*Dd + k0 + c);
            Xs[c+0][r]=x4.x; Xs[c+1][r]=x4.y; Xs[c+2][r]=x4.z; Xs[c+3][r]=x4.w;
        }
        for (int v = tid; v < Rtot*8; v += 256) {
            int r = v >> 3, c = (v & 7) << 2;
            const float* src = (r < 16) ? (L1a + (size_t)r*Dd)
                             : (r < 32) ? (L1b + (size_t)(r-16)*Dd)
                                        : (L1c + (size_t)(r-32)*Dd);
            float4 l4 = *(const float4*)(src + k0 + c);
            Ls[c+0][r]=l4.x; Ls[c+1][r]=l4.y; Ls[c+2][r]=l4.z; Ls[c+3][r]=l4.w;
        }
        __syncthreads();
        #pragma unroll
        for (int k = 0; k < 32; ++k) {
            float xv[4];
            #pragma unroll
            for (int i = 0; i < 4; ++i) xv[i] = Xs[k][4*ty + i];
            for (int j = 0; j < nmat; ++j) {
                float lv = Ls[k][tx + 16*j];
                #pragma unroll
                for (int i = 0; i < 4; ++i) acc[i][j] = fmaf(xv[i], lv, acc[i][j]);
            }
        }
    }
    float* out = Tp + (size_t)ks*MROWS*ldt;
    for (int j = 0; j < nmat; ++j)
        #pragma unroll
        for (int i = 0; i < 4; ++i)
            out[(size_t)(m0 + 4*ty + i)*ldt + tx + 16*j] = acc[i][j];
}

// ---------------------------------------------------------------------------
// lora_part_planes: same, but X reconstructed from bf16 hi/lo planes (stride KP)
// ---------------------------------------------------------------------------
__global__ __launch_bounds__(256) void lora_part_planes(
    const __nv_bfloat16* __restrict__ Xhi, const __nv_bfloat16* __restrict__ Xlo,
    const float* __restrict__ L1a,
    float* __restrict__ Tp, int ldt)
{
    __shared__ float Xs[32][68];
    __shared__ float Ls[32][20];
    const int tid = threadIdx.x;
    const int tx = tid & 15, ty = tid >> 4;
    const int m0 = blockIdx.x << 6;
    const int ks = blockIdx.y;
    float acc[4];
    #pragma unroll
    for (int i = 0; i < 4; ++i) acc[i] = 0.f;

    for (int k0 = ks*512; k0 < ks*512 + 512; k0 += 32) {
        __syncthreads();
        #pragma unroll
        for (int i = 0; i < 2; ++i) {
            int v = tid + i*256;
            int r = v >> 3, c = (v & 7) << 2;
            uint2 hu = *(const uint2*)(Xhi + (size_t)(m0 + r)*KP + k0 + c);
            uint2 lu = *(const uint2*)(Xlo + (size_t)(m0 + r)*KP + k0 + c);
            __nv_bfloat162 h0 = *(__nv_bfloat162*)&hu.x;
            __nv_bfloat162 h1 = *(__nv_bfloat162*)&hu.y;
            __nv_bfloat162 l0 = *(__nv_bfloat162*)&lu.x;
            __nv_bfloat162 l1 = *(__nv_bfloat162*)&lu.y;
            Xs[c+0][r] = __bfloat162float(h0.x) + __bfloat162float(l0.x);
            Xs[c+1][r] = __bfloat162float(h0.y) + __bfloat162float(l0.y);
            Xs[c+2][r] = __bfloat162float(h1.x) + __bfloat162float(l1.x);
            Xs[c+3][r] = __bfloat162float(h1.y) + __bfloat162float(l1.y);
        }
        for (int v = tid; v < 128; v += 256) {
            int r = v >> 3, c = (v & 7) << 2;
            float4 l4 = *(const float4*)(L1a + (size_t)r*Dd + k0 + c);
            Ls[c+0][r]=l4.x; Ls[c+1][r]=l4.y; Ls[c+2][r]=l4.z; Ls[c+3][r]=l4.w;
        }
        __syncthreads();
        #pragma unroll
        for (int k = 0; k < 32; ++k) {
            float lv = Ls[k][tx];
            #pragma unroll
            for (int i = 0; i < 4; ++i) acc[i] = fmaf(Xs[k][4*ty + i], lv, acc[i]);
        }
    }
    float* out = Tp + (size_t)ks*MROWS*ldt;
    #pragma unroll
    for (int i = 0; i < 4; ++i)
        out[(size_t)(m0 + 4*ty + i)*ldt + tx] = acc[i];
}

// ---------------------------------------------------------------------------
// adapter_part: partial AK/AV over k-range. grid (Dd/64, KSPL)
// ---------------------------------------------------------------------------
__global__ __launch_bounds__(256) void adapter_part(
    const float* __restrict__ Ad, const float* __restrict__ Wk, const float* __restrict__ Wv,
    float* __restrict__ AKp, float* __restrict__ AVp)
{
    __shared__ float Ads[20][68];
    __shared__ float Wks[64][65];
    __shared__ float Wvs[64][65];
    const int tid = threadIdx.x;
    const int nl = tid & 63, mg = tid >> 6;
    const int n0 = blockIdx.x << 6;
    const int ks = blockIdx.y;
    float ak[5] = {0,0,0,0,0}, av[5] = {0,0,0,0,0};

    for (int k0 = ks*512; k0 < ks*512 + 512; k0 += 64) {
        __syncthreads();
        for (int v = tid; v < 320; v += 256) {
            int r = v >> 4, c = (v & 15) << 2;
            float4 a4 = *(const float4*)(Ad + (size_t)r*Dd + k0 + c);
            Ads[r][c+0]=a4.x; Ads[r][c+1]=a4.y; Ads[r][c+2]=a4.z; Ads[r][c+3]=a4.w;
        }
        #pragma unroll
        for (int i = 0; i < 4; ++i) {
            int v = tid + i*256;
            int r = v >> 4, c = (v & 15) << 2;
            float4 w4 = *(const float4*)(Wk + (size_t)(n0 + r)*Dd + k0 + c);
            Wks[c+0][r]=w4.x; Wks[c+1][r]=w4.y; Wks[c+2][r]=w4.z; Wks[c+3][r]=w4.w;
            float4 w5 = *(const float4*)(Wv + (size_t)(n0 + r)*Dd + k0 + c);
            Wvs[c+0][r]=w5.x; Wvs[c+1][r]=w5.y; Wvs[c+2][r]=w5.z; Wvs[c+3][r]=w5.w;
        }
        __syncthreads();
        #pragma unroll
        for (int k = 0; k < 64; ++k) {
            float wkv = Wks[k][nl];
            float wvv = Wvs[k][nl];
            #pragma unroll
            for (int i = 0; i < 5; ++i) {
                float a = Ads[5*mg + i][k];
                ak[i] = fmaf(a, wkv, ak[i]);
                av[i] = fmaf(a, wvv, av[i]);
            }
        }
    }
    float* akp = AKp + (size_t)ks*20*Dd;
    float* avp = AVp + (size_t)ks*20*Dd;
    #pragma unroll
    for (int i = 0; i < 5; ++i) {
        akp[(size_t)(5*mg + i)*Dd + n0 + nl] = ak[i];
        avp[(size_t)(5*mg + i)*Dd + n0 + nl] = av[i];
    }
}

// ---------------------------------------------------------------------------
// Launch
// ---------------------------------------------------------------------------
extern "C" void kernel_launch(void* const* d_in, const int* in_sizes, int n_in,
                              void* d_out, int out_size)
{
    (void)in_sizes; (void)n_in; (void)out_size;
    const float* x       = (const float*)d_in[0];
    const float* adapter = (const float*)d_in[4];
    const float* wq  = (const float*)d_in[5];
    const float* wk  = (const float*)d_in[6];
    const float* wv  = (const float*)d_in[7];
    const float* wo  = (const float*)d_in[8];
    const float* lq1 = (const float*)d_in[9];
    const float* lq2 = (const float*)d_in[10];
    const float* lk1 = (const float*)d_in[11];
    const float* lk2 = (const float*)d_in[12];
    const float* lv1 = (const float*)d_in[13];
    const float* lv2 = (const float*)d_in[14];
    const float* lo1 = (const float*)d_in[15];
    const float* lo2 = (const float*)d_in[16];
    const float* gate  = (const float*)d_in[17];
    const float* ngate = (const float*)d_in[18];
    float* out = (float*)d_out;

    float *T, *Tp, *ak, *av, *akp, *avp;
    __nv_bfloat16 *cvAhi, *cvAlo, *cvBhi, *cvBlo, *qhi, *qlo, *khi, *klo, *vhi, *vlo;
    cudaGetSymbolAddress((void**)&T,    g_T);
    cudaGetSymbolAddress((void**)&Tp,   g_Tp);
    cudaGetSymbolAddress((void**)&ak,   g_ak);
    cudaGetSymbolAddress((void**)&av,   g_av);
    cudaGetSymbolAddress((void**)&akp,  g_akp);
    cudaGetSymbolAddress((void**)&avp,  g_avp);
    cudaGetSymbolAddress((void**)&cvAhi, g_cvAhi);
    cudaGetSymbolAddress((void**)&cvAlo, g_cvAlo);
    cudaGetSymbolAddress((void**)&cvBhi, g_cvBhi);
    cudaGetSymbolAddress((void**)&cvBlo, g_cvBlo);
    cudaGetSymbolAddress((void**)&qhi,  g_qhi);
    cudaGetSymbolAddress((void**)&qlo,  g_qlo);
    cudaGetSymbolAddress((void**)&khi,  g_khi);
    cudaGetSymbolAddress((void**)&klo,  g_klo);
    cudaGetSymbolAddress((void**)&vhi,  g_vhi);
    cudaGetSymbolAddress((void**)&vlo,  g_vlo);

    cudaFuncSetAttribute(gemm_bf,     cudaFuncAttributeMaxDynamicSharedMemorySize, GEMM_SMEM);
    cudaFuncSetAttribute(flash_fused, cudaFuncAttributeMaxDynamicSharedMemorySize, FLASH_SMEM);

    const dim3 gGrid(Dd/128, MROWS/128);
    const int convBlocks = MROWS*520/256;

    // 1) LoRA intermediates (q/k/v), k-split
    lora_part<<<dim3(MROWS/64, KSPL), 256>>>(x, lq1, lk1, lv1, Tp, 3, 48);
    reduce8<<<MROWS*48/256, 256>>>(T, Tp, MROWS*48);
    // 2) convert A = [x | T(48) | 0]
    conv_split<<<convBlocks, 256>>>(x, T, 48, 48, 0, cvAhi, cvAlo);
    // 3) QKV projections -> bf16 hi/lo planes
    conv_split<<<convBlocks, 256>>>(wq, lq2, 16, 16, 0, cvBhi, cvBlo);
    gemm_bf<<<gGrid, 512, GEMM_SMEM>>>(cvAhi, cvAlo, cvBhi, cvBlo, nullptr, qhi, qlo);
    conv_split<<<convBlocks, 256>>>(wk, lk2, 16, 16, 16, cvBhi, cvBlo);
    gemm_bf<<<gGrid, 512, GEMM_SMEM>>>(cvAhi, cvAlo, cvBhi, cvBlo, nullptr, khi, klo);
    conv_split<<<convBlocks, 256>>>(wv, lv2, 16, 16, 32, cvBhi, cvBlo);
    gemm_bf<<<gGrid, 512, GEMM_SMEM>>>(cvAhi, cvAlo, cvBhi, cvBlo, nullptr, vhi, vlo);
    // 4) adapter K/V projection, k-split
    adapter_part<<<dim3(Dd/64, KSPL), 256>>>(adapter, wk, wv, akp, avp);
    reduce8<<<20*Dd/256, 256>>>(ak, akp, 20*Dd);
    reduce8<<<20*Dd/256, 256>>>(av, avp, 20*Dd);
    // 5) flash attention + fused adapter -> cvA planes (cols h*128..)
    flash_fused<<<dim3(Ss/128, Hh, Bb), 256, FLASH_SMEM>>>(
        qhi, qlo, khi, klo, vhi, vlo, ak, av, gate, ngate, cvAhi, cvAlo);
    // 6) output LoRA chunk: To from att planes -> cvA cols [4096,4160)
    lora_part_planes<<<dim3(MROWS/64, KSPL), 256>>>(cvAhi, cvAlo, lo1, Tp, 16);
    reduce_fill<<<MROWS*64/256, 256>>>(Tp, cvAhi, cvAlo);
    // 7) output projection
    conv_split<<<convBlocks, 256>>>(wo, lo2, 16, 16, 0, cvBhi, cvBlo);
    gemm_bf<<<gGrid, 512, GEMM_SMEM>>>(cvAhi, cvAlo, cvBhi, cvBlo, out, nullptr, nullptr);
}

// round 9
// speedup vs baseline: 4.2399x; 1.0471x over previous
#include <cuda_runtime.h>
#include <cuda_bf16.h>
#include <math.h>
#include <stdint.h>

// Problem constants
#define Bb   2
#define Ss   2048
#define Dd   4096
#define Hh   32
#define HDd  128
#define ALa  10
#define MROWS (Bb*Ss)          // 4096
#define KP   4160              // 4096 + 64 (LoRA chunk)
#define NCH  65                // K'/64
#define KSPL 8                 // k-split for small gemms

// ---------------------------------------------------------------------------
// Scratch (device globals; no cudaMalloc allowed)
// ---------------------------------------------------------------------------
__device__ float g_T  [MROWS*48];
__device__ float g_Tp [KSPL*MROWS*48];
__device__ float g_ak [Bb*ALa*Dd];
__device__ float g_av [Bb*ALa*Dd];
__device__ float g_akp[KSPL*Bb*ALa*Dd];
__device__ float g_avp[KSPL*Bb*ALa*Dd];
__device__ __nv_bfloat16 g_cvAhi[MROWS*KP];
__device__ __nv_bfloat16 g_cvAlo[MROWS*KP];
__device__ __nv_bfloat16 g_cvB1hi[Dd*KP];
__device__ __nv_bfloat16 g_cvB1lo[Dd*KP];
__device__ __nv_bfloat16 g_cvB2hi[Dd*KP];
__device__ __nv_bfloat16 g_cvB2lo[Dd*KP];
__device__ __nv_bfloat16 g_qhi[MROWS*Dd];
__device__ __nv_bfloat16 g_qlo[MROWS*Dd];
__device__ __nv_bfloat16 g_khi[MROWS*Dd];
__device__ __nv_bfloat16 g_klo[MROWS*Dd];
__device__ __nv_bfloat16 g_vhi[MROWS*Dd];
__device__ __nv_bfloat16 g_vlo[MROWS*Dd];

// ---------------------------------------------------------------------------
// helpers
// ---------------------------------------------------------------------------
__device__ __forceinline__ uint32_t smem_u32(const void* p) {
    uint32_t a;
    asm("{ .reg .u64 t; cvta.to.shared.u64 t, %1; cvt.u32.u64 %0, t; }" : "=r"(a) : "l"(p));
    return a;
}
__device__ __forceinline__ void cpa16(uint32_t dst, const void* src) {
    asm volatile("cp.async.cg.shared.global [%0], [%1], 16;" :: "r"(dst), "l"(src));
}
__device__ __forceinline__ void cpa_commit() { asm volatile("cp.async.commit_group;"); }
#define CPA_WAIT(N) asm volatile("cp.async.wait_group %0;" :: "n"(N))
__device__ __forceinline__ void ldmx4(uint32_t* r, uint32_t addr) {
    asm volatile("ldmatrix.sync.aligned.m8n8.x4.shared.b16 {%0,%1,%2,%3}, [%4];"
                 : "=r"(r[0]), "=r"(r[1]), "=r"(r[2]), "=r"(r[3]) : "r"(addr));
}
__device__ __forceinline__ void ldmx4t(uint32_t* r, uint32_t addr) {
    asm volatile("ldmatrix.sync.aligned.m8n8.x4.trans.shared.b16 {%0,%1,%2,%3}, [%4];"
                 : "=r"(r[0]), "=r"(r[1]), "=r"(r[2]), "=r"(r[3]) : "r"(addr));
}
__device__ __forceinline__ void mma16816(float* c, const uint32_t* a, const uint32_t* b) {
    asm volatile(
        "mma.sync.aligned.m16n8k16.row.col.f32.bf16.bf16.f32 "
        "{%0,%1,%2,%3}, {%4,%5,%6,%7}, {%8,%9}, {%0,%1,%2,%3};"
        : "+f"(c[0]), "+f"(c[1]), "+f"(c[2]), "+f"(c[3])
        : "r"(a[0]), "r"(a[1]), "r"(a[2]), "r"(a[3]), "r"(b[0]), "r"(b[1]));
}
__device__ __forceinline__ void split2(float f0, float f1, uint32_t& hi, uint32_t& lo) {
    __nv_bfloat16 h0 = __float2bfloat16_rn(f0);
    __nv_bfloat16 h1 = __float2bfloat16_rn(f1);
    __nv_bfloat16 l0 = __float2bfloat16_rn(f0 - __bfloat162float(h0));
    __nv_bfloat16 l1 = __float2bfloat16_rn(f1 - __bfloat162float(h1));
    __nv_bfloat162 ph; ph.x = h0; ph.y = h1;
    __nv_bfloat162 pl; pl.x = l0; pl.y = l1;
    hi = *(uint32_t*)&ph;
    lo = *(uint32_t*)&pl;
}

// ---------------------------------------------------------------------------
// conv_split: dst[M x KP] (hi/lo bf16) = [src(Mx4096) | lora block | zeros]
// ---------------------------------------------------------------------------
__global__ __launch_bounds__(256) void conv_split(
    const float* __restrict__ src,
    const float* __restrict__ lsrc, int ldl, int lcols, int lshift,
    __nv_bfloat16* __restrict__ dhi, __nv_bfloat16* __restrict__ dlo)
{
    const int u = blockIdx.x * 256 + threadIdx.x;
    const int r = u / 520, g = u % 520;
    float f[8];
    if (g < 512) {
        float4 a = *(const float4*)(src + (size_t)r*4096 + g*8);
        float4 b = *(const float4*)(src + (size_t)r*4096 + g*8 + 4);
        f[0]=a.x; f[1]=a.y; f[2]=a.z; f[3]=a.w; f[4]=b.x; f[5]=b.y; f[6]=b.z; f[7]=b.w;
    } else {
        #pragma unroll
        for (int i = 0; i < 8; ++i) {
            int e = g*8 - 4096 + i;
            int lc = e - lshift;
            f[i] = (lc >= 0 && lc < lcols) ? lsrc[(size_t)r*ldl + lc] : 0.f;
        }
    }
    uint32_t h[4], l[4];
    #pragma unroll
    for (int e = 0; e < 4; ++e) split2(f[2*e], f[2*e+1], h[e], l[e]);
    *(uint4*)(dhi + (size_t)r*KP + g*8) = make_uint4(h[0], h[1], h[2], h[3]);
    *(uint4*)(dlo + (size_t)r*KP + g*8) = make_uint4(l[0], l[1], l[2], l[3]);
}

// ---------------------------------------------------------------------------
// reduce8: dst[i] = sum_{s<8} src[s*len + i]
// ---------------------------------------------------------------------------
__global__ __launch_bounds__(256) void reduce8(
    float* __restrict__ dst, const float* __restrict__ src, int len)
{
    const int i = blockIdx.x*256 + threadIdx.x;
    float s = 0.f;
    #pragma unroll
    for (int k = 0; k < KSPL; ++k) s += src[(size_t)k*len + i];
    dst[i] = s;
}

// ---------------------------------------------------------------------------
// reduce_fill: To = sum8 Tp; write split into cvA cols [4096, 4160)
// ---------------------------------------------------------------------------
__global__ __launch_bounds__(256) void reduce_fill(
    const float* __restrict__ Tp,
    __nv_bfloat16* __restrict__ dhi, __nv_bfloat16* __restrict__ dlo)
{
    const int u = blockIdx.x*256 + threadIdx.x;
    const int r = u >> 6, c = u & 63;
    float s = 0.f;
    if (c < 16) {
        #pragma unroll
        for (int k = 0; k < KSPL; ++k) s += Tp[(size_t)k*MROWS*16 + r*16 + c];
    }
    __nv_bfloat16 h = __float2bfloat16_rn(s);
    __nv_bfloat16 l = __float2bfloat16_rn(s - __bfloat162float(h));
    dhi[(size_t)r*KP + 4096 + c] = h;
    dlo[(size_t)r*KP + 4096 + c] = l;
}

// ---------------------------------------------------------------------------
// Pure-bf16 mma GEMM, 256 threads (8 warps, 32x64 warp tiles), cp.async
// 3-stage pipeline. C (fp32) optional; hi/lo output planes optional.
// (Reverted from 512t: the 32x32 config raised ldmatrix count 33% per mma
//  and regressed; this config measured tensor=78% @ 996us.)
// ---------------------------------------------------------------------------
#define GPLANE 16384
#define GSTGB  (4*GPLANE)
#define GEMM_SMEM (3*GSTGB)   // 196608

__global__ __launch_bounds__(256, 1) void gemm_bf(
    const __nv_bfloat16* __restrict__ Ahi, const __nv_bfloat16* __restrict__ Alo,
    const __nv_bfloat16* __restrict__ Bhi, const __nv_bfloat16* __restrict__ Blo,
    float* __restrict__ C, __nv_bfloat16* __restrict__ Chi, __nv_bfloat16* __restrict__ Clo)
{
    extern __shared__ char smg[];
    const int tid = threadIdx.x;
    const int lane = tid & 31, wid = tid >> 5;
    const int wm = wid & 3, wn = wid >> 2;    // 4 x 2 warp grid, 32x64 tiles
    const int m0 = blockIdx.y << 7;
    const int n0 = blockIdx.x << 7;
    const uint32_t sbase = smem_u32(smg);

    float acc[2][8][4];
    #pragma unroll
    for (int mt = 0; mt < 2; ++mt)
        #pragma unroll
        for (int nt = 0; nt < 8; ++nt)
            #pragma unroll
            for (int e = 0; e < 4; ++e) acc[mt][nt][e] = 0.f;

    auto load_st = [&](int kt, int s) {
        const __nv_bfloat16* srcs[4] = {
            Ahi + (size_t)m0*KP + kt*64, Alo + (size_t)m0*KP + kt*64,
            Bhi + (size_t)n0*KP + kt*64, Blo + (size_t)n0*KP + kt*64 };
        const uint32_t base = sbase + s*GSTGB;
        #pragma unroll
        for (int p = 0; p < 4; ++p) {
            #pragma unroll
            for (int i = 0; i < 4; ++i) {
                int u = tid + i*256;
                int r = u >> 3, c = u & 7;
                cpa16(base + p*GPLANE + r*128 + (((uint32_t)c ^ (r & 7)) << 4),
                      srcs[p] + (size_t)r*KP + c*8);
            }
        }
        cpa_commit();
    };

    load_st(0, 0);
    load_st(1, 1);

    for (int kt = 0; kt < NCH; ++kt) {
        const int s = kt % 3;
        CPA_WAIT(1);
        __syncthreads();

        const uint32_t aAhi = sbase + s*GSTGB;
        const uint32_t aAlo = aAhi + GPLANE;
        const uint32_t aBhi = aAhi + 2*GPLANE;
        const uint32_t aBlo = aAhi + 3*GPLANE;
        #pragma unroll
        for (int kk = 0; kk < 4; ++kk) {
            uint32_t ah[2][4], al[2][4];
            #pragma unroll
            for (int mt = 0; mt < 2; ++mt) {
                int row = wm*32 + mt*16 + (lane & 15);
                uint32_t c = kk*2 + (lane >> 4);
                uint32_t off = (uint32_t)row*128 + ((c ^ (row & 7)) << 4);
                ldmx4(ah[mt], aAhi + off);
                ldmx4(al[mt], aAlo + off);
            }
            uint32_t bh[8][2], bl[8][2];
            #pragma unroll
            for (int np = 0; np < 4; ++np) {
                int nrow = wn*64 + np*16 + (lane >> 4)*8 + (lane & 7);
                uint32_t c = kk*2 + ((lane >> 3) & 1);
                uint32_t off = (uint32_t)nrow*128 + ((c ^ (nrow & 7)) << 4);
                uint32_t t[4];
                ldmx4(t, aBhi + off);
                bh[2*np][0]=t[0]; bh[2*np][1]=t[1]; bh[2*np+1][0]=t[2]; bh[2*np+1][1]=t[3];
                ldmx4(t, aBlo + off);
                bl[2*np][0]=t[0]; bl[2*np][1]=t[1]; bl[2*np+1][0]=t[2]; bl[2*np+1][1]=t[3];
            }
            #pragma unroll
            for (int mt = 0; mt < 2; ++mt)
                #pragma unroll
                for (int nt = 0; nt < 8; ++nt) {
                    mma16816(acc[mt][nt], ah[mt], bh[nt]);
                    mma16816(acc[mt][nt], ah[mt], bl[nt]);
                    mma16816(acc[mt][nt], al[mt], bh[nt]);
                }
        }
        if (kt + 2 < NCH) load_st(kt + 2, (kt + 2) % 3);
    }

    #pragma unroll
    for (int mt = 0; mt < 2; ++mt) {
        const int row = m0 + wm*32 + mt*16 + (lane >> 2);
        #pragma unroll
        for (int nt = 0; nt < 8; ++nt) {
            const int col = n0 + wn*64 + nt*8 + (lane & 3)*2;
            if (C) {
                *(float2*)(C + (size_t)row*Dd + col)       = make_float2(acc[mt][nt][0], acc[mt][nt][1]);
                *(float2*)(C + (size_t)(row + 8)*Dd + col) = make_float2(acc[mt][nt][2], acc[mt][nt][3]);
            }
            if (Chi) {
                uint32_t h, l;
                split2(acc[mt][nt][0], acc[mt][nt][1], h, l);
                *(uint32_t*)(Chi + (size_t)row*Dd + col) = h;
                *(uint32_t*)(Clo + (size_t)row*Dd + col) = l;
                split2(acc[mt][nt][2], acc[mt][nt][3], h, l);
                *(uint32_t*)(Chi + (size_t)(row + 8)*Dd + col) = h;
                *(uint32_t*)(Clo + (size_t)(row + 8)*Dd + col) = l;
            }
        }
    }
}

// ---------------------------------------------------------------------------
// Flash attention + fused gated adapter cross-attention.
// CTA: 128 q x 64 kv, 8 warps. Q frags hoisted; 3-stage KV ring (stage2 = Q smem).
// Output written as bf16 hi/lo planes at stride KP (Wo GEMM A-operand layout).
// LPT: qt reversed so heavy CTAs launch first.
// ---------------------------------------------------------------------------
#define FQPL 32768
#define FKPL 16384
#define FKVSTG (4*FKPL)
#define FLASH_SMEM (2*FQPL + 2*FKVSTG)   // 196608

__global__ __launch_bounds__(256, 1) void flash_fused(
    const __nv_bfloat16* __restrict__ Qhi, const __nv_bfloat16* __restrict__ Qlo,
    const __nv_bfloat16* __restrict__ Khi, const __nv_bfloat16* __restrict__ Klo,
    const __nv_bfloat16* __restrict__ Vhi, const __nv_bfloat16* __restrict__ Vlo,
    const float* __restrict__ AK, const float* __restrict__ AV,
    const float* __restrict__ gate, const float* __restrict__ ngate,
    __nv_bfloat16* __restrict__ Ohi, __nv_bfloat16* __restrict__ Olo)
{
    extern __shared__ char smf[];
    const int tid = threadIdx.x;
    const int lane = tid & 31, w = tid >> 5;
    const int qt = (int)gridDim.x - 1 - (int)blockIdx.x;    // LPT: heavy first
    const int h = blockIdx.y, b = blockIdx.z;
    const int q0 = qt << 7;
    const uint32_t sbase = smem_u32(smf);
    const float scale = 0.08838834764831845f;

    // Q load (group 0)
    {
        const __nv_bfloat16* srcs[2] = {
            Qhi + (size_t)(b*Ss + q0)*Dd + h*HDd,
            Qlo + (size_t)(b*Ss + q0)*Dd + h*HDd };
        #pragma unroll
        for (int p = 0; p < 2; ++p)
            #pragma unroll
            for (int i = 0; i < 8; ++i) {
                int u = tid + i*256;
                int r = u >> 4, c = u & 15;
                uint32_t dst = sbase + p*FQPL + (uint32_t)r*256 + (c >> 3)*128
                             + ((((uint32_t)c & 7) ^ (r & 7)) << 4);
                cpa16(dst, srcs[p] + (size_t)r*Dd + c*8);
            }
        cpa_commit();
    }
    auto stg = [&](int s) -> uint32_t {
        return (s == 2) ? sbase : (sbase + 2*FQPL + s*FKVSTG);
    };
    auto loadKV = [&](int kt, int s) {
        const int k0 = kt << 6;
        const __nv_bfloat16* srcs[4] = {
            Khi + (size_t)(b*Ss + k0)*Dd + h*HDd, Klo + (size_t)(b*Ss + k0)*Dd + h*HDd,
            Vhi + (size_t)(b*Ss + k0)*Dd + h*HDd, Vlo + (size_t)(b*Ss + k0)*Dd + h*HDd };
        const uint32_t base = stg(s);
        #pragma unroll
        for (int p = 0; p < 4; ++p)
            #pragma unroll
            for (int i = 0; i < 4; ++i) {
                int u = tid + i*256;
                int r = u >> 4, c = u & 15;
                uint32_t dst = base + p*FKPL + (uint32_t)r*256 + (c >> 3)*128
                             + ((((uint32_t)c & 7) ^ (r & 7)) << 4);
                cpa16(dst, srcs[p] + (size_t)r*Dd + c*8);
            }
        cpa_commit();
    };
    loadKV(0, 0);
    CPA_WAIT(1);
    __syncthreads();

    uint32_t qh[8][4], ql[8][4];
    #pragma unroll
    for (int kk = 0; kk < 8; ++kk) {
        int row = w*16 + (lane & 15);
        uint32_t c = kk*2 + (lane >> 4);
        uint32_t off = (uint32_t)row*256 + (c >> 3)*128 + (((c & 7) ^ (row & 7)) << 4);
        ldmx4(qh[kk], sbase + off);
        ldmx4(ql[kk], sbase + FQPL + off);
    }
    loadKV(1, 1);

    float oacc[16][4];
    #pragma unroll
    for (int nt = 0; nt < 16; ++nt)
        #pragma unroll
        for (int e = 0; e < 4; ++e) oacc[nt][e] = 0.f;
    float mrow[2] = {-1e30f, -1e30f};
    float lrow[2] = {0.f, 0.f};

    const int nkt = 2*(qt + 1);
    for (int kt = 0; kt < nkt; ++kt) {
        if (kt + 1 < nkt) { CPA_WAIT(1); } else { CPA_WAIT(0); }
        __syncthreads();
        if (kt + 2 < nkt) loadKV(kt + 2, (kt + 2) % 3);

        const int k0 = kt << 6;
        const bool active = (k0 <= q0 + w*16 + 15);
        if (active) {
        const uint32_t kb = stg(kt % 3);
        const uint32_t vb = kb + 2*FKPL;

        float sacc[8][4];
        #pragma unroll
        for (int nt = 0; nt < 8; ++nt)
            #pragma unroll
            for (int e = 0; e < 4; ++e) sacc[nt][e] = 0.f;
        #pragma unroll
        for (int kk = 0; kk < 8; ++kk) {
            #pragma unroll
            for (int np = 0; np < 4; ++np) {
                int nrow = np*16 + (lane >> 4)*8 + (lane & 7);
                uint32_t c = kk*2 + ((lane >> 3) & 1);
                uint32_t off = (uint32_t)nrow*256 + (c >> 3)*128 + (((c & 7) ^ (nrow & 7)) << 4);
                uint32_t tb[4], tl[4];
                ldmx4(tb, kb + off);
                ldmx4(tl, kb + FKPL + off);
                uint32_t b0[2] = {tb[0], tb[1]}, b1[2] = {tb[2], tb[3]};
                uint32_t l0[2] = {tl[0], tl[1]}, l1[2] = {tl[2], tl[3]};
                mma16816(sacc[2*np],     qh[kk], b0);
                mma16816(sacc[2*np],     qh[kk], l0);
                mma16816(sacc[2*np],     ql[kk], b0);
                mma16816(sacc[2*np + 1], qh[kk], b1);
                mma16816(sacc[2*np + 1], qh[kk], l1);
                mma16816(sacc[2*np + 1], ql[kk], b1);
            }
        }

        const bool needmask = (k0 + 63 > q0 + w*16);
        float corr[2];
        #pragma unroll
        for (int hh = 0; hh < 2; ++hh) {
            const int rowg = q0 + w*16 + (lane >> 2) + hh*8;
            float rmax = -1e30f;
            #pragma unroll
            for (int nt = 0; nt < 8; ++nt)
                #pragma unroll
                for (int e2 = 0; e2 < 2; ++e2) {
                    float v = sacc[nt][hh*2 + e2] * scale;
                    if (needmask) {
                        int colg = k0 + nt*8 + (lane & 3)*2 + e2;
                        if (colg > rowg) v = -1e30f;
                    }
                    sacc[nt][hh*2 + e2] = v;
                    rmax = fmaxf(rmax, v);
                }
            rmax = fmaxf(rmax, __shfl_xor_sync(0xffffffffu, rmax, 1));
            rmax = fmaxf(rmax, __shfl_xor_sync(0xffffffffu, rmax, 2));
            float mn = fmaxf(mrow[hh], rmax);
            corr[hh] = __expf(mrow[hh] - mn);
            float rs = 0.f;
            #pragma unroll
            for (int nt = 0; nt < 8; ++nt)
                #pragma unroll
                for (int e2 = 0; e2 < 2; ++e2) {
                    float p = __expf(sacc[nt][hh*2 + e2] - mn);
                    sacc[nt][hh*2 + e2] = p;
                    rs += p;
                }
            rs += __shfl_xor_sync(0xffffffffu, rs, 1);
            rs += __shfl_xor_sync(0xffffffffu, rs, 2);
            lrow[hh] = lrow[hh]*corr[hh] + rs;
            mrow[hh] = mn;
        }
        #pragma unroll
        for (int nt = 0; nt < 16; ++nt) {
            oacc[nt][0] *= corr[0]; oacc[nt][1] *= corr[0];
            oacc[nt][2] *= corr[1]; oacc[nt][3] *= corr[1];
        }

        #pragma unroll
        for (int kk4 = 0; kk4 < 4; ++kk4) {
            uint32_t ph[4], pl[4];
            #pragma unroll
            for (int part = 0; part < 4; ++part) {
                int tl2 = 2*kk4 + (part >> 1);
                int eh = part & 1;
                split2(sacc[tl2][eh*2], sacc[tl2][eh*2 + 1], ph[part], pl[part]);
            }
            const int mi = lane >> 3;
            const int krow = kk4*16 + (lane & 7) + (mi & 1)*8;
            #pragma unroll
            for (int np = 0; np < 8; ++np) {
                uint32_t c = np*2 + (mi >> 1);
                uint32_t off = (uint32_t)krow*256 + (c >> 3)*128 + (((c & 7) ^ (krow & 7)) << 4);
                uint32_t t[4], t2[4];
                ldmx4t(t,  vb + off);
                ldmx4t(t2, vb + FKPL + off);
                uint32_t bvh0[2] = {t[0],  t[1]},  bvh1[2] = {t[2],  t[3]};
                uint32_t bvl0[2] = {t2[0], t2[1]}, bvl1[2] = {t2[2], t2[3]};
                mma16816(oacc[2*np],     ph, bvh0);
                mma16816(oacc[2*np],     ph, bvl0);
                mma16816(oacc[2*np],     pl, bvh0);
                mma16816(oacc[2*np + 1], ph, bvh1);
                mma16816(oacc[2*np + 1], ph, bvl1);
                mma16816(oacc[2*np + 1], pl, bvh1);
            }
        }
        } // active
    }

    // normalize main attention
    {
        const float inv0 = 1.f / lrow[0];
        const float inv1 = 1.f / lrow[1];
        #pragma unroll
        for (int nt = 0; nt < 16; ++nt) {
            oacc[nt][0] *= inv0; oacc[nt][1] *= inv0;
            oacc[nt][2] *= inv1; oacc[nt][3] *= inv1;
        }
    }

    // ---- fused adapter cross-attention ----
    __syncthreads();   // all warps done reading KV stages
    for (int u = tid; u < 16*64; u += 256) {
        int r = u >> 6, cp = u & 63;          // cols 2cp, 2cp+1
        float f0=0.f, f1=0.f, g0=0.f, g1=0.f;
        if (r < ALa) {
            const float* akp_ = AK + ((size_t)(b*ALa + r))*Dd + h*HDd + 2*cp;
            const float* avp_ = AV + ((size_t)(b*ALa + r))*Dd + h*HDd + 2*cp;
            f0 = akp_[0]; f1 = akp_[1];
            g0 = avp_[0]; g1 = avp_[1];
        }
        uint32_t cu = (uint32_t)(cp >> 2);
        uint32_t intra = ((uint32_t)cp*4) & 15;
        uint32_t off = (uint32_t)r*256 + ((cu >> 3) << 7) + (((cu & 7) ^ (r & 7)) << 4) + intra;
        uint32_t hv, lv;
        split2(f0, f1, hv, lv);
        *(uint32_t*)(smf + off)         = hv;
        *(uint32_t*)(smf + 4096 + off)  = lv;
        split2(g0, g1, hv, lv);
        *(uint32_t*)(smf + 8192 + off)  = hv;
        *(uint32_t*)(smf + 12288 + off) = lv;
    }
    __syncthreads();

    // adapter scores: S_a (16q x 16k), K = HD = 128
    float sa[2][4];
    #pragma unroll
    for (int nt = 0; nt < 2; ++nt)
        #pragma unroll
        for (int e = 0; e < 4; ++e) sa[nt][e] = 0.f;
    #pragma unroll
    for (int kk = 0; kk < 8; ++kk) {
        int nrow = (lane >> 4)*8 + (lane & 7);
        uint32_t c = kk*2 + ((lane >> 3) & 1);
        uint32_t off = (uint32_t)nrow*256 + ((c >> 3) << 7) + (((c & 7) ^ (nrow & 7)) << 4);
        uint32_t tb[4], tl[4];
        ldmx4(tb, sbase + off);
        ldmx4(tl, sbase + 4096 + off);
        uint32_t b0[2] = {tb[0], tb[1]}, b1[2] = {tb[2], tb[3]};
        uint32_t l0[2] = {tl[0], tl[1]}, l1[2] = {tl[2], tl[3]};
        mma16816(sa[0], qh[kk], b0);
        mma16816(sa[0], qh[kk], l0);
        mma16816(sa[0], ql[kk], b0);
        mma16816(sa[1], qh[kk], b1);
        mma16816(sa[1], qh[kk], l1);
        mma16816(sa[1], ql[kk], b1);
    }
    {
        const float g = tanhf(gate[h]) * ngate[0];
        #pragma unroll
        for (int hh = 0; hh < 2; ++hh) {
            float rmax = -1e30f;
            #pragma unroll
            for (int nt = 0; nt < 2; ++nt)
                #pragma unroll
                for (int e2 = 0; e2 < 2; ++e2) {
                    int colg = nt*8 + (lane & 3)*2 + e2;
                    float v = sa[nt][hh*2 + e2] * scale;
                    if (colg >= ALa) v = -1e30f;
                    sa[nt][hh*2 + e2] = v;
                    rmax = fmaxf(rmax, v);
                }
            rmax = fmaxf(rmax, __shfl_xor_sync(0xffffffffu, rmax, 1));
            rmax = fmaxf(rmax, __shfl_xor_sync(0xffffffffu, rmax, 2));
            float rs = 0.f;
            #pragma unroll
            for (int nt = 0; nt < 2; ++nt)
                #pragma unroll
                for (int e2 = 0; e2 < 2; ++e2) {
                    float p = __expf(sa[nt][hh*2 + e2] - rmax);
                    sa[nt][hh*2 + e2] = p;
                    rs += p;
                }
            rs += __shfl_xor_sync(0xffffffffu, rs, 1);
            rs += __shfl_xor_sync(0xffffffffu, rs, 2);
            const float wgt = g / rs;
            #pragma unroll
            for (int nt = 0; nt < 2; ++nt)
                #pragma unroll
                for (int e2 = 0; e2 < 2; ++e2)
                    sa[nt][hh*2 + e2] *= wgt;
        }
    }
    {
        uint32_t ph[4], pl[4];
        #pragma unroll
        for (int part = 0; part < 4; ++part) {
            int tl2 = part >> 1;
            int eh = part & 1;
            split2(sa[tl2][eh*2], sa[tl2][eh*2 + 1], ph[part], pl[part]);
        }
        const int mi = lane >> 3;
        const int krow = (lane & 7) + (mi & 1)*8;
        #pragma unroll
        for (int np = 0; np < 8; ++np) {
            uint32_t c = np*2 + (mi >> 1);
            uint32_t off = (uint32_t)krow*256 + ((c >> 3) << 7) + (((c & 7) ^ (krow & 7)) << 4);
            uint32_t t[4], t2[4];
            ldmx4t(t,  sbase + 8192 + off);
            ldmx4t(t2, sbase + 12288 + off);
            uint32_t bvh0[2] = {t[0],  t[1]},  bvh1[2] = {t[2],  t[3]};
            uint32_t bvl0[2] = {t2[0], t2[1]}, bvl1[2] = {t2[2], t2[3]};
            mma16816(oacc[2*np],     ph, bvh0);
            mma16816(oacc[2*np],     ph, bvl0);
            mma16816(oacc[2*np],     pl, bvh0);
            mma16816(oacc[2*np + 1], ph, bvh1);
            mma16816(oacc[2*np + 1], ph, bvl1);
            mma16816(oacc[2*np + 1], pl, bvh1);
        }
    }

    // ---- store hi/lo planes (Wo GEMM A-operand layout, stride KP)
    const size_t r0 = (size_t)(b*Ss + q0 + w*16 + (lane >> 2));
    #pragma unroll
    for (int nt = 0; nt < 16; ++nt) {
        const int col = h*HDd + nt*8 + (lane & 3)*2;
        uint32_t hv, lv;
        split2(oacc[nt][0], oacc[nt][1], hv, lv);
        *(uint32_t*)(Ohi + r0*KP + col) = hv;
        *(uint32_t*)(Olo + r0*KP + col) = lv;
        split2(oacc[nt][2], oacc[nt][3], hv, lv);
        *(uint32_t*)(Ohi + (r0 + 8)*KP + col) = hv;
        *(uint32_t*)(Olo + (r0 + 8)*KP + col) = lv;
    }
}

// ---------------------------------------------------------------------------
// lora_part: partial T over k-range, X = fp32. grid (M/64, KSPL)
// ---------------------------------------------------------------------------
__global__ __launch_bounds__(256) void lora_part(
    const float* __restrict__ X,
    const float* __restrict__ L1a, const float* __restrict__ L1b, const float* __restrict__ L1c,
    float* __restrict__ Tp, int nmat, int ldt)
{
    __shared__ float Xs[32][68];
    __shared__ float Ls[32][52];
    const int tid = threadIdx.x;
    const int tx = tid & 15, ty = tid >> 4;
    const int m0 = blockIdx.x << 6;
    const int ks = blockIdx.y;
    const int Rtot = nmat << 4;
    float acc[4][3];
    #pragma unroll
    for (int i = 0; i < 4; ++i)
        #pragma unroll
        for (int j = 0; j < 3; ++j) acc[i][j] = 0.f;

    for (int k0 = ks*512; k0 < ks*512 + 512; k0 += 32) {
        __syncthreads();
        #pragma unroll
        for (int i = 0; i < 2; ++i) {
            int v = tid + i*256;
            int r = v >> 3, c = (v & 7) << 2;
            float4 x4 = *(const float4*)(X + (size_t)(m0 + r)*Dd + k0 + c);
            Xs[c+0][r]=x4.x; Xs[c+1][r]=x4.y; Xs[c+2][r]=x4.z; Xs[c+3][r]=x4.w;
        }
        for (int v = tid; v < Rtot*8; v += 256) {
            int r = v >> 3, c = (v & 7) << 2;
            const float* src = (r < 16) ? (L1a + (size_t)r*Dd)
                             : (r < 32) ? (L1b + (size_t)(r-16)*Dd)
                                        : (L1c + (size_t)(r-32)*Dd);
            float4 l4 = *(const float4*)(src + k0 + c);
            Ls[c+0][r]=l4.x; Ls[c+1][r]=l4.y; Ls[c+2][r]=l4.z; Ls[c+3][r]=l4.w;
        }
        __syncthreads();
        #pragma unroll
        for (int k = 0; k < 32; ++k) {
            float xv[4];
            #pragma unroll
            for (int i = 0; i < 4; ++i) xv[i] = Xs[k][4*ty + i];
            for (int j = 0; j < nmat; ++j) {
                float lv = Ls[k][tx + 16*j];
                #pragma unroll
                for (int i = 0; i < 4; ++i) acc[i][j] = fmaf(xv[i], lv, acc[i][j]);
            }
        }
    }
    float* out = Tp + (size_t)ks*MROWS*ldt;
    for (int j = 0; j < nmat; ++j)
        #pragma unroll
        for (int i = 0; i < 4; ++i)
            out[(size_t)(m0 + 4*ty + i)*ldt + tx + 16*j] = acc[i][j];
}

// ---------------------------------------------------------------------------
// lora_part_planes: X reconstructed from bf16 hi/lo planes (stride KP)
// ---------------------------------------------------------------------------
__global__ __launch_bounds__(256) void lora_part_planes(
    const __nv_bfloat16* __restrict__ Xhi, const __nv_bfloat16* __restrict__ Xlo,
    const float* __restrict__ L1a,
    float* __restrict__ Tp, int ldt)
{
    __shared__ float Xs[32][68];
    __shared__ float Ls[32][20];
    const int tid = threadIdx.x;
    const int tx = tid & 15, ty = tid >> 4;
    const int m0 = blockIdx.x << 6;
    const int ks = blockIdx.y;
    float acc[4];
    #pragma unroll
    for (int i = 0; i < 4; ++i) acc[i] = 0.f;

    for (int k0 = ks*512; k0 < ks*512 + 512; k0 += 32) {
        __syncthreads();
        #pragma unroll
        for (int i = 0; i < 2; ++i) {
            int v = tid + i*256;
            int r = v >> 3, c = (v & 7) << 2;
            uint2 hu = *(const uint2*)(Xhi + (size_t)(m0 + r)*KP + k0 + c);
            uint2 lu = *(const uint2*)(Xlo + (size_t)(m0 + r)*KP + k0 + c);
            __nv_bfloat162 h0 = *(__nv_bfloat162*)&hu.x;
            __nv_bfloat162 h1 = *(__nv_bfloat162*)&hu.y;
            __nv_bfloat162 l0 = *(__nv_bfloat162*)&lu.x;
            __nv_bfloat162 l1 = *(__nv_bfloat162*)&lu.y;
            Xs[c+0][r] = __bfloat162float(h0.x) + __bfloat162float(l0.x);
            Xs[c+1][r] = __bfloat162float(h0.y) + __bfloat162float(l0.y);
            Xs[c+2][r] = __bfloat162float(h1.x) + __bfloat162float(l1.x);
            Xs[c+3][r] = __bfloat162float(h1.y) + __bfloat162float(l1.y);
        }
        for (int v = tid; v < 128; v += 256) {
            int r = v >> 3, c = (v & 7) << 2;
            float4 l4 = *(const float4*)(L1a + (size_t)r*Dd + k0 + c);
            Ls[c+0][r]=l4.x; Ls[c+1][r]=l4.y; Ls[c+2][r]=l4.z; Ls[c+3][r]=l4.w;
        }
        __syncthreads();
        #pragma unroll
        for (int k = 0; k < 32; ++k) {
            float lv = Ls[k][tx];
            #pragma unroll
            for (int i = 0; i < 4; ++i) acc[i] = fmaf(Xs[k][4*ty + i], lv, acc[i]);
        }
    }
    float* out = Tp + (size_t)ks*MROWS*ldt;
    #pragma unroll
    for (int i = 0; i < 4; ++i)
        out[(size_t)(m0 + 4*ty + i)*ldt + tx] = acc[i];
}

// ---------------------------------------------------------------------------
// adapter_part: partial AK/AV over k-range. grid (Dd/64, KSPL)
// ---------------------------------------------------------------------------
__global__ __launch_bounds__(256) void adapter_part(
    const float* __restrict__ Ad, const float* __restrict__ Wk, const float* __restrict__ Wv,
    float* __restrict__ AKp, float* __restrict__ AVp)
{
    __shared__ float Ads[20][68];
    __shared__ float Wks[64][65];
    __shared__ float Wvs[64][65];
    const int tid = threadIdx.x;
    const int nl = tid & 63, mg = tid >> 6;
    const int n0 = blockIdx.x << 6;
    const int ks = blockIdx.y;
    float ak[5] = {0,0,0,0,0}, av[5] = {0,0,0,0,0};

    for (int k0 = ks*512; k0 < ks*512 + 512; k0 += 64) {
        __syncthreads();
        for (int v = tid; v < 320; v += 256) {
            int r = v >> 4, c = (v & 15) << 2;
            float4 a4 = *(const float4*)(Ad + (size_t)r*Dd + k0 + c);
            Ads[r][c+0]=a4.x; Ads[r][c+1]=a4.y; Ads[r][c+2]=a4.z; Ads[r][c+3]=a4.w;
        }
        #pragma unroll
        for (int i = 0; i < 4; ++i) {
            int v = tid + i*256;
            int r = v >> 4, c = (v & 15) << 2;
            float4 w4 = *(const float4*)(Wk + (size_t)(n0 + r)*Dd + k0 + c);
            Wks[c+0][r]=w4.x; Wks[c+1][r]=w4.y; Wks[c+2][r]=w4.z; Wks[c+3][r]=w4.w;
            float4 w5 = *(const float4*)(Wv + (size_t)(n0 + r)*Dd + k0 + c);
            Wvs[c+0][r]=w5.x; Wvs[c+1][r]=w5.y; Wvs[c+2][r]=w5.z; Wvs[c+3][r]=w5.w;
        }
        __syncthreads();
        #pragma unroll
        for (int k = 0; k < 64; ++k) {
            float wkv = Wks[k][nl];
            float wvv = Wvs[k][nl];
            #pragma unroll
            for (int i = 0; i < 5; ++i) {
                float a = Ads[5*mg + i][k];
                ak[i] = fmaf(a, wkv, ak[i]);
                av[i] = fmaf(a, wvv, av[i]);
            }
        }
    }
    float* akp = AKp + (size_t)ks*20*Dd;
    float* avp = AVp + (size_t)ks*20*Dd;
    #pragma unroll
    for (int i = 0; i < 5; ++i) {
        akp[(size_t)(5*mg + i)*Dd + n0 + nl] = ak[i];
        avp[(size_t)(5*mg + i)*Dd + n0 + nl] = av[i];
    }
}

// ---------------------------------------------------------------------------
// Launch.  Order arranged so launch #6 (1-based) is gemm_bf -> ncu -s 5 -c 1
// captures the GEMM next round.
// ---------------------------------------------------------------------------
extern "C" void kernel_launch(void* const* d_in, const int* in_sizes, int n_in,
                              void* d_out, int out_size)
{
    (void)in_sizes; (void)n_in; (void)out_size;
    const float* x       = (const float*)d_in[0];
    const float* adapter = (const float*)d_in[4];
    const float* wq  = (const float*)d_in[5];
    const float* wk  = (const float*)d_in[6];
    const float* wv  = (const float*)d_in[7];
    const float* wo  = (const float*)d_in[8];
    const float* lq1 = (const float*)d_in[9];
    const float* lq2 = (const float*)d_in[10];
    const float* lk1 = (const float*)d_in[11];
    const float* lk2 = (const float*)d_in[12];
    const float* lv1 = (const float*)d_in[13];
    const float* lv2 = (const float*)d_in[14];
    const float* lo1 = (const float*)d_in[15];
    const float* lo2 = (const float*)d_in[16];
    const float* gate  = (const float*)d_in[17];
    const float* ngate = (const float*)d_in[18];
    float* out = (float*)d_out;

    float *T, *Tp, *ak, *av, *akp, *avp;
    __nv_bfloat16 *cvAhi, *cvAlo, *cvB1hi, *cvB1lo, *cvB2hi, *cvB2lo;
    __nv_bfloat16 *qhi, *qlo, *khi, *klo, *vhi, *vlo;
    cudaGetSymbolAddress((void**)&T,    g_T);
    cudaGetSymbolAddress((void**)&Tp,   g_Tp);
    cudaGetSymbolAddress((void**)&ak,   g_ak);
    cudaGetSymbolAddress((void**)&av,   g_av);
    cudaGetSymbolAddress((void**)&akp,  g_akp);
    cudaGetSymbolAddress((void**)&avp,  g_avp);
    cudaGetSymbolAddress((void**)&cvAhi, g_cvAhi);
    cudaGetSymbolAddress((void**)&cvAlo, g_cvAlo);
    cudaGetSymbolAddress((void**)&cvB1hi, g_cvB1hi);
    cudaGetSymbolAddress((void**)&cvB1lo, g_cvB1lo);
    cudaGetSymbolAddress((void**)&cvB2hi, g_cvB2hi);
    cudaGetSymbolAddress((void**)&cvB2lo, g_cvB2lo);
    cudaGetSymbolAddress((void**)&qhi,  g_qhi);
    cudaGetSymbolAddress((void**)&qlo,  g_qlo);
    cudaGetSymbolAddress((void**)&khi,  g_khi);
    cudaGetSymbolAddress((void**)&klo,  g_klo);
    cudaGetSymbolAddress((void**)&vhi,  g_vhi);
    cudaGetSymbolAddress((void**)&vlo,  g_vlo);

    cudaFuncSetAttribute(gemm_bf,     cudaFuncAttributeMaxDynamicSharedMemorySize, GEMM_SMEM);
    cudaFuncSetAttribute(flash_fused, cudaFuncAttributeMaxDynamicSharedMemorySize, FLASH_SMEM);

    const dim3 gGrid(Dd/128, MROWS/128);
    const int convBlocks = MROWS*520/256;

    // #1 LoRA intermediates (q/k/v), k-split
    lora_part<<<dim3(MROWS/64, KSPL), 256>>>(x, lq1, lk1, lv1, Tp, 3, 48);
    // #2
    reduce8<<<MROWS*48/256, 256>>>(T, Tp, MROWS*48);
    // #3 convert A = [x | T(48) | 0]
    conv_split<<<convBlocks, 256>>>(x, T, 48, 48, 0, cvAhi, cvAlo);
    // #4, #5 convert wq -> B1, wk -> B2
    conv_split<<<convBlocks, 256>>>(wq, lq2, 16, 16, 0,  cvB1hi, cvB1lo);
    conv_split<<<convBlocks, 256>>>(wk, lk2, 16, 16, 16, cvB2hi, cvB2lo);
    // #6 gemm_q  (ncu -s 5 -c 1 captures this launch)
    gemm_bf<<<gGrid, 256, GEMM_SMEM>>>(cvAhi, cvAlo, cvB1hi, cvB1lo, nullptr, qhi, qlo);
    // #7 gemm_k
    gemm_bf<<<gGrid, 256, GEMM_SMEM>>>(cvAhi, cvAlo, cvB2hi, cvB2lo, nullptr, khi, klo);
    // #8, #9 convert wv -> B1, gemm_v
    conv_split<<<convBlocks, 256>>>(wv, lv2, 16, 16, 32, cvB1hi, cvB1lo);
    gemm_bf<<<gGrid, 256, GEMM_SMEM>>>(cvAhi, cvAlo, cvB1hi, cvB1lo, nullptr, vhi, vlo);
    // adapter K/V projection, k-split
    adapter_part<<<dim3(Dd/64, KSPL), 256>>>(adapter, wk, wv, akp, avp);
    reduce8<<<20*Dd/256, 256>>>(ak, akp, 20*Dd);
    reduce8<<<20*Dd/256, 256>>>(av, avp, 20*Dd);
    // flash attention + fused adapter -> cvA planes
    flash_fused<<<dim3(Ss/128, Hh, Bb), 256, FLASH_SMEM>>>(
        qhi, qlo, khi, klo, vhi, vlo, ak, av, gate, ngate, cvAhi, cvAlo);
    // output LoRA chunk into cvA cols [4096,4160)
    lora_part_planes<<<dim3(MROWS/64, KSPL), 256>>>(cvAhi, cvAlo, lo1, Tp, 16);
    reduce_fill<<<MROWS*64/256, 256>>>(Tp, cvAhi, cvAlo);
    // output projection
    conv_split<<<convBlocks, 256>>>(wo, lo2, 16, 16, 0, cvB2hi, cvB2lo);
    gemm_bf<<<gGrid, 256, GEMM_SMEM>>>(cvAhi, cvAlo, cvB2hi, cvB2lo, out, nullptr, nullptr);
}

// round 12
// speedup vs baseline: 5.3659x; 1.2656x over previous
#include <cuda_runtime.h>
#include <cuda_fp16.h>
#include <math.h>
#include <stdint.h>

// Problem constants
#define Bb   2
#define Ss   2048
#define Dd   4096
#define Hh   32
#define HDd  128
#define ALa  10
#define MROWS (Bb*Ss)          // 4096
#define KP   4160              // 4096 + 64 (LoRA chunk)
#define NCH  65                // K'/64
#define KSPL 8                 // k-split for small gemms

// ---------------------------------------------------------------------------
// Scratch (device globals; no cudaMalloc allowed)
// ---------------------------------------------------------------------------
__device__ float g_T  [MROWS*48];
__device__ float g_Tp [KSPL*MROWS*48];
__device__ float g_ak [Bb*ALa*Dd];
__device__ float g_av [Bb*ALa*Dd];
__device__ float g_akp[KSPL*Bb*ALa*Dd];
__device__ float g_avp[KSPL*Bb*ALa*Dd];
__device__ __half g_cvAhi[MROWS*KP];
__device__ __half g_cvAlo[MROWS*KP];
__device__ __half g_cvB1hi[Dd*KP];
__device__ __half g_cvB2hi[Dd*KP];
__device__ __half g_qhi[MROWS*Dd];
__device__ __half g_qlo[MROWS*Dd];
__device__ __half g_khi[MROWS*Dd];
__device__ __half g_klo[MROWS*Dd];
__device__ __half g_vhi[MROWS*Dd];
__device__ __half g_vlo[MROWS*Dd];

// ---------------------------------------------------------------------------
// helpers
// ---------------------------------------------------------------------------
__device__ __forceinline__ uint32_t smem_u32(const void* p) {
    uint32_t a;
    asm("{ .reg .u64 t; cvta.to.shared.u64 t, %1; cvt.u32.u64 %0, t; }" : "=r"(a) : "l"(p));
    return a;
}
__device__ __forceinline__ void cpa16(uint32_t dst, const void* src) {
    asm volatile("cp.async.cg.shared.global [%0], [%1], 16;" :: "r"(dst), "l"(src));
}
__device__ __forceinline__ void cpa_commit() { asm volatile("cp.async.commit_group;"); }
#define CPA_WAIT(N) asm volatile("cp.async.wait_group %0;" :: "n"(N))
__device__ __forceinline__ void ldmx4(uint32_t* r, uint32_t addr) {
    asm volatile("ldmatrix.sync.aligned.m8n8.x4.shared.b16 {%0,%1,%2,%3}, [%4];"
                 : "=r"(r[0]), "=r"(r[1]), "=r"(r[2]), "=r"(r[3]) : "r"(addr));
}
__device__ __forceinline__ void ldmx4t(uint32_t* r, uint32_t addr) {
    asm volatile("ldmatrix.sync.aligned.m8n8.x4.trans.shared.b16 {%0,%1,%2,%3}, [%4];"
                 : "=r"(r[0]), "=r"(r[1]), "=r"(r[2]), "=r"(r[3]) : "r"(addr));
}
// fp16 mma with fp32 accumulate
__device__ __forceinline__ void mma16816(float* c, const uint32_t* a, const uint32_t* b) {
    asm volatile(
        "mma.sync.aligned.m16n8k16.row.col.f32.f16.f16.f32 "
        "{%0,%1,%2,%3}, {%4,%5,%6,%7}, {%8,%9}, {%0,%1,%2,%3};"
        : "+f"(c[0]), "+f"(c[1]), "+f"(c[2]), "+f"(c[3])
        : "r"(a[0]), "r"(a[1]), "r"(a[2]), "r"(a[3]), "r"(b[0]), "r"(b[1]));
}
// pack 2 fp32 -> fp16x2 (hi) and residual fp16x2 (lo)
__device__ __forceinline__ void split2(float f0, float f1, uint32_t& hi, uint32_t& lo) {
    __half h0 = __float2half_rn(f0);
    __half h1 = __float2half_rn(f1);
    __half l0 = __float2half_rn(f0 - __half2float(h0));
    __half l1 = __float2half_rn(f1 - __half2float(h1));
    __half2 ph = __halves2half2(h0, h1);
    __half2 pl = __halves2half2(l0, l1);
    hi = *(uint32_t*)&ph;
    lo = *(uint32_t*)&pl;
}

// ---------------------------------------------------------------------------
// conv_split: dst[M x KP] (hi/lo fp16) = [src(Mx4096) | lora block | zeros]
// ---------------------------------------------------------------------------
__global__ __launch_bounds__(256) void conv_split(
    const float* __restrict__ src,
    const float* __restrict__ lsrc, int ldl, int lcols, int lshift,
    __half* __restrict__ dhi, __half* __restrict__ dlo)
{
    const int u = blockIdx.x * 256 + threadIdx.x;
    const int r = u / 520, g = u % 520;
    float f[8];
    if (g < 512) {
        float4 a = *(const float4*)(src + (size_t)r*4096 + g*8);
        float4 b = *(const float4*)(src + (size_t)r*4096 + g*8 + 4);
        f[0]=a.x; f[1]=a.y; f[2]=a.z; f[3]=a.w; f[4]=b.x; f[5]=b.y; f[6]=b.z; f[7]=b.w;
    } else {
        #pragma unroll
        for (int i = 0; i < 8; ++i) {
            int e = g*8 - 4096 + i;
            int lc = e - lshift;
            f[i] = (lc >= 0 && lc < lcols) ? lsrc[(size_t)r*ldl + lc] : 0.f;
        }
    }
    uint32_t h[4], l[4];
    #pragma unroll
    for (int e = 0; e < 4; ++e) split2(f[2*e], f[2*e+1], h[e], l[e]);
    *(uint4*)(dhi + (size_t)r*KP + g*8) = make_uint4(h[0], h[1], h[2], h[3]);
    if (dlo)
        *(uint4*)(dlo + (size_t)r*KP + g*8) = make_uint4(l[0], l[1], l[2], l[3]);
}

// ---------------------------------------------------------------------------
// reduce8: dst[i] = sum_{s<8} src[s*len + i]
// ---------------------------------------------------------------------------
__global__ __launch_bounds__(256) void reduce8(
    float* __restrict__ dst, const float* __restrict__ src, int len)
{
    const int i = blockIdx.x*256 + threadIdx.x;
    float s = 0.f;
    #pragma unroll
    for (int k = 0; k < KSPL; ++k) s += src[(size_t)k*len + i];
    dst[i] = s;
}

// ---------------------------------------------------------------------------
// reduce_fill: To = sum8 Tp; write split into cvA cols [4096, 4160)
// ---------------------------------------------------------------------------
__global__ __launch_bounds__(256) void reduce_fill(
    const float* __restrict__ Tp,
    __half* __restrict__ dhi, __half* __restrict__ dlo)
{
    const int u = blockIdx.x*256 + threadIdx.x;
    const int r = u >> 6, c = u & 63;
    float s = 0.f;
    if (c < 16) {
        #pragma unroll
        for (int k = 0; k < KSPL; ++k) s += Tp[(size_t)k*MROWS*16 + r*16 + c];
    }
    __half h = __float2half_rn(s);
    __half l = __float2half_rn(s - __half2float(h));
    dhi[(size_t)r*KP + 4096 + c] = h;
    dlo[(size_t)r*KP + 4096 + c] = l;
}

// ---------------------------------------------------------------------------
// fp16 2-pass mma GEMM: C = (Ahi+Alo) * Bhi^T.  A split fp16 (err 2^-22),
// B single fp16 (err 2^-11 -> ~2.8e-4 rel per GEMM).  256 threads, 8 warps,
// 32x64 warp tiles, 3-plane smem stage (Ahi,Alo,Bhi), 3-stage cp.async ring.
// ---------------------------------------------------------------------------
#define GPLANE 16384
#define GSTGB  (3*GPLANE)     // 49152
#define GEMM_SMEM (3*GSTGB)   // 147456

__global__ __launch_bounds__(256, 1) void gemm_fp16(
    const __half* __restrict__ Ahi, const __half* __restrict__ Alo,
    const __half* __restrict__ Bhi,
    float* __restrict__ C, __half* __restrict__ Chi, __half* __restrict__ Clo)
{
    extern __shared__ char smg[];
    const int tid = threadIdx.x;
    const int lane = tid & 31, wid = tid >> 5;
    const int wm = wid & 3, wn = wid >> 2;    // 4 x 2 warp grid, 32x64 tiles
    const int m0 = blockIdx.y << 7;
    const int n0 = blockIdx.x << 7;
    const uint32_t sbase = smem_u32(smg);

    float acc[2][8][4];
    #pragma unroll
    for (int mt = 0; mt < 2; ++mt)
        #pragma unroll
        for (int nt = 0; nt < 8; ++nt)
            #pragma unroll
            for (int e = 0; e < 4; ++e) acc[mt][nt][e] = 0.f;

    auto load_st = [&](int kt, int s) {
        const __half* srcs[3] = {
            Ahi + (size_t)m0*KP + kt*64, Alo + (size_t)m0*KP + kt*64,
            Bhi + (size_t)n0*KP + kt*64 };
        const uint32_t base = sbase + s*GSTGB;
        #pragma unroll
        for (int p = 0; p < 3; ++p) {
            #pragma unroll
            for (int i = 0; i < 4; ++i) {
                int u = tid + i*256;
                int r = u >> 3, c = u & 7;
                cpa16(base + p*GPLANE + r*128 + (((uint32_t)c ^ (r & 7)) << 4),
                      srcs[p] + (size_t)r*KP + c*8);
            }
        }
        cpa_commit();
    };

    load_st(0, 0);
    load_st(1, 1);

    for (int kt = 0; kt < NCH; ++kt) {
        const int s = kt % 3;
        CPA_WAIT(1);
        __syncthreads();

        const uint32_t aAhi = sbase + s*GSTGB;
        const uint32_t aAlo = aAhi + GPLANE;
        const uint32_t aBhi = aAhi + 2*GPLANE;
        #pragma unroll
        for (int kk = 0; kk < 4; ++kk) {
            uint32_t ah[2][4], al[2][4];
            #pragma unroll
            for (int mt = 0; mt < 2; ++mt) {
                int row = wm*32 + mt*16 + (lane & 15);
                uint32_t c = kk*2 + (lane >> 4);
                uint32_t off = (uint32_t)row*128 + ((c ^ (row & 7)) << 4);
                ldmx4(ah[mt], aAhi + off);
                ldmx4(al[mt], aAlo + off);
            }
            uint32_t bh[8][2];
            #pragma unroll
            for (int np = 0; np < 4; ++np) {
                int nrow = wn*64 + np*16 + (lane >> 4)*8 + (lane & 7);
                uint32_t c = kk*2 + ((lane >> 3) & 1);
                uint32_t off = (uint32_t)nrow*128 + ((c ^ (nrow & 7)) << 4);
                uint32_t t[4];
                ldmx4(t, aBhi + off);
                bh[2*np][0]=t[0]; bh[2*np][1]=t[1]; bh[2*np+1][0]=t[2]; bh[2*np+1][1]=t[3];
            }
            #pragma unroll
            for (int mt = 0; mt < 2; ++mt)
                #pragma unroll
                for (int nt = 0; nt < 8; ++nt) {
                    mma16816(acc[mt][nt], ah[mt], bh[nt]);
                    mma16816(acc[mt][nt], al[mt], bh[nt]);
                }
        }
        if (kt + 2 < NCH) load_st(kt + 2, (kt + 2) % 3);
    }

    #pragma unroll
    for (int mt = 0; mt < 2; ++mt) {
        const int row = m0 + wm*32 + mt*16 + (lane >> 2);
        #pragma unroll
        for (int nt = 0; nt < 8; ++nt) {
            const int col = n0 + wn*64 + nt*8 + (lane & 3)*2;
            if (C) {
                *(float2*)(C + (size_t)row*Dd + col)       = make_float2(acc[mt][nt][0], acc[mt][nt][1]);
                *(float2*)(C + (size_t)(row + 8)*Dd + col) = make_float2(acc[mt][nt][2], acc[mt][nt][3]);
            }
            if (Chi) {
                uint32_t h, l;
                split2(acc[mt][nt][0], acc[mt][nt][1], h, l);
                *(uint32_t*)(Chi + (size_t)row*Dd + col) = h;
                *(uint32_t*)(Clo + (size_t)row*Dd + col) = l;
                split2(acc[mt][nt][2], acc[mt][nt][3], h, l);
                *(uint32_t*)(Chi + (size_t)(row + 8)*Dd + col) = h;
                *(uint32_t*)(Clo + (size_t)(row + 8)*Dd + col) = l;
            }
        }
    }
}

// ---------------------------------------------------------------------------
// Flash attention + fused gated adapter cross-attention, fp16 3-pass.
// CTA: 128 q x 64 kv, 8 warps. Q frags hoisted; 3-stage KV ring (stage2 = Q smem).
// Output written as fp16 hi/lo planes at stride KP (Wo GEMM A-operand layout).
// ---------------------------------------------------------------------------
#define FQPL 32768
#define FKPL 16384
#define FKVSTG (4*FKPL)
#define FLASH_SMEM (2*FQPL + 2*FKVSTG)   // 196608

__global__ __launch_bounds__(256, 1) void flash_fused(
    const __half* __restrict__ Qhi, const __half* __restrict__ Qlo,
    const __half* __restrict__ Khi, const __half* __restrict__ Klo,
    const __half* __restrict__ Vhi, const __half* __restrict__ Vlo,
    const float* __restrict__ AK, const float* __restrict__ AV,
    const float* __restrict__ gate, const float* __restrict__ ngate,
    __half* __restrict__ Ohi, __half* __restrict__ Olo)
{
    extern __shared__ char smf[];
    const int tid = threadIdx.x;
    const int lane = tid & 31, w = tid >> 5;
    const int qt = (int)gridDim.x - 1 - (int)blockIdx.x;    // LPT: heavy first
    const int h = blockIdx.y, b = blockIdx.z;
    const int q0 = qt << 7;
    const uint32_t sbase = smem_u32(smf);
    const float scale = 0.08838834764831845f;

    // Q load (group 0)
    {
        const __half* srcs[2] = {
            Qhi + (size_t)(b*Ss + q0)*Dd + h*HDd,
            Qlo + (size_t)(b*Ss + q0)*Dd + h*HDd };
        #pragma unroll
        for (int p = 0; p < 2; ++p)
            #pragma unroll
            for (int i = 0; i < 8; ++i) {
                int u = tid + i*256;
                int r = u >> 4, c = u & 15;
                uint32_t dst = sbase + p*FQPL + (uint32_t)r*256 + (c >> 3)*128
                             + ((((uint32_t)c & 7) ^ (r & 7)) << 4);
                cpa16(dst, srcs[p] + (size_t)r*Dd + c*8);
            }
        cpa_commit();
    }
    auto stg = [&](int s) -> uint32_t {
        return (s == 2) ? sbase : (sbase + 2*FQPL + s*FKVSTG);
    };
    auto loadKV = [&](int kt, int s) {
        const int k0 = kt << 6;
        const __half* srcs[4] = {
            Khi + (size_t)(b*Ss + k0)*Dd + h*HDd, Klo + (size_t)(b*Ss + k0)*Dd + h*HDd,
            Vhi + (size_t)(b*Ss + k0)*Dd + h*HDd, Vlo + (size_t)(b*Ss + k0)*Dd + h*HDd };
        const uint32_t base = stg(s);
        #pragma unroll
        for (int p = 0; p < 4; ++p)
            #pragma unroll
            for (int i = 0; i < 4; ++i) {
                int u = tid + i*256;
                int r = u >> 4, c = u & 15;
                uint32_t dst = base + p*FKPL + (uint32_t)r*256 + (c >> 3)*128
                             + ((((uint32_t)c & 7) ^ (r & 7)) << 4);
                cpa16(dst, srcs[p] + (size_t)r*Dd + c*8);
            }
        cpa_commit();
    };
    loadKV(0, 0);
    CPA_WAIT(1);
    __syncthreads();

    uint32_t qh[8][4], ql[8][4];
    #pragma unroll
    for (int kk = 0; kk < 8; ++kk) {
        int row = w*16 + (lane & 15);
        uint32_t c = kk*2 + (lane >> 4);
        uint32_t off = (uint32_t)row*256 + (c >> 3)*128 + (((c & 7) ^ (row & 7)) << 4);
        ldmx4(qh[kk], sbase + off);
        ldmx4(ql[kk], sbase + FQPL + off);
    }
    loadKV(1, 1);

    float oacc[16][4];
    #pragma unroll
    for (int nt = 0; nt < 16; ++nt)
        #pragma unroll
        for (int e = 0; e < 4; ++e) oacc[nt][e] = 0.f;
    float mrow[2] = {-1e30f, -1e30f};
    float lrow[2] = {0.f, 0.f};

    const int nkt = 2*(qt + 1);
    for (int kt = 0; kt < nkt; ++kt) {
        if (kt + 1 < nkt) { CPA_WAIT(1); } else { CPA_WAIT(0); }
        __syncthreads();
        if (kt + 2 < nkt) loadKV(kt + 2, (kt + 2) % 3);

        const int k0 = kt << 6;
        const bool active = (k0 <= q0 + w*16 + 15);
        if (active) {
        const uint32_t kb = stg(kt % 3);
        const uint32_t vb = kb + 2*FKPL;

        float sacc[8][4];
        #pragma unroll
        for (int nt = 0; nt < 8; ++nt)
            #pragma unroll
            for (int e = 0; e < 4; ++e) sacc[nt][e] = 0.f;
        #pragma unroll
        for (int kk = 0; kk < 8; ++kk) {
            #pragma unroll
            for (int np = 0; np < 4; ++np) {
                int nrow = np*16 + (lane >> 4)*8 + (lane & 7);
                uint32_t c = kk*2 + ((lane >> 3) & 1);
                uint32_t off = (uint32_t)nrow*256 + (c >> 3)*128 + (((c & 7) ^ (nrow & 7)) << 4);
                uint32_t tb[4], tl[4];
                ldmx4(tb, kb + off);
                ldmx4(tl, kb + FKPL + off);
                uint32_t b0[2] = {tb[0], tb[1]}, b1[2] = {tb[2], tb[3]};
                uint32_t l0[2] = {tl[0], tl[1]}, l1[2] = {tl[2], tl[3]};
                mma16816(sacc[2*np],     qh[kk], b0);
                mma16816(sacc[2*np],     qh[kk], l0);
                mma16816(sacc[2*np],     ql[kk], b0);
                mma16816(sacc[2*np + 1], qh[kk], b1);
                mma16816(sacc[2*np + 1], qh[kk], l1);
                mma16816(sacc[2*np + 1], ql[kk], b1);
            }
        }

        const bool needmask = (k0 + 63 > q0 + w*16);
        float corr[2];
        #pragma unroll
        for (int hh = 0; hh < 2; ++hh) {
            const int rowg = q0 + w*16 + (lane >> 2) + hh*8;
            float rmax = -1e30f;
            #pragma unroll
            for (int nt = 0; nt < 8; ++nt)
                #pragma unroll
                for (int e2 = 0; e2 < 2; ++e2) {
                    float v = sacc[nt][hh*2 + e2] * scale;
                    if (needmask) {
                        int colg = k0 + nt*8 + (lane & 3)*2 + e2;
                        if (colg > rowg) v = -1e30f;
                    }
                    sacc[nt][hh*2 + e2] = v;
                    rmax = fmaxf(rmax, v);
                }
            rmax = fmaxf(rmax, __shfl_xor_sync(0xffffffffu, rmax, 1));
            rmax = fmaxf(rmax, __shfl_xor_sync(0xffffffffu, rmax, 2));
            float mn = fmaxf(mrow[hh], rmax);
            corr[hh] = __expf(mrow[hh] - mn);
            float rs = 0.f;
            #pragma unroll
            for (int nt = 0; nt < 8; ++nt)
                #pragma unroll
                for (int e2 = 0; e2 < 2; ++e2) {
                    float p = __expf(sacc[nt][hh*2 + e2] - mn);
                    sacc[nt][hh*2 + e2] = p;
                    rs += p;
                }
            rs += __shfl_xor_sync(0xffffffffu, rs, 1);
            rs += __shfl_xor_sync(0xffffffffu, rs, 2);
            lrow[hh] = lrow[hh]*corr[hh] + rs;
            mrow[hh] = mn;
        }
        #pragma unroll
        for (int nt = 0; nt < 16; ++nt) {
            oacc[nt][0] *= corr[0]; oacc[nt][1] *= corr[0];
            oacc[nt][2] *= corr[1]; oacc[nt][3] *= corr[1];
        }

        #pragma unroll
        for (int kk4 = 0; kk4 < 4; ++kk4) {
            uint32_t ph[4], pl[4];
            #pragma unroll
            for (int part = 0; part < 4; ++part) {
                int tl2 = 2*kk4 + (part >> 1);
                int eh = part & 1;
                split2(sacc[tl2][eh*2], sacc[tl2][eh*2 + 1], ph[part], pl[part]);
            }
            const int mi = lane >> 3;
            const int krow = kk4*16 + (lane & 7) + (mi & 1)*8;
            #pragma unroll
            for (int np = 0; np < 8; ++np) {
                uint32_t c = np*2 + (mi >> 1);
                uint32_t off = (uint32_t)krow*256 + (c >> 3)*128 + (((c & 7) ^ (krow & 7)) << 4);
                uint32_t t[4], t2[4];
                ldmx4t(t,  vb + off);
                ldmx4t(t2, vb + FKPL + off);
                uint32_t bvh0[2] = {t[0],  t[1]},  bvh1[2] = {t[2],  t[3]};
                uint32_t bvl0[2] = {t2[0], t2[1]}, bvl1[2] = {t2[2], t2[3]};
                mma16816(oacc[2*np],     ph, bvh0);
                mma16816(oacc[2*np],     ph, bvl0);
                mma16816(oacc[2*np],     pl, bvh0);
                mma16816(oacc[2*np + 1], ph, bvh1);
                mma16816(oacc[2*np + 1], ph, bvl1);
                mma16816(oacc[2*np + 1], pl, bvh1);
            }
        }
        } // active
    }

    // normalize main attention
    {
        const float inv0 = 1.f / lrow[0];
        const float inv1 = 1.f / lrow[1];
        #pragma unroll
        for (int nt = 0; nt < 16; ++nt) {
            oacc[nt][0] *= inv0; oacc[nt][1] *= inv0;
            oacc[nt][2] *= inv1; oacc[nt][3] *= inv1;
        }
    }

    // ---- fused adapter cross-attention ----
    __syncthreads();   // all warps done reading KV stages
    for (int u = tid; u < 16*64; u += 256) {
        int r = u >> 6, cp = u & 63;          // cols 2cp, 2cp+1
        float f0=0.f, f1=0.f, g0=0.f, g1=0.f;
        if (r < ALa) {
            const float* akp_ = AK + ((size_t)(b*ALa + r))*Dd + h*HDd + 2*cp;
            const float* avp_ = AV + ((size_t)(b*ALa + r))*Dd + h*HDd + 2*cp;
            f0 = akp_[0]; f1 = akp_[1];
            g0 = avp_[0]; g1 = avp_[1];
        }
        uint32_t cu = (uint32_t)(cp >> 2);
        uint32_t intra = ((uint32_t)cp*4) & 15;
        uint32_t off = (uint32_t)r*256 + ((cu >> 3) << 7) + (((cu & 7) ^ (r & 7)) << 4) + intra;
        uint32_t hv, lv;
        split2(f0, f1, hv, lv);
        *(uint32_t*)(smf + off)         = hv;
        *(uint32_t*)(smf + 4096 + off)  = lv;
        split2(g0, g1, hv, lv);
        *(uint32_t*)(smf + 8192 + off)  = hv;
        *(uint32_t*)(smf + 12288 + off) = lv;
    }
    __syncthreads();

    // adapter scores: S_a (16q x 16k), K = HD = 128
    float sa[2][4];
    #pragma unroll
    for (int nt = 0; nt < 2; ++nt)
        #pragma unroll
        for (int e = 0; e < 4; ++e) sa[nt][e] = 0.f;
    #pragma unroll
    for (int kk = 0; kk < 8; ++kk) {
        int nrow = (lane >> 4)*8 + (lane & 7);
        uint32_t c = kk*2 + ((lane >> 3) & 1);
        uint32_t off = (uint32_t)nrow*256 + ((c >> 3) << 7) + (((c & 7) ^ (nrow & 7)) << 4);
        uint32_t tb[4], tl[4];
        ldmx4(tb, sbase + off);
        ldmx4(tl, sbase + 4096 + off);
        uint32_t b0[2] = {tb[0], tb[1]}, b1[2] = {tb[2], tb[3]};
        uint32_t l0[2] = {tl[0], tl[1]}, l1[2] = {tl[2], tl[3]};
        mma16816(sa[0], qh[kk], b0);
        mma16816(sa[0], qh[kk], l0);
        mma16816(sa[0], ql[kk], b0);
        mma16816(sa[1], qh[kk], b1);
        mma16816(sa[1], qh[kk], l1);
        mma16816(sa[1], ql[kk], b1);
    }
    {
        const float g = tanhf(gate[h]) * ngate[0];
        #pragma unroll
        for (int hh = 0; hh < 2; ++hh) {
            float rmax = -1e30f;
            #pragma unroll
            for (int nt = 0; nt < 2; ++nt)
                #pragma unroll
                for (int e2 = 0; e2 < 2; ++e2) {
                    int colg = nt*8 + (lane & 3)*2 + e2;
                    float v = sa[nt][hh*2 + e2] * scale;
                    if (colg >= ALa) v = -1e30f;
                    sa[nt][hh*2 + e2] = v;
                    rmax = fmaxf(rmax, v);
                }
            rmax = fmaxf(rmax, __shfl_xor_sync(0xffffffffu, rmax, 1));
            rmax = fmaxf(rmax, __shfl_xor_sync(0xffffffffu, rmax, 2));
            float rs = 0.f;
            #pragma unroll
            for (int nt = 0; nt < 2; ++nt)
                #pragma unroll
                for (int e2 = 0; e2 < 2; ++e2) {
                    float p = __expf(sa[nt][hh*2 + e2] - rmax);
                    sa[nt][hh*2 + e2] = p;
                    rs += p;
                }
            rs += __shfl_xor_sync(0xffffffffu, rs, 1);
            rs += __shfl_xor_sync(0xffffffffu, rs, 2);
            const float wgt = g / rs;
            #pragma unroll
            for (int nt = 0; nt < 2; ++nt)
                #pragma unroll
                for (int e2 = 0; e2 < 2; ++e2)
                    sa[nt][hh*2 + e2] *= wgt;
        }
    }
    {
        uint32_t ph[4], pl[4];
        #pragma unroll
        for (int part = 0; part < 4; ++part) {
            int tl2 = part >> 1;
            int eh = part & 1;
            split2(sa[tl2][eh*2], sa[tl2][eh*2 + 1], ph[part], pl[part]);
        }
        const int mi = lane >> 3;
        const int krow = (lane & 7) + (mi & 1)*8;
        #pragma unroll
        for (int np = 0; np < 8; ++np) {
            uint32_t c = np*2 + (mi >> 1);
            uint32_t off = (uint32_t)krow*256 + ((c >> 3) << 7) + (((c & 7) ^ (krow & 7)) << 4);
            uint32_t t[4], t2[4];
            ldmx4t(t,  sbase + 8192 + off);
            ldmx4t(t2, sbase + 12288 + off);
            uint32_t bvh0[2] = {t[0],  t[1]},  bvh1[2] = {t[2],  t[3]};
            uint32_t bvl0[2] = {t2[0], t2[1]}, bvl1[2] = {t2[2], t2[3]};
            mma16816(oacc[2*np],     ph, bvh0);
            mma16816(oacc[2*np],     ph, bvl0);
            mma16816(oacc[2*np],     pl, bvh0);
            mma16816(oacc[2*np + 1], ph, bvh1);
            mma16816(oacc[2*np + 1], ph, bvl1);
            mma16816(oacc[2*np + 1], pl, bvh1);
        }
    }

    // ---- store hi/lo planes (Wo GEMM A-operand layout, stride KP)
    const size_t r0 = (size_t)(b*Ss + q0 + w*16 + (lane >> 2));
    #pragma unroll
    for (int nt = 0; nt < 16; ++nt) {
        const int col = h*HDd + nt*8 + (lane & 3)*2;
        uint32_t hv, lv;
        split2(oacc[nt][0], oacc[nt][1], hv, lv);
        *(uint32_t*)(Ohi + r0*KP + col) = hv;
        *(uint32_t*)(Olo + r0*KP + col) = lv;
        split2(oacc[nt][2], oacc[nt][3], hv, lv);
        *(uint32_t*)(Ohi + (r0 + 8)*KP + col) = hv;
        *(uint32_t*)(Olo + (r0 + 8)*KP + col) = lv;
    }
}

// ---------------------------------------------------------------------------
// lora_part: partial T over k-range, X = fp32. grid (M/64, KSPL)
// ---------------------------------------------------------------------------
__global__ __launch_bounds__(256) void lora_part(
    const float* __restrict__ X,
    const float* __restrict__ L1a, const float* __restrict__ L1b, const float* __restrict__ L1c,
    float* __restrict__ Tp, int nmat, int ldt)
{
    __shared__ float Xs[32][68];
    __shared__ float Ls[32][52];
    const int tid = threadIdx.x;
    const int tx = tid & 15, ty = tid >> 4;
    const int m0 = blockIdx.x << 6;
    const int ks = blockIdx.y;
    const int Rtot = nmat << 4;
    float acc[4][3];
    #pragma unroll
    for (int i = 0; i < 4; ++i)
        #pragma unroll
        for (int j = 0; j < 3; ++j) acc[i][j] = 0.f;

    for (int k0 = ks*512; k0 < ks*512 + 512; k0 += 32) {
        __syncthreads();
        #pragma unroll
        for (int i = 0; i < 2; ++i) {
            int v = tid + i*256;
            int r = v >> 3, c = (v & 7) << 2;
            float4 x4 = *(const float4*)(X + (size_t)(m0 + r)*Dd + k0 + c);
            Xs[c+0][r]=x4.x; Xs[c+1][r]=x4.y; Xs[c+2][r]=x4.z; Xs[c+3][r]=x4.w;
        }
        for (int v = tid; v < Rtot*8; v += 256) {
            int r = v >> 3, c = (v & 7) << 2;
            const float* src = (r < 16) ? (L1a + (size_t)r*Dd)
                             : (r < 32) ? (L1b + (size_t)(r-16)*Dd)
                                        : (L1c + (size_t)(r-32)*Dd);
            float4 l4 = *(const float4*)(src + k0 + c);
            Ls[c+0][r]=l4.x; Ls[c+1][r]=l4.y; Ls[c+2][r]=l4.z; Ls[c+3][r]=l4.w;
        }
        __syncthreads();
        #pragma unroll
        for (int k = 0; k < 32; ++k) {
            float xv[4];
            #pragma unroll
            for (int i = 0; i < 4; ++i) xv[i] = Xs[k][4*ty + i];
            for (int j = 0; j < nmat; ++j) {
                float lv = Ls[k][tx + 16*j];
                #pragma unroll
                for (int i = 0; i < 4; ++i) acc[i][j] = fmaf(xv[i], lv, acc[i][j]);
            }
        }
    }
    float* out = Tp + (size_t)ks*MROWS*ldt;
    for (int j = 0; j < nmat; ++j)
        #pragma unroll
        for (int i = 0; i < 4; ++i)
            out[(size_t)(m0 + 4*ty + i)*ldt + tx + 16*j] = acc[i][j];
}

// ---------------------------------------------------------------------------
// lora_part_planes: X reconstructed from fp16 hi/lo planes (stride KP)
// ---------------------------------------------------------------------------
__global__ __launch_bounds__(256) void lora_part_planes(
    const __half* __restrict__ Xhi, const __half* __restrict__ Xlo,
    const float* __restrict__ L1a,
    float* __restrict__ Tp, int ldt)
{
    __shared__ float Xs[32][68];
    __shared__ float Ls[32][20];
    const int tid = threadIdx.x;
    const int tx = tid & 15, ty = tid >> 4;
    const int m0 = blockIdx.x << 6;
    const int ks = blockIdx.y;
    float acc[4];
    #pragma unroll
    for (int i = 0; i < 4; ++i) acc[i] = 0.f;

    for (int k0 = ks*512; k0 < ks*512 + 512; k0 += 32) {
        __syncthreads();
        #pragma unroll
        for (int i = 0; i < 2; ++i) {
            int v = tid + i*256;
            int r = v >> 3, c = (v & 7) << 2;
            uint2 hu = *(const uint2*)(Xhi + (size_t)(m0 + r)*KP + k0 + c);
            uint2 lu = *(const uint2*)(Xlo + (size_t)(m0 + r)*KP + k0 + c);
            __half2 h0 = *(__half2*)&hu.x;
            __half2 h1 = *(__half2*)&hu.y;
            __half2 l0 = *(__half2*)&lu.x;
            __half2 l1 = *(__half2*)&lu.y;
            Xs[c+0][r] = __half2float(h0.x) + __half2float(l0.x);
            Xs[c+1][r] = __half2float(h0.y) + __half2float(l0.y);
            Xs[c+2][r] = __half2float(h1.x) + __half2float(l1.x);
            Xs[c+3][r] = __half2float(h1.y) + __half2float(l1.y);
        }
        for (int v = tid; v < 128; v += 256) {
            int r = v >> 3, c = (v & 7) << 2;
            float4 l4 = *(const float4*)(L1a + (size_t)r*Dd + k0 + c);
            Ls[c+0][r]=l4.x; Ls[c+1][r]=l4.y; Ls[c+2][r]=l4.z; Ls[c+3][r]=l4.w;
        }
        __syncthreads();
        #pragma unroll
        for (int k = 0; k < 32; ++k) {
            float lv = Ls[k][tx];
            #pragma unroll
            for (int i = 0; i < 4; ++i) acc[i] = fmaf(Xs[k][4*ty + i], lv, acc[i]);
        }
    }
    float* out = Tp + (size_t)ks*MROWS*ldt;
    #pragma unroll
    for (int i = 0; i < 4; ++i)
        out[(size_t)(m0 + 4*ty + i)*ldt + tx] = acc[i];
}

// ---------------------------------------------------------------------------
// adapter_part: partial AK/AV over k-range. grid (Dd/64, KSPL)
// ---------------------------------------------------------------------------
__global__ __launch_bounds__(256) void adapter_part(
    const float* __restrict__ Ad, const float* __restrict__ Wk, const float* __restrict__ Wv,
    float* __restrict__ AKp, float* __restrict__ AVp)
{
    __shared__ float Ads[20][68];
    __shared__ float Wks[64][65];
    __shared__ float Wvs[64][65];
    const int tid = threadIdx.x;
    const int nl = tid & 63, mg = tid >> 6;
    const int n0 = blockIdx.x << 6;
    const int ks = blockIdx.y;
    float ak[5] = {0,0,0,0,0}, av[5] = {0,0,0,0,0};

    for (int k0 = ks*512; k0 < ks*512 + 512; k0 += 64) {
        __syncthreads();
        for (int v = tid; v < 320; v += 256) {
            int r = v >> 4, c = (v & 15) << 2;
            float4 a4 = *(const float4*)(Ad + (size_t)r*Dd + k0 + c);
            Ads[r][c+0]=a4.x; Ads[r][c+1]=a4.y; Ads[r][c+2]=a4.z; Ads[r][c+3]=a4.w;
        }
        #pragma unroll
        for (int i = 0; i < 4; ++i) {
            int v = tid + i*256;
            int r = v >> 4, c = (v & 15) << 2;
            float4 w4 = *(const float4*)(Wk + (size_t)(n0 + r)*Dd + k0 + c);
            Wks[c+0][r]=w4.x; Wks[c+1][r]=w4.y; Wks[c+2][r]=w4.z; Wks[c+3][r]=w4.w;
            float4 w5 = *(const float4*)(Wv + (size_t)(n0 + r)*Dd + k0 + c);
            Wvs[c+0][r]=w5.x; Wvs[c+1][r]=w5.y; Wvs[c+2][r]=w5.z; Wvs[c+3][r]=w5.w;
        }
        __syncthreads();
        #pragma unroll
        for (int k = 0; k < 64; ++k) {
            float wkv = Wks[k][nl];
            float wvv = Wvs[k][nl];
            #pragma unroll
            for (int i = 0; i < 5; ++i) {
                float a = Ads[5*mg + i][k];
                ak[i] = fmaf(a, wkv, ak[i]);
                av[i] = fmaf(a, wvv, av[i]);
            }
        }
    }
    float* akp = AKp + (size_t)ks*20*Dd;
    float* avp = AVp + (size_t)ks*20*Dd;
    #pragma unroll
    for (int i = 0; i < 5; ++i) {
        akp[(size_t)(5*mg + i)*Dd + n0 + nl] = ak[i];
        avp[(size_t)(5*mg + i)*Dd + n0 + nl] = av[i];
    }
}

// ---------------------------------------------------------------------------
// Launch
// ---------------------------------------------------------------------------
extern "C" void kernel_launch(void* const* d_in, const int* in_sizes, int n_in,
                              void* d_out, int out_size)
{
    (void)in_sizes; (void)n_in; (void)out_size;
    const float* x       = (const float*)d_in[0];
    const float* adapter = (const float*)d_in[4];
    const float* wq  = (const float*)d_in[5];
    const float* wk  = (const float*)d_in[6];
    const float* wv  = (const float*)d_in[7];
    const float* wo  = (const float*)d_in[8];
    const float* lq1 = (const float*)d_in[9];
    const float* lq2 = (const float*)d_in[10];
    const float* lk1 = (const float*)d_in[11];
    const float* lk2 = (const float*)d_in[12];
    const float* lv1 = (const float*)d_in[13];
    const float* lv2 = (const float*)d_in[14];
    const float* lo1 = (const float*)d_in[15];
    const float* lo2 = (const float*)d_in[16];
    const float* gate  = (const float*)d_in[17];
    const float* ngate = (const float*)d_in[18];
    float* out = (float*)d_out;

    float *T, *Tp, *ak, *av, *akp, *avp;
    __half *cvAhi, *cvAlo, *cvB1hi, *cvB2hi;
    __half *qhi, *qlo, *khi, *klo, *vhi, *vlo;
    cudaGetSymbolAddress((void**)&T,    g_T);
    cudaGetSymbolAddress((void**)&Tp,   g_Tp);
    cudaGetSymbolAddress((void**)&ak,   g_ak);
    cudaGetSymbolAddress((void**)&av,   g_av);
    cudaGetSymbolAddress((void**)&akp,  g_akp);
    cudaGetSymbolAddress((void**)&avp,  g_avp);
    cudaGetSymbolAddress((void**)&cvAhi, g_cvAhi);
    cudaGetSymbolAddress((void**)&cvAlo, g_cvAlo);
    cudaGetSymbolAddress((void**)&cvB1hi, g_cvB1hi);
    cudaGetSymbolAddress((void**)&cvB2hi, g_cvB2hi);
    cudaGetSymbolAddress((void**)&qhi,  g_qhi);
    cudaGetSymbolAddress((void**)&qlo,  g_qlo);
    cudaGetSymbolAddress((void**)&khi,  g_khi);
    cudaGetSymbolAddress((void**)&klo,  g_klo);
    cudaGetSymbolAddress((void**)&vhi,  g_vhi);
    cudaGetSymbolAddress((void**)&vlo,  g_vlo);

    cudaFuncSetAttribute(gemm_fp16,   cudaFuncAttributeMaxDynamicSharedMemorySize, GEMM_SMEM);
    cudaFuncSetAttribute(flash_fused, cudaFuncAttributeMaxDynamicSharedMemorySize, FLASH_SMEM);

    const dim3 gGrid(Dd/128, MROWS/128);
    const int convBlocks = MROWS*520/256;

    // #1 LoRA intermediates (q/k/v), k-split
    lora_part<<<dim3(MROWS/64, KSPL), 256>>>(x, lq1, lk1, lv1, Tp, 3, 48);
    // #2
    reduce8<<<MROWS*48/256, 256>>>(T, Tp, MROWS*48);
    // #3 convert A = [x | T(48) | 0]  (hi + lo planes)
    conv_split<<<convBlocks, 256>>>(x, T, 48, 48, 0, cvAhi, cvAlo);
    // #4, #5 convert wq -> B1 (hi only), wk -> B2 (hi only)
    conv_split<<<convBlocks, 256>>>(wq, lq2, 16, 16, 0,  cvB1hi, nullptr);
    conv_split<<<convBlocks, 256>>>(wk, lk2, 16, 16, 16, cvB2hi, nullptr);
    // #6 gemm_q
    gemm_fp16<<<gGrid, 256, GEMM_SMEM>>>(cvAhi, cvAlo, cvB1hi, nullptr, qhi, qlo);
    // #7 gemm_k
    gemm_fp16<<<gGrid, 256, GEMM_SMEM>>>(cvAhi, cvAlo, cvB2hi, nullptr, khi, klo);
    // #8, #9 convert wv -> B1, gemm_v
    conv_split<<<convBlocks, 256>>>(wv, lv2, 16, 16, 32, cvB1hi, nullptr);
    gemm_fp16<<<gGrid, 256, GEMM_SMEM>>>(cvAhi, cvAlo, cvB1hi, nullptr, vhi, vlo);
    // adapter K/V projection, k-split
    adapter_part<<<dim3(Dd/64, KSPL), 256>>>(adapter, wk, wv, akp, avp);
    reduce8<<<20*Dd/256, 256>>>(ak, akp, 20*Dd);
    reduce8<<<20*Dd/256, 256>>>(av, avp, 20*Dd);
    // flash attention + fused adapter -> cvA planes
    flash_fused<<<dim3(Ss/128, Hh, Bb), 256, FLASH_SMEM>>>(
        qhi, qlo, khi, klo, vhi, vlo, ak, av, gate, ngate, cvAhi, cvAlo);
    // output LoRA chunk into cvA cols [4096,4160)
    lora_part_planes<<<dim3(MROWS/64, KSPL), 256>>>(cvAhi, cvAlo, lo1, Tp, 16);
    reduce_fill<<<MROWS*64/256, 256>>>(Tp, cvAhi, cvAlo);
    // output projection
    conv_split<<<convBlocks, 256>>>(wo, lo2, 16, 16, 0, cvB2hi, nullptr);
    gemm_fp16<<<gGrid, 256, GEMM_SMEM>>>(cvAhi, cvAlo, cvB2hi, out, nullptr, nullptr);
}

// round 14
// speedup vs baseline: 5.6732x; 1.0573x over previous
#include <cuda_runtime.h>
#include <cuda_fp16.h>
#include <math.h>
#include <stdint.h>

// Problem constants
#define Bb   2
#define Ss   2048
#define Dd   4096
#define Hh   32
#define HDd  128
#define ALa  10
#define MROWS (Bb*Ss)          // 4096
#define KP   4160              // 4096 + 64 (LoRA chunk)
#define NCH  65                // K'/64
#define KSPL 8                 // k-split for small gemms

// ---------------------------------------------------------------------------
// Scratch (device globals; no cudaMalloc allowed)
// ---------------------------------------------------------------------------
__device__ float g_T  [MROWS*48];
__device__ float g_Tp [KSPL*MROWS*48];
__device__ float g_ak [Bb*ALa*Dd];
__device__ float g_av [Bb*ALa*Dd];
__device__ float g_akp[KSPL*Bb*ALa*Dd];
__device__ float g_avp[KSPL*Bb*ALa*Dd];
__device__ __half g_cvAhi[MROWS*KP];
__device__ __half g_cvAlo[MROWS*KP];
__device__ __half g_cvB1hi[Dd*KP];
__device__ __half g_cvB2hi[Dd*KP];
__device__ __half g_qhi[MROWS*Dd];
__device__ __half g_qlo[MROWS*Dd];
__device__ __half g_khi[MROWS*Dd];
__device__ __half g_vhi[MROWS*Dd];

// ---------------------------------------------------------------------------
// helpers
// ---------------------------------------------------------------------------
__device__ __forceinline__ uint32_t smem_u32(const void* p) {
    uint32_t a;
    asm("{ .reg .u64 t; cvta.to.shared.u64 t, %1; cvt.u32.u64 %0, t; }" : "=r"(a) : "l"(p));
    return a;
}
__device__ __forceinline__ void cpa16(uint32_t dst, const void* src) {
    asm volatile("cp.async.cg.shared.global [%0], [%1], 16;" :: "r"(dst), "l"(src));
}
__device__ __forceinline__ void cpa_commit() { asm volatile("cp.async.commit_group;"); }
#define CPA_WAIT(N) asm volatile("cp.async.wait_group %0;" :: "n"(N))
__device__ __forceinline__ void ldmx4(uint32_t* r, uint32_t addr) {
    asm volatile("ldmatrix.sync.aligned.m8n8.x4.shared.b16 {%0,%1,%2,%3}, [%4];"
                 : "=r"(r[0]), "=r"(r[1]), "=r"(r[2]), "=r"(r[3]) : "r"(addr));
}
__device__ __forceinline__ void ldmx4t(uint32_t* r, uint32_t addr) {
    asm volatile("ldmatrix.sync.aligned.m8n8.x4.trans.shared.b16 {%0,%1,%2,%3}, [%4];"
                 : "=r"(r[0]), "=r"(r[1]), "=r"(r[2]), "=r"(r[3]) : "r"(addr));
}
// fp16 mma with fp32 accumulate
__device__ __forceinline__ void mma16816(float* c, const uint32_t* a, const uint32_t* b) {
    asm volatile(
        "mma.sync.aligned.m16n8k16.row.col.f32.f16.f16.f32 "
        "{%0,%1,%2,%3}, {%4,%5,%6,%7}, {%8,%9}, {%0,%1,%2,%3};"
        : "+f"(c[0]), "+f"(c[1]), "+f"(c[2]), "+f"(c[3])
        : "r"(a[0]), "r"(a[1]), "r"(a[2]), "r"(a[3]), "r"(b[0]), "r"(b[1]));
}
// pack 2 fp32 -> fp16x2 (hi) and residual fp16x2 (lo)
__device__ __forceinline__ void split2(float f0, float f1, uint32_t& hi, uint32_t& lo) {
    __half h0 = __float2half_rn(f0);
    __half h1 = __float2half_rn(f1);
    __half l0 = __float2half_rn(f0 - __half2float(h0));
    __half l1 = __float2half_rn(f1 - __half2float(h1));
    __half2 ph = __halves2half2(h0, h1);
    __half2 pl = __halves2half2(l0, l1);
    hi = *(uint32_t*)&ph;
    lo = *(uint32_t*)&pl;
}

// ---------------------------------------------------------------------------
// conv_split: dst[M x KP] (hi/lo fp16) = [src(Mx4096) | lora block | zeros]
// ---------------------------------------------------------------------------
__global__ __launch_bounds__(256) void conv_split(
    const float* __restrict__ src,
    const float* __restrict__ lsrc, int ldl, int lcols, int lshift,
    __half* __restrict__ dhi, __half* __restrict__ dlo)
{
    const int u = blockIdx.x * 256 + threadIdx.x;
    const int r = u / 520, g = u % 520;
    float f[8];
    if (g < 512) {
        float4 a = *(const float4*)(src + (size_t)r*4096 + g*8);
        float4 b = *(const float4*)(src + (size_t)r*4096 + g*8 + 4);
        f[0]=a.x; f[1]=a.y; f[2]=a.z; f[3]=a.w; f[4]=b.x; f[5]=b.y; f[6]=b.z; f[7]=b.w;
    } else {
        #pragma unroll
        for (int i = 0; i < 8; ++i) {
            int e = g*8 - 4096 + i;
            int lc = e - lshift;
            f[i] = (lc >= 0 && lc < lcols) ? lsrc[(size_t)r*ldl + lc] : 0.f;
        }
    }
    uint32_t h[4], l[4];
    #pragma unroll
    for (int e = 0; e < 4; ++e) split2(f[2*e], f[2*e+1], h[e], l[e]);
    *(uint4*)(dhi + (size_t)r*KP + g*8) = make_uint4(h[0], h[1], h[2], h[3]);
    if (dlo)
        *(uint4*)(dlo + (size_t)r*KP + g*8) = make_uint4(l[0], l[1], l[2], l[3]);
}

// ---------------------------------------------------------------------------
// reduce8: dst[i] = sum_{s<8} src[s*len + i]
// ---------------------------------------------------------------------------
__global__ __launch_bounds__(256) void reduce8(
    float* __restrict__ dst, const float* __restrict__ src, int len)
{
    const int i = blockIdx.x*256 + threadIdx.x;
    float s = 0.f;
    #pragma unroll
    for (int k = 0; k < KSPL; ++k) s += src[(size_t)k*len + i];
    dst[i] = s;
}

// ---------------------------------------------------------------------------
// reduce_fill: To = sum8 Tp; write split into cvA cols [4096, 4160)
// ---------------------------------------------------------------------------
__global__ __launch_bounds__(256) void reduce_fill(
    const float* __restrict__ Tp,
    __half* __restrict__ dhi, __half* __restrict__ dlo)
{
    const int u = blockIdx.x*256 + threadIdx.x;
    const int r = u >> 6, c = u & 63;
    float s = 0.f;
    if (c < 16) {
        #pragma unroll
        for (int k = 0; k < KSPL; ++k) s += Tp[(size_t)k*MROWS*16 + r*16 + c];
    }
    __half h = __float2half_rn(s);
    __half l = __float2half_rn(s - __half2float(h));
    dhi[(size_t)r*KP + 4096 + c] = h;
    dlo[(size_t)r*KP + 4096 + c] = l;
}

// ---------------------------------------------------------------------------
// fp16 2-pass mma GEMM: C = (Ahi+Alo) * Bhi^T.  256 threads, 8 warps,
// 32x64 warp tiles, 3-plane smem stage (Ahi,Alo,Bhi), 3-stage cp.async ring.
// Chi/Clo output planes independently nullable.
// ---------------------------------------------------------------------------
#define GPLANE 16384
#define GSTGB  (3*GPLANE)     // 49152
#define GEMM_SMEM (3*GSTGB)   // 147456

__global__ __launch_bounds__(256, 1) void gemm_fp16(
    const __half* __restrict__ Ahi, const __half* __restrict__ Alo,
    const __half* __restrict__ Bhi,
    float* __restrict__ C, __half* __restrict__ Chi, __half* __restrict__ Clo)
{
    extern __shared__ char smg[];
    const int tid = threadIdx.x;
    const int lane = tid & 31, wid = tid >> 5;
    const int wm = wid & 3, wn = wid >> 2;    // 4 x 2 warp grid, 32x64 tiles
    const int m0 = blockIdx.y << 7;
    const int n0 = blockIdx.x << 7;
    const uint32_t sbase = smem_u32(smg);

    float acc[2][8][4];
    #pragma unroll
    for (int mt = 0; mt < 2; ++mt)
        #pragma unroll
        for (int nt = 0; nt < 8; ++nt)
            #pragma unroll
            for (int e = 0; e < 4; ++e) acc[mt][nt][e] = 0.f;

    auto load_st = [&](int kt, int s) {
        const __half* srcs[3] = {
            Ahi + (size_t)m0*KP + kt*64, Alo + (size_t)m0*KP + kt*64,
            Bhi + (size_t)n0*KP + kt*64 };
        const uint32_t base = sbase + s*GSTGB;
        #pragma unroll
        for (int p = 0; p < 3; ++p) {
            #pragma unroll
            for (int i = 0; i < 4; ++i) {
                int u = tid + i*256;
                int r = u >> 3, c = u & 7;
                cpa16(base + p*GPLANE + r*128 + (((uint32_t)c ^ (r & 7)) << 4),
                      srcs[p] + (size_t)r*KP + c*8);
            }
        }
        cpa_commit();
    };

    load_st(0, 0);
    load_st(1, 1);

    for (int kt = 0; kt < NCH; ++kt) {
        const int s = kt % 3;
        CPA_WAIT(1);
        __syncthreads();

        const uint32_t aAhi = sbase + s*GSTGB;
        const uint32_t aAlo = aAhi + GPLANE;
        const uint32_t aBhi = aAhi + 2*GPLANE;
        #pragma unroll
        for (int kk = 0; kk < 4; ++kk) {
            uint32_t ah[2][4], al[2][4];
            #pragma unroll
            for (int mt = 0; mt < 2; ++mt) {
                int row = wm*32 + mt*16 + (lane & 15);
                uint32_t c = kk*2 + (lane >> 4);
                uint32_t off = (uint32_t)row*128 + ((c ^ (row & 7)) << 4);
                ldmx4(ah[mt], aAhi + off);
                ldmx4(al[mt], aAlo + off);
            }
            uint32_t bh[8][2];
            #pragma unroll
            for (int np = 0; np < 4; ++np) {
                int nrow = wn*64 + np*16 + (lane >> 4)*8 + (lane & 7);
                uint32_t c = kk*2 + ((lane >> 3) & 1);
                uint32_t off = (uint32_t)nrow*128 + ((c ^ (nrow & 7)) << 4);
                uint32_t t[4];
                ldmx4(t, aBhi + off);
                bh[2*np][0]=t[0]; bh[2*np][1]=t[1]; bh[2*np+1][0]=t[2]; bh[2*np+1][1]=t[3];
            }
            #pragma unroll
            for (int mt = 0; mt < 2; ++mt)
                #pragma unroll
                for (int nt = 0; nt < 8; ++nt) {
                    mma16816(acc[mt][nt], ah[mt], bh[nt]);
                    mma16816(acc[mt][nt], al[mt], bh[nt]);
                }
        }
        if (kt + 2 < NCH) load_st(kt + 2, (kt + 2) % 3);
    }

    #pragma unroll
    for (int mt = 0; mt < 2; ++mt) {
        const int row = m0 + wm*32 + mt*16 + (lane >> 2);
        #pragma unroll
        for (int nt = 0; nt < 8; ++nt) {
            const int col = n0 + wn*64 + nt*8 + (lane & 3)*2;
            if (C) {
                *(float2*)(C + (size_t)row*Dd + col)       = make_float2(acc[mt][nt][0], acc[mt][nt][1]);
                *(float2*)(C + (size_t)(row + 8)*Dd + col) = make_float2(acc[mt][nt][2], acc[mt][nt][3]);
            }
            if (Chi) {
                uint32_t h, l;
                split2(acc[mt][nt][0], acc[mt][nt][1], h, l);
                *(uint32_t*)(Chi + (size_t)row*Dd + col) = h;
                if (Clo) *(uint32_t*)(Clo + (size_t)row*Dd + col) = l;
                split2(acc[mt][nt][2], acc[mt][nt][3], h, l);
                *(uint32_t*)(Chi + (size_t)(row + 8)*Dd + col) = h;
                if (Clo) *(uint32_t*)(Clo + (size_t)(row + 8)*Dd + col) = l;
            }
        }
    }
}

// ---------------------------------------------------------------------------
// Flash attention + fused gated adapter cross-attention.
// Q split fp16 (hi/lo), K and V single fp16 plane (calibrated error budget).
// CTA: 128 q x 64 kv, 8 warps. Q frags hoisted; 3 dedicated KV stages.
// Output written as fp16 hi/lo planes at stride KP (Wo GEMM A-operand layout).
// ---------------------------------------------------------------------------
#define FQPL 32768
#define FKPL 16384
#define FKVSTG (2*FKPL)                    // Khi + Vhi = 32768
#define FLASH_SMEM (2*FQPL + 3*FKVSTG)     // 163840

__global__ __launch_bounds__(256, 1) void flash_fused(
    const __half* __restrict__ Qhi, const __half* __restrict__ Qlo,
    const __half* __restrict__ Khi, const __half* __restrict__ Vhi,
    const float* __restrict__ AK, const float* __restrict__ AV,
    const float* __restrict__ gate, const float* __restrict__ ngate,
    __half* __restrict__ Ohi, __half* __restrict__ Olo)
{
    extern __shared__ char smf[];
    const int tid = threadIdx.x;
    const int lane = tid & 31, w = tid >> 5;
    const int qt = (int)gridDim.x - 1 - (int)blockIdx.x;    // LPT: heavy first
    const int h = blockIdx.y, b = blockIdx.z;
    const int q0 = qt << 7;
    const uint32_t sbase = smem_u32(smf);
    const float scale = 0.08838834764831845f;

    // Q load (group 0)
    {
        const __half* srcs[2] = {
            Qhi + (size_t)(b*Ss + q0)*Dd + h*HDd,
            Qlo + (size_t)(b*Ss + q0)*Dd + h*HDd };
        #pragma unroll
        for (int p = 0; p < 2; ++p)
            #pragma unroll
            for (int i = 0; i < 8; ++i) {
                int u = tid + i*256;
                int r = u >> 4, c = u & 15;
                uint32_t dst = sbase + p*FQPL + (uint32_t)r*256 + (c >> 3)*128
                             + ((((uint32_t)c & 7) ^ (r & 7)) << 4);
                cpa16(dst, srcs[p] + (size_t)r*Dd + c*8);
            }
        cpa_commit();
    }
    auto stg = [&](int s) -> uint32_t {
        return sbase + 2*FQPL + s*FKVSTG;
    };
    auto loadKV = [&](int kt, int s) {
        const int k0 = kt << 6;
        const __half* srcs[2] = {
            Khi + (size_t)(b*Ss + k0)*Dd + h*HDd,
            Vhi + (size_t)(b*Ss + k0)*Dd + h*HDd };
        const uint32_t base = stg(s);
        #pragma unroll
        for (int p = 0; p < 2; ++p)
            #pragma unroll
            for (int i = 0; i < 4; ++i) {
                int u = tid + i*256;
                int r = u >> 4, c = u & 15;
                uint32_t dst = base + p*FKPL + (uint32_t)r*256 + (c >> 3)*128
                             + ((((uint32_t)c & 7) ^ (r & 7)) << 4);
                cpa16(dst, srcs[p] + (size_t)r*Dd + c*8);
            }
        cpa_commit();
    };
    loadKV(0, 0);
    CPA_WAIT(1);
    __syncthreads();

    uint32_t qh[8][4], ql[8][4];
    #pragma unroll
    for (int kk = 0; kk < 8; ++kk) {
        int row = w*16 + (lane & 15);
        uint32_t c = kk*2 + (lane >> 4);
        uint32_t off = (uint32_t)row*256 + (c >> 3)*128 + (((c & 7) ^ (row & 7)) << 4);
        ldmx4(qh[kk], sbase + off);
        ldmx4(ql[kk], sbase + FQPL + off);
    }
    loadKV(1, 1);

    float oacc[16][4];
    #pragma unroll
    for (int nt = 0; nt < 16; ++nt)
        #pragma unroll
        for (int e = 0; e < 4; ++e) oacc[nt][e] = 0.f;
    float mrow[2] = {-1e30f, -1e30f};
    float lrow[2] = {0.f, 0.f};

    const int nkt = 2*(qt + 1);
    for (int kt = 0; kt < nkt; ++kt) {
        if (kt + 1 < nkt) { CPA_WAIT(1); } else { CPA_WAIT(0); }
        __syncthreads();
        if (kt + 2 < nkt) loadKV(kt + 2, (kt + 2) % 3);

        const int k0 = kt << 6;
        const bool active = (k0 <= q0 + w*16 + 15);
        if (active) {
        const uint32_t kb = stg(kt % 3);
        const uint32_t vb = kb + FKPL;

        float sacc[8][4];
        #pragma unroll
        for (int nt = 0; nt < 8; ++nt)
            #pragma unroll
            for (int e = 0; e < 4; ++e) sacc[nt][e] = 0.f;
        #pragma unroll
        for (int kk = 0; kk < 8; ++kk) {
            #pragma unroll
            for (int np = 0; np < 4; ++np) {
                int nrow = np*16 + (lane >> 4)*8 + (lane & 7);
                uint32_t c = kk*2 + ((lane >> 3) & 1);
                uint32_t off = (uint32_t)nrow*256 + (c >> 3)*128 + (((c & 7) ^ (nrow & 7)) << 4);
                uint32_t tb[4];
                ldmx4(tb, kb + off);
                uint32_t b0[2] = {tb[0], tb[1]}, b1[2] = {tb[2], tb[3]};
                mma16816(sacc[2*np],     qh[kk], b0);
                mma16816(sacc[2*np],     ql[kk], b0);
                mma16816(sacc[2*np + 1], qh[kk], b1);
                mma16816(sacc[2*np + 1], ql[kk], b1);
            }
        }

        const bool needmask = (k0 + 63 > q0 + w*16);
        float corr[2];
        #pragma unroll
        for (int hh = 0; hh < 2; ++hh) {
            const int rowg = q0 + w*16 + (lane >> 2) + hh*8;
            float rmax = -1e30f;
            #pragma unroll
            for (int nt = 0; nt < 8; ++nt)
                #pragma unroll
                for (int e2 = 0; e2 < 2; ++e2) {
                    float v = sacc[nt][hh*2 + e2] * scale;
                    if (needmask) {
                        int colg = k0 + nt*8 + (lane & 3)*2 + e2;
                        if (colg > rowg) v = -1e30f;
                    }
                    sacc[nt][hh*2 + e2] = v;
                    rmax = fmaxf(rmax, v);
                }
            rmax = fmaxf(rmax, __shfl_xor_sync(0xffffffffu, rmax, 1));
            rmax = fmaxf(rmax, __shfl_xor_sync(0xffffffffu, rmax, 2));
            float mn = fmaxf(mrow[hh], rmax);
            corr[hh] = __expf(mrow[hh] - mn);
            float rs = 0.f;
            #pragma unroll
            for (int nt = 0; nt < 8; ++nt)
                #pragma unroll
                for (int e2 = 0; e2 < 2; ++e2) {
                    float p = __expf(sacc[nt][hh*2 + e2] - mn);
                    sacc[nt][hh*2 + e2] = p;
                    rs += p;
                }
            rs += __shfl_xor_sync(0xffffffffu, rs, 1);
            rs += __shfl_xor_sync(0xffffffffu, rs, 2);
            lrow[hh] = lrow[hh]*corr[hh] + rs;
            mrow[hh] = mn;
        }
        #pragma unroll
        for (int nt = 0; nt < 16; ++nt) {
            oacc[nt][0] *= corr[0]; oacc[nt][1] *= corr[0];
            oacc[nt][2] *= corr[1]; oacc[nt][3] *= corr[1];
        }

        #pragma unroll
        for (int kk4 = 0; kk4 < 4; ++kk4) {
            uint32_t ph[4], pl[4];
            #pragma unroll
            for (int part = 0; part < 4; ++part) {
                int tl2 = 2*kk4 + (part >> 1);
                int eh = part & 1;
                split2(sacc[tl2][eh*2], sacc[tl2][eh*2 + 1], ph[part], pl[part]);
            }
            const int mi = lane >> 3;
            const int krow = kk4*16 + (lane & 7) + (mi & 1)*8;
            #pragma unroll
            for (int np = 0; np < 8; ++np) {
                uint32_t c = np*2 + (mi >> 1);
                uint32_t off = (uint32_t)krow*256 + (c >> 3)*128 + (((c & 7) ^ (krow & 7)) << 4);
                uint32_t t[4];
                ldmx4t(t, vb + off);
                uint32_t bvh0[2] = {t[0], t[1]}, bvh1[2] = {t[2], t[3]};
                mma16816(oacc[2*np],     ph, bvh0);
                mma16816(oacc[2*np],     pl, bvh0);
                mma16816(oacc[2*np + 1], ph, bvh1);
                mma16816(oacc[2*np + 1], pl, bvh1);
            }
        }
        } // active
    }

    // normalize main attention
    {
        const float inv0 = 1.f / lrow[0];
        const float inv1 = 1.f / lrow[1];
        #pragma unroll
        for (int nt = 0; nt < 16; ++nt) {
            oacc[nt][0] *= inv0; oacc[nt][1] *= inv0;
            oacc[nt][2] *= inv1; oacc[nt][3] *= inv1;
        }
    }

    // ---- fused adapter cross-attention (tiles overwrite Q smem region) ----
    __syncthreads();   // all warps done with KV stages & Q smem
    for (int u = tid; u < 16*64; u += 256) {
        int r = u >> 6, cp = u & 63;          // cols 2cp, 2cp+1
        float f0=0.f, f1=0.f, g0=0.f, g1=0.f;
        if (r < ALa) {
            const float* akp_ = AK + ((size_t)(b*ALa + r))*Dd + h*HDd + 2*cp;
            const float* avp_ = AV + ((size_t)(b*ALa + r))*Dd + h*HDd + 2*cp;
            f0 = akp_[0]; f1 = akp_[1];
            g0 = avp_[0]; g1 = avp_[1];
        }
        uint32_t cu = (uint32_t)(cp >> 2);
        uint32_t intra = ((uint32_t)cp*4) & 15;
        uint32_t off = (uint32_t)r*256 + ((cu >> 3) << 7) + (((cu & 7) ^ (r & 7)) << 4) + intra;
        uint32_t hv, lv;
        split2(f0, f1, hv, lv);
        *(uint32_t*)(smf + off)         = hv;
        *(uint32_t*)(smf + 4096 + off)  = lv;
        split2(g0, g1, hv, lv);
        *(uint32_t*)(smf + 8192 + off)  = hv;
        *(uint32_t*)(smf + 12288 + off) = lv;
    }
    __syncthreads();

    // adapter scores: S_a (16q x 16k), K = HD = 128
    float sa[2][4];
    #pragma unroll
    for (int nt = 0; nt < 2; ++nt)
        #pragma unroll
        for (int e = 0; e < 4; ++e) sa[nt][e] = 0.f;
    #pragma unroll
    for (int kk = 0; kk < 8; ++kk) {
        int nrow = (lane >> 4)*8 + (lane & 7);
        uint32_t c = kk*2 + ((lane >> 3) & 1);
        uint32_t off = (uint32_t)nrow*256 + ((c >> 3) << 7) + (((c & 7) ^ (nrow & 7)) << 4);
        uint32_t tb[4], tl[4];
        ldmx4(tb, sbase + off);
        ldmx4(tl, sbase + 4096 + off);
        uint32_t b0[2] = {tb[0], tb[1]}, b1[2] = {tb[2], tb[3]};
        uint32_t l0[2] = {tl[0], tl[1]}, l1[2] = {tl[2], tl[3]};
        mma16816(sa[0], qh[kk], b0);
        mma16816(sa[0], qh[kk], l0);
        mma16816(sa[0], ql[kk], b0);
        mma16816(sa[1], qh[kk], b1);
        mma16816(sa[1], qh[kk], l1);
        mma16816(sa[1], ql[kk], b1);
    }
    {
        const float g = tanhf(gate[h]) * ngate[0];
        #pragma unroll
        for (int hh = 0; hh < 2; ++hh) {
            float rmax = -1e30f;
            #pragma unroll
            for (int nt = 0; nt < 2; ++nt)
                #pragma unroll
                for (int e2 = 0; e2 < 2; ++e2) {
                    int colg = nt*8 + (lane & 3)*2 + e2;
                    float v = sa[nt][hh*2 + e2] * scale;
                    if (colg >= ALa) v = -1e30f;
                    sa[nt][hh*2 + e2] = v;
                    rmax = fmaxf(rmax, v);
                }
            rmax = fmaxf(rmax, __shfl_xor_sync(0xffffffffu, rmax, 1));
            rmax = fmaxf(rmax, __shfl_xor_sync(0xffffffffu, rmax, 2));
            float rs = 0.f;
            #pragma unroll
            for (int nt = 0; nt < 2; ++nt)
                #pragma unroll
                for (int e2 = 0; e2 < 2; ++e2) {
                    float p = __expf(sa[nt][hh*2 + e2] - rmax);
                    sa[nt][hh*2 + e2] = p;
                    rs += p;
                }
            rs += __shfl_xor_sync(0xffffffffu, rs, 1);
            rs += __shfl_xor_sync(0xffffffffu, rs, 2);
            const float wgt = g / rs;
            #pragma unroll
            for (int nt = 0; nt < 2; ++nt)
                #pragma unroll
                for (int e2 = 0; e2 < 2; ++e2)
                    sa[nt][hh*2 + e2] *= wgt;
        }
    }
    {
        uint32_t ph[4], pl[4];
        #pragma unroll
        for (int part = 0; part < 4; ++part) {
            int tl2 = part >> 1;
            int eh = part & 1;
            split2(sa[tl2][eh*2], sa[tl2][eh*2 + 1], ph[part], pl[part]);
        }
        const int mi = lane >> 3;
        const int krow = (lane & 7) + (mi & 1)*8;
        #pragma unroll
        for (int np = 0; np < 8; ++np) {
            uint32_t c = np*2 + (mi >> 1);
            uint32_t off = (uint32_t)krow*256 + ((c >> 3) << 7) + (((c & 7) ^ (krow & 7)) << 4);
            uint32_t t[4], t2[4];
            ldmx4t(t,  sbase + 8192 + off);
            ldmx4t(t2, sbase + 12288 + off);
            uint32_t bvh0[2] = {t[0],  t[1]},  bvh1[2] = {t[2],  t[3]};
            uint32_t bvl0[2] = {t2[0], t2[1]}, bvl1[2] = {t2[2], t2[3]};
            mma16816(oacc[2*np],     ph, bvh0);
            mma16816(oacc[2*np],     ph, bvl0);
            mma16816(oacc[2*np],     pl, bvh0);
            mma16816(oacc[2*np + 1], ph, bvh1);
            mma16816(oacc[2*np + 1], ph, bvl1);
            mma16816(oacc[2*np + 1], pl, bvh1);
        }
    }

    // ---- store hi/lo planes (Wo GEMM A-operand layout, stride KP)
    const size_t r0 = (size_t)(b*Ss + q0 + w*16 + (lane >> 2));
    #pragma unroll
    for (int nt = 0; nt < 16; ++nt) {
        const int col = h*HDd + nt*8 + (lane & 3)*2;
        uint32_t hv, lv;
        split2(oacc[nt][0], oacc[nt][1], hv, lv);
        *(uint32_t*)(Ohi + r0*KP + col) = hv;
        *(uint32_t*)(Olo + r0*KP + col) = lv;
        split2(oacc[nt][2], oacc[nt][3], hv, lv);
        *(uint32_t*)(Ohi + (r0 + 8)*KP + col) = hv;
        *(uint32_t*)(Olo + (r0 + 8)*KP + col) = lv;
    }
}

// ---------------------------------------------------------------------------
// lora_part: partial T over k-range, X = fp32. grid (M/64, KSPL)
// ---------------------------------------------------------------------------
__global__ __launch_bounds__(256) void lora_part(
    const float* __restrict__ X,
    const float* __restrict__ L1a, const float* __restrict__ L1b, const float* __restrict__ L1c,
    float* __restrict__ Tp, int nmat, int ldt)
{
    __shared__ float Xs[32][68];
    __shared__ float Ls[32][52];
    const int tid = threadIdx.x;
    const int tx = tid & 15, ty = tid >> 4;
    const int m0 = blockIdx.x << 6;
    const int ks = blockIdx.y;
    const int Rtot = nmat << 4;
    float acc[4][3];
    #pragma unroll
    for (int i = 0; i < 4; ++i)
        #pragma unroll
        for (int j = 0; j < 3; ++j) acc[i][j] = 0.f;

    for (int k0 = ks*512; k0 < ks*512 + 512; k0 += 32) {
        __syncthreads();
        #pragma unroll
        for (int i = 0; i < 2; ++i) {
            int v = tid + i*256;
            int r = v >> 3, c = (v & 7) << 2;
            float4 x4 = *(const float4*)(X + (size_t)(m0 + r)*Dd + k0 + c);
            Xs[c+0][r]=x4.x; Xs[c+1][r]=x4.y; Xs[c+2][r]=x4.z; Xs[c+3][r]=x4.w;
        }
        for (int v = tid; v < Rtot*8; v += 256) {
            int r = v >> 3, c = (v & 7) << 2;
            const float* src = (r < 16) ? (L1a + (size_t)r*Dd)
                             : (r < 32) ? (L1b + (size_t)(r-16)*Dd)
                                        : (L1c + (size_t)(r-32)*Dd);
            float4 l4 = *(const float4*)(src + k0 + c);
            Ls[c+0][r]=l4.x; Ls[c+1][r]=l4.y; Ls[c+2][r]=l4.z; Ls[c+3][r]=l4.w;
        }
        __syncthreads();
        #pragma unroll
        for (int k = 0; k < 32; ++k) {
            float xv[4];
            #pragma unroll
            for (int i = 0; i < 4; ++i) xv[i] = Xs[k][4*ty + i];
            for (int j = 0; j < nmat; ++j) {
                float lv = Ls[k][tx + 16*j];
                #pragma unroll
                for (int i = 0; i < 4; ++i) acc[i][j] = fmaf(xv[i], lv, acc[i][j]);
            }
        }
    }
    float* out = Tp + (size_t)ks*MROWS*ldt;
    for (int j = 0; j < nmat; ++j)
        #pragma unroll
        for (int i = 0; i < 4; ++i)
            out[(size_t)(m0 + 4*ty + i)*ldt + tx + 16*j] = acc[i][j];
}

// ---------------------------------------------------------------------------
// lora_part_planes: X reconstructed from fp16 hi/lo planes (stride KP)
// ---------------------------------------------------------------------------
__global__ __launch_bounds__(256) void lora_part_planes(
    const __half* __restrict__ Xhi, const __half* __restrict__ Xlo,
    const float* __restrict__ L1a,
    float* __restrict__ Tp, int ldt)
{
    __shared__ float Xs[32][68];
    __shared__ float Ls[32][20];
    const int tid = threadIdx.x;
    const int tx = tid & 15, ty = tid >> 4;
    const int m0 = blockIdx.x << 6;
    const int ks = blockIdx.y;
    float acc[4];
    #pragma unroll
    for (int i = 0; i < 4; ++i) acc[i] = 0.f;

    for (int k0 = ks*512; k0 < ks*512 + 512; k0 += 32) {
        __syncthreads();
        #pragma unroll
        for (int i = 0; i < 2; ++i) {
            int v = tid + i*256;
            int r = v >> 3, c = (v & 7) << 2;
            uint2 hu = *(const uint2*)(Xhi + (size_t)(m0 + r)*KP + k0 + c);
            uint2 lu = *(const uint2*)(Xlo + (size_t)(m0 + r)*KP + k0 + c);
            __half2 h0 = *(__half2*)&hu.x;
            __half2 h1 = *(__half2*)&hu.y;
            __half2 l0 = *(__half2*)&lu.x;
            __half2 l1 = *(__half2*)&lu.y;
            Xs[c+0][r] = __half2float(h0.x) + __half2float(l0.x);
            Xs[c+1][r] = __half2float(h0.y) + __half2float(l0.y);
            Xs[c+2][r] = __half2float(h1.x) + __half2float(l1.x);
            Xs[c+3][r] = __half2float(h1.y) + __half2float(l1.y);
        }
        for (int v = tid; v < 128; v += 256) {
            int r = v >> 3, c = (v & 7) << 2;
            float4 l4 = *(const float4*)(L1a + (size_t)r*Dd + k0 + c);
            Ls[c+0][r]=l4.x; Ls[c+1][r]=l4.y; Ls[c+2][r]=l4.z; Ls[c+3][r]=l4.w;
        }
        __syncthreads();
        #pragma unroll
        for (int k = 0; k < 32; ++k) {
            float lv = Ls[k][tx];
            #pragma unroll
            for (int i = 0; i < 4; ++i) acc[i] = fmaf(Xs[k][4*ty + i], lv, acc[i]);
        }
    }
    float* out = Tp + (size_t)ks*MROWS*ldt;
    #pragma unroll
    for (int i = 0; i < 4; ++i)
        out[(size_t)(m0 + 4*ty + i)*ldt + tx] = acc[i];
}

// ---------------------------------------------------------------------------
// adapter_part: partial AK/AV over k-range. grid (Dd/64, KSPL)
// ---------------------------------------------------------------------------
__global__ __launch_bounds__(256) void adapter_part(
    const float* __restrict__ Ad, const float* __restrict__ Wk, const float* __restrict__ Wv,
    float* __restrict__ AKp, float* __restrict__ AVp)
{
    __shared__ float Ads[20][68];
    __shared__ float Wks[64][65];
    __shared__ float Wvs[64][65];
    const int tid = threadIdx.x;
    const int nl = tid & 63, mg = tid >> 6;
    const int n0 = blockIdx.x << 6;
    const int ks = blockIdx.y;
    float ak[5] = {0,0,0,0,0}, av[5] = {0,0,0,0,0};

    for (int k0 = ks*512; k0 < ks*512 + 512; k0 += 64) {
        __syncthreads();
        for (int v = tid; v < 320; v += 256) {
            int r = v >> 4, c = (v & 15) << 2;
            float4 a4 = *(const float4*)(Ad + (size_t)r*Dd + k0 + c);
            Ads[r][c+0]=a4.x; Ads[r][c+1]=a4.y; Ads[r][c+2]=a4.z; Ads[r][c+3]=a4.w;
        }
        #pragma unroll
        for (int i = 0; i < 4; ++i) {
            int v = tid + i*256;
            int r = v >> 4, c = (v & 15) << 2;
            float4 w4 = *(const float4*)(Wk + (size_t)(n0 + r)*Dd + k0 + c);
            Wks[c+0][r]=w4.x; Wks[c+1][r]=w4.y; Wks[c+2][r]=w4.z; Wks[c+3][r]=w4.w;
            float4 w5 = *(const float4*)(Wv + (size_t)(n0 + r)*Dd + k0 + c);
            Wvs[c+0][r]=w5.x; Wvs[c+1][r]=w5.y; Wvs[c+2][r]=w5.z; Wvs[c+3][r]=w5.w;
        }
        __syncthreads();
        #pragma unroll
        for (int k = 0; k < 64; ++k) {
            float wkv = Wks[k][nl];
            float wvv = Wvs[k][nl];
            #pragma unroll
            for (int i = 0; i < 5; ++i) {
                float a = Ads[5*mg + i][k];
                ak[i] = fmaf(a, wkv, ak[i]);
                av[i] = fmaf(a, wvv, av[i]);
            }
        }
    }
    float* akp = AKp + (size_t)ks*20*Dd;
    float* avp = AVp + (size_t)ks*20*Dd;
    #pragma unroll
    for (int i = 0; i < 5; ++i) {
        akp[(size_t)(5*mg + i)*Dd + n0 + nl] = ak[i];
        avp[(size_t)(5*mg + i)*Dd + n0 + nl] = av[i];
    }
}

// ---------------------------------------------------------------------------
// Launch
// ---------------------------------------------------------------------------
extern "C" void kernel_launch(void* const* d_in, const int* in_sizes, int n_in,
                              void* d_out, int out_size)
{
    (void)in_sizes; (void)n_in; (void)out_size;
    const float* x       = (const float*)d_in[0];
    const float* adapter = (const float*)d_in[4];
    const float* wq  = (const float*)d_in[5];
    const float* wk  = (const float*)d_in[6];
    const float* wv  = (const float*)d_in[7];
    const float* wo  = (const float*)d_in[8];
    const float* lq1 = (const float*)d_in[9];
    const float* lq2 = (const float*)d_in[10];
    const float* lk1 = (const float*)d_in[11];
    const float* lk2 = (const float*)d_in[12];
    const float* lv1 = (const float*)d_in[13];
    const float* lv2 = (const float*)d_in[14];
    const float* lo1 = (const float*)d_in[15];
    const float* lo2 = (const float*)d_in[16];
    const float* gate  = (const float*)d_in[17];
    const float* ngate = (const float*)d_in[18];
    float* out = (float*)d_out;

    float *T, *Tp, *ak, *av, *akp, *avp;
    __half *cvAhi, *cvAlo, *cvB1hi, *cvB2hi;
    __half *qhi, *qlo, *khi, *vhi;
    cudaGetSymbolAddress((void**)&T,    g_T);
    cudaGetSymbolAddress((void**)&Tp,   g_Tp);
    cudaGetSymbolAddress((void**)&ak,   g_ak);
    cudaGetSymbolAddress((void**)&av,   g_av);
    cudaGetSymbolAddress((void**)&akp,  g_akp);
    cudaGetSymbolAddress((void**)&avp,  g_avp);
    cudaGetSymbolAddress((void**)&cvAhi, g_cvAhi);
    cudaGetSymbolAddress((void**)&cvAlo, g_cvAlo);
    cudaGetSymbolAddress((void**)&cvB1hi, g_cvB1hi);
    cudaGetSymbolAddress((void**)&cvB2hi, g_cvB2hi);
    cudaGetSymbolAddress((void**)&qhi,  g_qhi);
    cudaGetSymbolAddress((void**)&qlo,  g_qlo);
    cudaGetSymbolAddress((void**)&khi,  g_khi);
    cudaGetSymbolAddress((void**)&vhi,  g_vhi);

    cudaFuncSetAttribute(gemm_fp16,   cudaFuncAttributeMaxDynamicSharedMemorySize, GEMM_SMEM);
    cudaFuncSetAttribute(flash_fused, cudaFuncAttributeMaxDynamicSharedMemorySize, FLASH_SMEM);

    const dim3 gGrid(Dd/128, MROWS/128);
    const int convBlocks = MROWS*520/256;

    // #1 LoRA intermediates (q/k/v), k-split
    lora_part<<<dim3(MROWS/64, KSPL), 256>>>(x, lq1, lk1, lv1, Tp, 3, 48);
    // #2
    reduce8<<<MROWS*48/256, 256>>>(T, Tp, MROWS*48);
    // #3 convert A = [x | T(48) | 0]  (hi + lo planes)
    conv_split<<<convBlocks, 256>>>(x, T, 48, 48, 0, cvAhi, cvAlo);
    // #4, #5 convert wq -> B1 (hi only), wk -> B2 (hi only)
    conv_split<<<convBlocks, 256>>>(wq, lq2, 16, 16, 0,  cvB1hi, nullptr);
    conv_split<<<convBlocks, 256>>>(wk, lk2, 16, 16, 16, cvB2hi, nullptr);
    // #6 gemm_q (q split: hi + lo)
    gemm_fp16<<<gGrid, 256, GEMM_SMEM>>>(cvAhi, cvAlo, cvB1hi, nullptr, qhi, qlo);
    // #7 gemm_k (k single plane)
    gemm_fp16<<<gGrid, 256, GEMM_SMEM>>>(cvAhi, cvAlo, cvB2hi, nullptr, khi, nullptr);
    // #8, #9 convert wv -> B1, gemm_v (v single plane)
    conv_split<<<convBlocks, 256>>>(wv, lv2, 16, 16, 32, cvB1hi, nullptr);
    gemm_fp16<<<gGrid, 256, GEMM_SMEM>>>(cvAhi, cvAlo, cvB1hi, nullptr, vhi, nullptr);
    // adapter K/V projection, k-split
    adapter_part<<<dim3(Dd/64, KSPL), 256>>>(adapter, wk, wv, akp, avp);
    reduce8<<<20*Dd/256, 256>>>(ak, akp, 20*Dd);
    reduce8<<<20*Dd/256, 256>>>(av, avp, 20*Dd);
    // flash attention + fused adapter -> cvA planes
    flash_fused<<<dim3(Ss/128, Hh, Bb), 256, FLASH_SMEM>>>(
        qhi, qlo, khi, vhi, ak, av, gate, ngate, cvAhi, cvAlo);
    // output LoRA chunk into cvA cols [4096,4160)
    lora_part_planes<<<dim3(MROWS/64, KSPL), 256>>>(cvAhi, cvAlo, lo1, Tp, 16);
    reduce_fill<<<MROWS*64/256, 256>>>(Tp, cvAhi, cvAlo);
    // output projection
    conv_split<<<convBlocks, 256>>>(wo, lo2, 16, 16, 0, cvB2hi, nullptr);
    gemm_fp16<<<gGrid, 256, GEMM_SMEM>>>(cvAhi, cvAlo, cvB2hi, out, nullptr, nullptr);
}